// round 13
// baseline (speedup 1.0000x reference)
#include <cuda_runtime.h>
#include <cuda_bf16.h>
#include <mma.h>
#include <cstdint>

using namespace nvcuda;

#define NN 100000
#define NB 20000
#define INC 64
#define HID 128
#define NBX 49
#define MAXE 3000000

// ================= scratch (device globals; no runtime allocation) ==========
__device__ float g_pn  [(size_t)NN * 192];
__device__ float g_pb  [(size_t)NB * 128];
__device__ float g_aggn[(size_t)NN * 384];
__device__ float g_aggb[(size_t)NB * 256];
__device__ float g_On  [(size_t)NN * 384];
__device__ float g_Ob  [(size_t)NB * 256];
__device__ float g_xn0 [(size_t)NN * HID];
__device__ float g_xn1 [(size_t)NN * HID];
__device__ float g_xb0 [(size_t)NB * HID];
__device__ float g_xb1 [(size_t)NB * HID];
__device__ float g_cnt [5][NN];
__device__ int   g_cnti[5][NN];
__device__ int   g_rowp[5][NN + 1];
__device__ int   g_bsum[5][64];
__device__ int   g_col [MAXE];
__device__ int   g_emode;

// bias scratch
__device__ float g_pbCatN[192];
__device__ float g_pbCatB[128];
__device__ float g_l0blCatN[384];
__device__ float g_l0blCatB[256];
__device__ float g_b1SumN[128];
__device__ float g_b1SumB[128];
__device__ float g_b2SumN[128];
__device__ float g_bnS[128];
// bf16 transposed+split weights [Npad x K], hi/lo
__device__ __nv_bfloat16 g_BtProjN[2][256 * 64];
__device__ __nv_bfloat16 g_BtProjB[2][128 * 64];
__device__ __nv_bfloat16 g_BtL0  [2][5][128 * 128];
__device__ __nv_bfloat16 g_BtL1N [2][128 * 512];
__device__ __nv_bfloat16 g_BtL1B [2][128 * 384];
__device__ __nv_bfloat16 g_BtL2N [2][128 * 512];
__device__ __nv_bfloat16 g_BtM1  [2][128 * 128];
__device__ __nv_bfloat16 g_BtM2  [2][128 * 128];

__device__ __forceinline__ int edge_at(const int* e, long long i) {
    if (g_emode) return (int)((const long long*)e)[i];
    return e[i];
}
__global__ void counti5_k(const int* e0, const int* e1, const int* e2,
                          const int* e3, const int* e4,
                          int E0, int E1, int E2, int E3, int E4) {
    int r = blockIdx.y;
    const int* e; int E;
    switch (r) {
        case 0: e = e0; E = E0; break;
        case 1: e = e1; E = E1; break;
        case 2: e = e2; E = E2; break;
        case 3: e = e3; E = E3; break;
        default: e = e4; E = E4; break;
    }
    int i = blockIdx.x * 256 + threadIdx.x;
    if (i >= E) return;
    atomicAdd(&g_cnti[r][edge_at(e, (long long)E + i)], 1);
}
__global__ void scan1_k() {
    int r = blockIdx.y;
    int n = (r == 2 || r == 4) ? NB : NN;
    int t = threadIdx.x;
    int base = blockIdx.x * 2048 + t * 8;
    int vals[8];
#pragma unroll
    for (int j = 0; j < 8; j++) {
        int idx = base + j;
        vals[j] = (idx < n) ? g_cnti[r][idx] : 0;
        if (idx < n) g_cnt[r][idx] = 1.0f / (float)max(vals[j], 1);
    }
    int tot = 0;
#pragma unroll
    for (int j = 0; j < 8; j++) tot += vals[j];
    int lane = t & 31, wid = t >> 5;
    int x = tot;
#pragma unroll
    for (int o = 1; o < 32; o <<= 1) {
        int y = __shfl_up_sync(0xffffffffu, x, o);
        if (lane >= o) x += y;
    }
    __shared__ int wsum[8];
    if (lane == 31) wsum[wid] = x;
    __syncthreads();
    if (t == 0) {
        int run = 0;
#pragma unroll
        for (int i = 0; i < 8; i++) { int v = wsum[i]; wsum[i] = run; run += v; }
        g_bsum[r][blockIdx.x] = run;
    }
    __syncthreads();
    int run = (x - tot) + wsum[wid];
#pragma unroll
    for (int j = 0; j < 8; j++) {
        int idx = base + j;
        if (idx < n) g_rowp[r][idx] = run;
        run += vals[j];
    }
}
__global__ void scan3_k() {
    int r = blockIdx.y;
    int n = (r == 2 || r == 4) ? NB : NN;
    int bx = blockIdx.x;
    int t = threadIdx.x;
    __shared__ int sb[64];
    __shared__ int s_add;
    if (t < 64) sb[t] = (t < NBX) ? g_bsum[r][t] : 0;
    __syncthreads();
    if (t == 0) {
        int a = 0;
        for (int i = 0; i < bx; i++) a += sb[i];
        s_add = a;
        if (bx == NBX - 1) g_rowp[r][n] = a + sb[NBX - 1];
    }
    __syncthreads();
    int add = s_add;
    int base = bx * 2048 + t * 8;
#pragma unroll
    for (int j = 0; j < 8; j++) {
        int idx = base + j;
        if (idx < n) {
            int v = g_rowp[r][idx] + add;
            g_rowp[r][idx] = v;
            g_cnti[r][idx] = v;
        }
    }
}
__global__ void fill5_k(const int* e0, const int* e1, const int* e2,
                        const int* e3, const int* e4,
                        int E0, int E1, int E2, int E3, int E4,
                        int b0, int b1, int b2, int b3, int b4) {
    int r = blockIdx.y;
    const int* e; int E; int eb;
    switch (r) {
        case 0: e = e0; E = E0; eb = b0; break;
        case 1: e = e1; E = E1; eb = b1; break;
        case 2: e = e2; E = E2; eb = b2; break;
        case 3: e = e3; E = E3; eb = b3; break;
        default: e = e4; E = E4; eb = b4; break;
    }
    int i = blockIdx.x * 256 + threadIdx.x;
    if (i >= E) return;
    int s = edge_at(e, i);
    int d = edge_at(e, (long long)E + i);
    int pos = atomicAdd(&g_cnti[r][d], 1);
    g_col[eb + pos] = s;
}

// ---- merged CSR seg-mean aggregation (job table, warp per dst row) ---------
struct Agg5 {
    const float* xf[5];
    const int* rowp[5];
    const int* col[5];
    const float* invc[5];
    float* agg[5];
    int lds[5], soff[5], ldd[5], doff[5], n[5];
    int boff[6];
    int nslots;
};

template <int V>
__global__ void aggmulti_k(Agg5 J) {
    int b = blockIdx.x;
    int s = 0;
    while (s + 1 < J.nslots && b >= J.boff[s + 1]) s++;
    int row = (b - J.boff[s]) * 8 + (threadIdx.x >> 5);
    if (row >= J.n[s]) return;
    int lane = threadIdx.x & 31;
    const float* xf = J.xf[s];
    const int* col = J.col[s];
    int lds = J.lds[s], soff = J.soff[s];
    int beg = J.rowp[s][row], end = J.rowp[s][row + 1];
    float acc[V];
#pragma unroll
    for (int j = 0; j < V; j++) acc[j] = 0.0f;
    int e = beg;
    for (; e + 7 < end; e += 8) {
        int si[8];
#pragma unroll
        for (int u = 0; u < 8; u++) si[u] = __ldg(&col[e + u]);
        if (V == 4) {
            float4 vv[8];
#pragma unroll
            for (int u = 0; u < 8; u++)
                vv[u] = *(const float4*)(xf + (size_t)si[u] * lds + soff + lane * V);
#pragma unroll
            for (int u = 0; u < 8; u++) {
                acc[0] += vv[u].x; acc[1] += vv[u].y;
                acc[2] += vv[u].z; acc[3] += vv[u].w;
            }
        } else {
            float2 vv[8];
#pragma unroll
            for (int u = 0; u < 8; u++)
                vv[u] = *(const float2*)(xf + (size_t)si[u] * lds + soff + lane * V);
#pragma unroll
            for (int u = 0; u < 8; u++) {
                acc[0] += vv[u].x; acc[1] += vv[u].y;
            }
        }
    }
    for (; e < end; e++) {
        int s0 = __ldg(&col[e]);
        const float* p0 = xf + (size_t)s0 * lds + soff + lane * V;
        if (V == 4) {
            float4 a = *(const float4*)p0;
            acc[0] += a.x; acc[1] += a.y; acc[2] += a.z; acc[3] += a.w;
        } else {
            float2 a = *(const float2*)p0;
            acc[0] += a.x; acc[1] += a.y;
        }
    }
    float inv = J.invc[s][row];
    float* q = J.agg[s] + (size_t)row * J.ldd[s] + J.doff[s] + lane * V;
    if (V == 4) {
        *(float4*)q = make_float4(acc[0] * inv, acc[1] * inv, acc[2] * inv, acc[3] * inv);
    } else {
        *(float2*)q = make_float2(acc[0] * inv, acc[1] * inv);
    }
}

// ================= cp.async helpers =========================================
__device__ __forceinline__ void cp16(uint32_t dst, const void* src) {
    asm volatile("cp.async.ca.shared.global [%0], [%1], 16;" :: "r"(dst), "l"(src));
}
__device__ __forceinline__ void cp_commit() {
    asm volatile("cp.async.commit_group;");
}
__device__ __forceinline__ void cp_wait0() {
    asm volatile("cp.async.wait_group 0;" ::: "memory");
}

__device__ __forceinline__ void bsplit(float x, __nv_bfloat16& h, __nv_bfloat16& l) {
    h = __float2bfloat16_rn(x);
    l = __float2bfloat16_rn(x - __bfloat162float(h));
}

// ================= wmma bf16 split GEMM (job table, cp.async B) =============
// Per z-slot: epi(alpha*([A1|A2]@W) + bias[n]).
// EPI: 0 plain, 1 relu, 3 relu+LN fused (Nfull==128),
//      5 full final: o=(acc+bias)*invr -> o@W1+b1 -> relu+BN -> @W2+b2 -> Cout.
struct TGJob {
    const float* A1[5];
    const float* A2[5];
    const __nv_bfloat16* Bhi[5];
    const __nv_bfloat16* Blo[5];
    const float* bias[5];
    float* C[5];
    int lda1[5], K1[5], lda2[5], K2[5], ldK[5], ldc[5], coff[5], M[5], Nfull[5];
    float alpha[5];
    float invr[5];
    // EPI=5 extras (slot 0 only)
    const __nv_bfloat16* W1h;
    const __nv_bfloat16* W1l;
    const float* b1;
    const __nv_bfloat16* W2h;
    const __nv_bfloat16* W2l;
    const float* b2;
    float* Cout;
};
#define TG_DSM 81920
template <int EPI>
__global__ __launch_bounds__(256) void tgemm_k(
    TGJob J, const float* __restrict__ bnS, const float* __restrict__ bnB)
{
    extern __shared__ char dynsmem[];
    __nv_bfloat16* Asm = reinterpret_cast<__nv_bfloat16*>(dynsmem);
    __nv_bfloat16* Bsm = reinterpret_cast<__nv_bfloat16*>(dynsmem + 40960);
    uint32_t Bu32 = (uint32_t)__cvta_generic_to_shared(Bsm);

    int z = blockIdx.z;
    const float* A1 = J.A1[z];
    const float* A2 = J.A2[z];
    const __nv_bfloat16* Bhi = J.Bhi[z];
    const __nv_bfloat16* Blo = J.Blo[z];
    const float* bias = J.bias[z];
    float* C = J.C[z];
    int lda1 = J.lda1[z], K1 = J.K1[z], lda2 = J.lda2[z], K2 = J.K2[z];
    int ldK = J.ldK[z], ldc = J.ldc[z], coff = J.coff[z];
    int M = J.M[z], Nfull = J.Nfull[z];
    float alpha = J.alpha[z];

    int m0 = blockIdx.x * 128;
    int n0 = blockIdx.y * 128;
    if (m0 >= M || n0 >= Nfull) return;

    int tid = threadIdx.x;
    int wid = tid >> 5, lane = tid & 31;
    int wm = wid >> 2, wn = wid & 3;
    int mw = m0 + wm * 64;
    int nw = n0 + wn * 32;
    int nl = wn * 32;
    bool active = (nw < Nfull);
    int K = K1 + K2;
    int nkt = K >> 5;

    wmma::fragment<wmma::accumulator, 16, 16, 16, float> acc[4][2];
#pragma unroll
    for (int i = 0; i < 4; i++)
#pragma unroll
        for (int j = 0; j < 2; j++) wmma::fill_fragment(acc[i][j], 0.0f);

    int row = tid >> 1, half = tid & 1;
    int m = m0 + row;
    bool mok = (m < M);
    int brow = row, bhalf = half;

    // ---- prologue ----
    float4 v[4];
    {
        const float* Ap; int ld, kl;
        if (0 < K1) { Ap = A1; ld = lda1; kl = 0; }
        else        { Ap = A2; ld = lda2; kl = -K1; }
        const float* src = Ap + (size_t)m * ld + kl + half * 16;
#pragma unroll
        for (int i = 0; i < 4; i++)
            v[i] = mok ? *(const float4*)(src + i * 4) : make_float4(0.f, 0.f, 0.f, 0.f);
    }
    {
        const __nv_bfloat16* sH = Bhi + (size_t)(n0 + brow) * ldK + bhalf * 16;
        const __nv_bfloat16* sL = Blo + (size_t)(n0 + brow) * ldK + bhalf * 16;
        uint32_t dH = Bu32 + (uint32_t)(((0 * 2 + 0) * 128 + brow) * 40 + bhalf * 16) * 2;
        uint32_t dL = Bu32 + (uint32_t)(((0 * 2 + 1) * 128 + brow) * 40 + bhalf * 16) * 2;
        cp16(dH, sH); cp16(dH + 16, sH + 8);
        cp16(dL, sL); cp16(dL + 16, sL + 8);
        cp_commit();
    }

    int buf = 0;
    for (int kt = 0; kt < nkt; kt++) {
        {
            __nv_bfloat162* ah = reinterpret_cast<__nv_bfloat162*>(
                Asm + ((buf * 2 + 0) * 128 + row) * 40);
            __nv_bfloat162* al = reinterpret_cast<__nv_bfloat162*>(
                Asm + ((buf * 2 + 1) * 128 + row) * 40);
#pragma unroll
            for (int i = 0; i < 4; i++) {
                int col = half * 16 + i * 4;
                float4 x = v[i];
                __nv_bfloat16 hx = __float2bfloat16_rn(x.x);
                __nv_bfloat16 hy = __float2bfloat16_rn(x.y);
                __nv_bfloat16 hz = __float2bfloat16_rn(x.z);
                __nv_bfloat16 hw = __float2bfloat16_rn(x.w);
                __nv_bfloat162 h01; h01.x = hx; h01.y = hy;
                __nv_bfloat162 h23; h23.x = hz; h23.y = hw;
                ah[(col >> 1) + 0] = h01;
                ah[(col >> 1) + 1] = h23;
                __nv_bfloat162 l01, l23;
                l01.x = __float2bfloat16_rn(x.x - __bfloat162float(hx));
                l01.y = __float2bfloat16_rn(x.y - __bfloat162float(hy));
                l23.x = __float2bfloat16_rn(x.z - __bfloat162float(hz));
                l23.y = __float2bfloat16_rn(x.w - __bfloat162float(hw));
                al[(col >> 1) + 0] = l01;
                al[(col >> 1) + 1] = l23;
            }
        }
        cp_wait0();
        __syncthreads();
        if (kt + 1 < nkt) {
            int k0n = (kt + 1) << 5;
            const __nv_bfloat16* sH = Bhi + (size_t)(n0 + brow) * ldK + k0n + bhalf * 16;
            const __nv_bfloat16* sL = Blo + (size_t)(n0 + brow) * ldK + k0n + bhalf * 16;
            int ob = buf ^ 1;
            uint32_t dH = Bu32 + (uint32_t)(((ob * 2 + 0) * 128 + brow) * 40 + bhalf * 16) * 2;
            uint32_t dL = Bu32 + (uint32_t)(((ob * 2 + 1) * 128 + brow) * 40 + bhalf * 16) * 2;
            cp16(dH, sH); cp16(dH + 16, sH + 8);
            cp16(dL, sL); cp16(dL + 16, sL + 8);
            cp_commit();
            const float* Ap; int ld, kl;
            if (k0n < K1) { Ap = A1; ld = lda1; kl = k0n; }
            else          { Ap = A2; ld = lda2; kl = k0n - K1; }
            const float* src = Ap + (size_t)m * ld + kl + half * 16;
#pragma unroll
            for (int i = 0; i < 4; i++)
                v[i] = mok ? *(const float4*)(src + i * 4) : make_float4(0.f, 0.f, 0.f, 0.f);
        }
        if (active) {
            const __nv_bfloat16* BsH = Bsm + (buf * 2 + 0) * 128 * 40;
            const __nv_bfloat16* BsL = Bsm + (buf * 2 + 1) * 128 * 40;
#pragma unroll
            for (int kk = 0; kk < 32; kk += 16) {
                wmma::fragment<wmma::matrix_b, 16, 16, 16, __nv_bfloat16, wmma::col_major> bh[2], bl2[2];
#pragma unroll
                for (int j = 0; j < 2; j++) {
                    wmma::load_matrix_sync(bh[j],  BsH + (nl + j * 16) * 40 + kk, 40u);
                    wmma::load_matrix_sync(bl2[j], BsL + (nl + j * 16) * 40 + kk, 40u);
                }
#pragma unroll
                for (int i = 0; i < 4; i++) {
                    wmma::fragment<wmma::matrix_a, 16, 16, 16, __nv_bfloat16, wmma::row_major> ah, al;
                    wmma::load_matrix_sync(ah, Asm + ((buf * 2 + 0) * 128 + wm * 64 + i * 16) * 40 + kk, 40u);
                    wmma::load_matrix_sync(al, Asm + ((buf * 2 + 1) * 128 + wm * 64 + i * 16) * 40 + kk, 40u);
#pragma unroll
                    for (int j = 0; j < 2; j++) {
                        wmma::mma_sync(acc[i][j], ah, bh[j],  acc[i][j]);
                        wmma::mma_sync(acc[i][j], ah, bl2[j], acc[i][j]);
                        wmma::mma_sync(acc[i][j], al, bh[j],  acc[i][j]);
                    }
                }
            }
        }
        buf ^= 1;
    }
    __syncthreads();

    if (EPI == 3) {
        // ---- fused relu -> LayerNorm epilogue (Nfull == 128) ----
        float* obuf = reinterpret_cast<float*>(dynsmem);   // 128 x 132 f32
#pragma unroll
        for (int i = 0; i < 4; i++)
#pragma unroll
            for (int j = 0; j < 2; j++)
                wmma::store_matrix_sync(obuf + (wm * 64 + i * 16) * 132 + nl + j * 16,
                                        acc[i][j], 132u, wmma::mem_row_major);
        __syncthreads();
        float invr = J.invr[z];
        int r0 = wid * 16;
        for (int rr = 0; rr < 16; rr++) {
            int rloc = r0 + rr;
            int mm = m0 + rloc;
            if (mm >= M) continue;
            float vv[4]; float s = 0.f;
#pragma unroll
            for (int j = 0; j < 4; j++) {
                int c = lane + 32 * j;
                float val = obuf[rloc * 132 + c] * alpha + bias[c];
                vv[j] = fmaxf(val * invr, 0.f);
                s += vv[j];
            }
#pragma unroll
            for (int o = 16; o; o >>= 1) s += __shfl_xor_sync(0xffffffffu, s, o);
            float mean = s * (1.0f / 128.0f);
            float ss = 0.f;
#pragma unroll
            for (int j = 0; j < 4; j++) { float d = vv[j] - mean; ss += d * d; }
#pragma unroll
            for (int o = 16; o; o >>= 1) ss += __shfl_xor_sync(0xffffffffu, ss, o);
            float inv = rsqrtf(ss * (1.0f / 128.0f) + 1e-5f);
            float* q = C + (size_t)mm * ldc;
#pragma unroll
            for (int j = 0; j < 4; j++) {
                int c = lane + 32 * j;
                q[c] = (vv[j] - mean) * inv * bnS[c] + bnB[c];
            }
        }
    } else if (EPI == 5) {
        // ---- full final fusion: o=(acc+bias)*invr -> W1 -> relu+BN -> W2 ----
        // smem: oH/oL 2*128*136*2 = 69632 at 0; per-warp scratch 1536 B at 69632.
        __nv_bfloat16* oH = reinterpret_cast<__nv_bfloat16*>(dynsmem);
        __nv_bfloat16* oL = oH + 128 * 136;
        char* wbase = dynsmem + 69632 + wid * 1536;
        float* myp = reinterpret_cast<float*>(wbase);
        int base = lane * 8;
        int pr = base >> 4, pc = base & 15;
        float scl = J.invr[z];
        // stage 1: acc -> o (bf16 split, scaled)
#pragma unroll
        for (int i = 0; i < 4; i++) {
#pragma unroll
            for (int j = 0; j < 2; j++) {
                wmma::store_matrix_sync(myp, acc[i][j], 20u, wmma::mem_row_major);
                __syncwarp();
                int rloc = wm * 64 + i * 16 + pr;
                int nb = nl + j * 16;
                bool rok = (m0 + rloc < M);
#pragma unroll
                for (int t = 0; t < 8; t++) {
                    int n = nb + pc + t;
                    float val = rok ? (myp[pr * 20 + pc + t] + bias[n]) * scl : 0.f;
                    __nv_bfloat16 hh, ll;
                    bsplit(val, hh, ll);
                    oH[rloc * 136 + n] = hh;
                    oL[rloc * 136 + n] = ll;
                }
                __syncwarp();
            }
        }
        __syncthreads();
        // stage 2+3: per warp 16 rows; W1 GEMM -> relu+BN -> W2 GEMM
        int r0w = wid * 16;
        __nv_bfloat16* hH = reinterpret_cast<__nv_bfloat16*>(wbase);   // 16x24
        __nv_bfloat16* hL = hH + 16 * 24;
        wmma::fragment<wmma::accumulator, 16, 16, 16, float> acc2[2];
        wmma::fill_fragment(acc2[0], 0.f);
        wmma::fill_fragment(acc2[1], 0.f);
        for (int j = 0; j < 8; j++) {
            wmma::fragment<wmma::accumulator, 16, 16, 16, float> acc1;
            wmma::fill_fragment(acc1, 0.f);
#pragma unroll
            for (int kf = 0; kf < 8; kf++) {
                wmma::fragment<wmma::matrix_a, 16, 16, 16, __nv_bfloat16, wmma::row_major> ahf, alf;
                wmma::load_matrix_sync(ahf, oH + r0w * 136 + kf * 16, 136u);
                wmma::load_matrix_sync(alf, oL + r0w * 136 + kf * 16, 136u);
                wmma::fragment<wmma::matrix_b, 16, 16, 16, __nv_bfloat16, wmma::col_major> bhf, blf;
                wmma::load_matrix_sync(bhf, J.W1h + (size_t)(j * 16) * 128 + kf * 16, 128u);
                wmma::load_matrix_sync(blf, J.W1l + (size_t)(j * 16) * 128 + kf * 16, 128u);
                wmma::mma_sync(acc1, ahf, bhf, acc1);
                wmma::mma_sync(acc1, ahf, blf, acc1);
                wmma::mma_sync(acc1, alf, bhf, acc1);
            }
            wmma::store_matrix_sync(myp, acc1, 20u, wmma::mem_row_major);
            __syncwarp();
            float hv[8];
#pragma unroll
            for (int t = 0; t < 8; t++) {
                int n = j * 16 + pc + t;
                float val = myp[pr * 20 + pc + t] + J.b1[n];
                hv[t] = fmaxf(val, 0.f) * bnS[n] + bnB[n];
            }
            __syncwarp();
#pragma unroll
            for (int t = 0; t < 8; t++) {
                __nv_bfloat16 hh, ll;
                bsplit(hv[t], hh, ll);
                hH[pr * 24 + pc + t] = hh;
                hL[pr * 24 + pc + t] = ll;
            }
            __syncwarp();
            wmma::fragment<wmma::matrix_a, 16, 16, 16, __nv_bfloat16, wmma::row_major> haf, laf;
            wmma::load_matrix_sync(haf, hH, 24u);
            wmma::load_matrix_sync(laf, hL, 24u);
#pragma unroll
            for (int n2 = 0; n2 < 2; n2++) {
                wmma::fragment<wmma::matrix_b, 16, 16, 16, __nv_bfloat16, wmma::col_major> bh2, bl22;
                wmma::load_matrix_sync(bh2,  J.W2h + (size_t)(n2 * 16) * 128 + j * 16, 128u);
                wmma::load_matrix_sync(bl22, J.W2l + (size_t)(n2 * 16) * 128 + j * 16, 128u);
                wmma::mma_sync(acc2[n2], haf, bh2,  acc2[n2]);
                wmma::mma_sync(acc2[n2], haf, bl22, acc2[n2]);
                wmma::mma_sync(acc2[n2], laf, bh2,  acc2[n2]);
            }
            __syncwarp();
        }
#pragma unroll
        for (int n2 = 0; n2 < 2; n2++) {
            wmma::store_matrix_sync(myp, acc2[n2], 20u, wmma::mem_row_major);
            __syncwarp();
            int mm = m0 + r0w + pr;
            if (mm < M) {
                float out[8];
#pragma unroll
                for (int t = 0; t < 8; t++)
                    out[t] = myp[pr * 20 + pc + t] + J.b2[n2 * 16 + pc + t];
                float* dst = J.Cout + (size_t)mm * 32 + n2 * 16 + pc;
                *(float4*)dst = *(float4*)&out[0];
                *(float4*)(dst + 4) = *(float4*)&out[4];
            }
            __syncwarp();
        }
    } else if (active) {
        float* myp = reinterpret_cast<float*>(dynsmem) + wid * 320;
        int base = lane * 8;
        int pr = base >> 4, pc = base & 15;
#pragma unroll
        for (int i = 0; i < 4; i++) {
#pragma unroll
            for (int j = 0; j < 2; j++) {
                wmma::store_matrix_sync(myp, acc[i][j], 20u, wmma::mem_row_major);
                __syncwarp();
                int mb = mw + i * 16, nb = nw + j * 16;
                if (mb + pr < M) {
                    float out[8];
#pragma unroll
                    for (int t = 0; t < 8; t++) {
                        int n = nb + pc + t;
                        float val = myp[pr * 20 + pc + t] * alpha + bias[n];
                        if (EPI >= 1) val = fmaxf(val, 0.0f);
                        out[t] = val;
                    }
                    float* dst = C + (size_t)(mb + pr) * ldc + coff + nb + pc;
                    *(float4*)dst = *(float4*)&out[0];
                    *(float4*)(dst + 4) = *(float4*)&out[4];
                }
                __syncwarp();
            }
        }
    }
}

// ================= merged elementwise: layer-0 post ==========================
__global__ void l0post2_k(const float* __restrict__ On, const float* __restrict__ Ob,
                          const float* __restrict__ gg, const float* __restrict__ bb,
                          float* __restrict__ xn, float* __restrict__ xb, int nblkN) {
    int b = blockIdx.x;
    const float* O; float* xout; int ldo, M, R;
    if (b < nblkN) { O = On; xout = xn; ldo = 384; M = NN; R = 3; }
    else           { O = Ob; xout = xb; ldo = 256; M = NB; R = 2; b -= nblkN; }
    int row = b * 8 + (threadIdx.x >> 5);
    if (row >= M) return;
    int lane = threadIdx.x & 31;
    float acc[4] = {0.f, 0.f, 0.f, 0.f};
    for (int rb = 0; rb < R; rb++) {
        const float* p = O + (size_t)row * ldo + rb * 128;
        float v[4]; float ss = 0.f;
#pragma unroll
        for (int j = 0; j < 4; j++) { v[j] = p[lane + 32 * j]; ss += v[j] * v[j]; }
#pragma unroll
        for (int s = 16; s; s >>= 1) ss += __shfl_xor_sync(0xffffffffu, ss, s);
        float inv = 1.0f / fmaxf(sqrtf(ss), 1e-12f);
#pragma unroll
        for (int j = 0; j < 4; j++) acc[j] += v[j] * inv;
    }
    const float invR = 1.0f / R;
    float s = 0.f;
#pragma unroll
    for (int j = 0; j < 4; j++) { acc[j] = fmaxf(acc[j] * invR, 0.f); s += acc[j]; }
#pragma unroll
    for (int o = 16; o; o >>= 1) s += __shfl_xor_sync(0xffffffffu, s, o);
    float m = s * (1.0f / 128.0f);
    float ss = 0.f;
#pragma unroll
    for (int j = 0; j < 4; j++) { float d = acc[j] - m; ss += d * d; }
#pragma unroll
    for (int o = 16; o; o >>= 1) ss += __shfl_xor_sync(0xffffffffu, ss, o);
    float inv = rsqrtf(ss * (1.0f / 128.0f) + 1e-5f);
    float* q = xout + (size_t)row * 128;
#pragma unroll
    for (int j = 0; j < 4; j++) {
        int c = lane + 32 * j;
        q[c] = (acc[j] - m) * inv * gg[c] + bb[c];
    }
}

// ================= fused weight-prep + init kernel ===========================
__device__ __forceinline__ void lsplit_body(__nv_bfloat16* hi, __nv_bfloat16* lo,
                                            const float* WlL, const float* WrL,
                                            int r0, int r1, int r2, int nrel, int idx) {
    int K = nrel * 128 + 128;
    int n = idx / K, k = idx - n * K;
    float x;
    if (k < nrel * 128) {
        int j = k >> 7, kk = k & 127;
        int r = (j == 0) ? r0 : (j == 1) ? r1 : r2;
        x = WlL[(size_t)r * 16384 + kk * 128 + n];
    } else {
        int kk = k - nrel * 128;
        x = WrL[(size_t)r0 * 16384 + kk * 128 + n] + WrL[(size_t)r1 * 16384 + kk * 128 + n];
        if (nrel == 3) x += WrL[(size_t)r2 * 16384 + kk * 128 + n];
    }
    __nv_bfloat16 h, l;
    bsplit(x, h, l);
    hi[idx] = h;
    lo[idx] = l;
}
#define PREP_TOTAL (305152 + 5 * NN)
__global__ void prep_k(const float* __restrict__ proj_W, const float* __restrict__ proj_b,
                       const float* __restrict__ l0_Wl, const float* __restrict__ l0_bl,
                       const float* __restrict__ l0_Wr,
                       const float* __restrict__ Wl, const float* __restrict__ bl,
                       const float* __restrict__ Wr,
                       const float* __restrict__ mlp_W1, const float* __restrict__ mlp_W2,
                       const float* __restrict__ bn_g, const int* __restrict__ e0) {
    int idx = blockIdx.x * 256 + threadIdx.x;
    __nv_bfloat16 h, l;
    if (idx < 12288) {
        int j = idx >> 12, rem = idx & 4095;
        int k = rem >> 6, c = rem & 63;
        float x = proj_W[(size_t)j * 4096 + k * 64 + c];
        int n = j * 64 + c;
        bsplit(x, h, l);
        g_BtProjN[0][n * 64 + k] = h; g_BtProjN[1][n * 64 + k] = l;
        return;
    }
    idx -= 12288;
    if (idx < 8192) {
        int j = idx >> 12, rem = idx & 4095;
        int k = rem >> 6, c = rem & 63;
        int r = (j == 0) ? 3 : 4;
        float x = proj_W[(size_t)r * 4096 + k * 64 + c];
        int n = j * 64 + c;
        bsplit(x, h, l);
        g_BtProjB[0][n * 64 + k] = h; g_BtProjB[1][n * 64 + k] = l;
        return;
    }
    idx -= 8192;
    if (idx < 81920) {
        int s = idx >> 14, rem = idx & 16383;
        int n = rem >> 7, k = rem & 127;
        const int rels[5] = {0, 1, 3, 2, 4};
        int r = rels[s];
        float x = (k < 64) ? l0_Wr[(size_t)r * 8192 + k * 128 + n]
                           : l0_Wl[(size_t)r * 8192 + (k - 64) * 128 + n];
        bsplit(x, h, l);
        g_BtL0[0][s][rem] = h; g_BtL0[1][s][rem] = l;
        return;
    }
    idx -= 81920;
    if (idx < 65536) { lsplit_body(g_BtL1N[0], g_BtL1N[1], Wl, Wr, 0, 1, 3, 3, idx); return; }
    idx -= 65536;
    if (idx < 49152) { lsplit_body(g_BtL1B[0], g_BtL1B[1], Wl, Wr, 2, 4, 0, 2, idx); return; }
    idx -= 49152;
    if (idx < 65536) { lsplit_body(g_BtL2N[0], g_BtL2N[1], Wl + 5 * 16384, Wr + 5 * 16384, 0, 1, 3, 3, idx); return; }
    idx -= 65536;
    if (idx < 16384) {
        int k = idx >> 7, n = idx & 127;
        bsplit(mlp_W1[idx], h, l);
        g_BtM1[0][n * 128 + k] = h; g_BtM1[1][n * 128 + k] = l;
        return;
    }
    idx -= 16384;
    if (idx < 4096) {
        int k = idx / 32, n = idx - (idx / 32) * 32;
        bsplit(mlp_W2[idx], h, l);
        g_BtM2[0][n * 128 + k] = h; g_BtM2[1][n * 128 + k] = l;
        return;
    }
    idx -= 4096;
    if (idx < 2048) {
        int t = idx;
        if (t < 192) {
            int j = t / 64;
            g_pbCatN[t] = proj_b[(size_t)j * 64 + (t - j * 64)];
        } else if (t < 320) {
            int local = t - 192; int j = local / 64;
            int r = (j == 0) ? 3 : 4;
            g_pbCatB[local] = proj_b[(size_t)r * 64 + (local - j * 64)];
        } else if (t < 704) {
            int local = t - 320; int j = local / 128;
            int r = (j == 0) ? 0 : (j == 1) ? 1 : 3;
            g_l0blCatN[local] = l0_bl[(size_t)r * 128 + (local - j * 128)];
        } else if (t < 960) {
            int local = t - 704; int j = local / 128;
            int r = (j == 0) ? 2 : 4;
            g_l0blCatB[local] = l0_bl[(size_t)r * 128 + (local - j * 128)];
        } else if (t < 1088) {
            int i = t - 960;
            g_b1SumN[i] = bl[i] + bl[128 + i] + bl[3 * 128 + i];
        } else if (t < 1216) {
            int i = t - 1088;
            g_b1SumB[i] = bl[2 * 128 + i] + bl[4 * 128 + i];
        } else if (t < 1344) {
            int i = t - 1216;
            g_b2SumN[i] = bl[(5 + 0) * 128 + i] + bl[(5 + 1) * 128 + i] + bl[(5 + 3) * 128 + i];
        } else if (t < 1472) {
            int i = t - 1344;
            g_bnS[i] = bn_g[i] * rsqrtf(1.0f + 1e-5f);
        } else if (t == 1472) {
            int z = 1;
            for (int i = 1; i < 64; i += 2)
                if (e0[i] != 0) z = 0;
            g_emode = z;
        }
        return;
    }
    idx -= 2048;
    if (idx < 5 * NN) ((int*)g_cnti)[idx] = 0;
}

// ================= host dispatch =============================================
static void tgemmJ(int epi, const TGJob& J, int nslots, const float* p0, const float* p1) {
    int maxM = 0, maxN = 0;
    for (int s = 0; s < nslots; s++) {
        if (J.M[s] > maxM) maxM = J.M[s];
        if (J.Nfull[s] > maxN) maxN = J.Nfull[s];
    }
    dim3 g((maxM + 127) / 128, (maxN + 127) / 128, nslots);
    if (epi == 0) {
        cudaFuncSetAttribute(tgemm_k<0>, cudaFuncAttributeMaxDynamicSharedMemorySize, TG_DSM);
        tgemm_k<0><<<g, 256, TG_DSM>>>(J, p0, p1);
    } else if (epi == 1) {
        cudaFuncSetAttribute(tgemm_k<1>, cudaFuncAttributeMaxDynamicSharedMemorySize, TG_DSM);
        tgemm_k<1><<<g, 256, TG_DSM>>>(J, p0, p1);
    } else if (epi == 3) {
        cudaFuncSetAttribute(tgemm_k<3>, cudaFuncAttributeMaxDynamicSharedMemorySize, TG_DSM);
        tgemm_k<3><<<g, 256, TG_DSM>>>(J, p0, p1);
    } else {
        cudaFuncSetAttribute(tgemm_k<5>, cudaFuncAttributeMaxDynamicSharedMemorySize, TG_DSM);
        tgemm_k<5><<<g, 256, TG_DSM>>>(J, p0, p1);
    }
}
static void setslot(TGJob& J, int s, const float* A1, int lda1, int K1,
                    const float* A2, int lda2, int K2,
                    const __nv_bfloat16* Bh, const __nv_bfloat16* Bl, int ldK,
                    const float* bias, float* C, int ldc, int coff,
                    int M, int Nfull, float alpha, float invr = 1.0f) {
    J.A1[s] = A1; J.lda1[s] = lda1; J.K1[s] = K1;
    J.A2[s] = A2; J.lda2[s] = lda2; J.K2[s] = K2;
    J.Bhi[s] = Bh; J.Blo[s] = Bl; J.ldK[s] = ldK;
    J.bias[s] = bias; J.C[s] = C; J.ldc[s] = ldc; J.coff[s] = coff;
    J.M[s] = M; J.Nfull[s] = Nfull; J.alpha[s] = alpha; J.invr[s] = invr;
}

extern "C" void kernel_launch(void* const* d_in, const int* in_sizes, int n_in,
                              void* d_out, int out_size) {
    const float* x_note = (const float*)d_in[0];
    const float* x_beat = (const float*)d_in[1];
    const int* e[5] = {(const int*)d_in[2], (const int*)d_in[3], (const int*)d_in[4],
                       (const int*)d_in[5], (const int*)d_in[6]};
    int E[5];
    for (int r = 0; r < 5; r++) E[r] = in_sizes[2 + r] / 2;
    const float* proj_W = (const float*)d_in[7];
    const float* proj_b = (const float*)d_in[8];
    const float* l0_Wl  = (const float*)d_in[9];
    const float* l0_bl  = (const float*)d_in[10];
    const float* l0_Wr  = (const float*)d_in[11];
    const float* Wl     = (const float*)d_in[12];
    const float* bl     = (const float*)d_in[13];
    const float* Wr     = (const float*)d_in[14];
    const float* ln_g   = (const float*)d_in[15];
    const float* ln_b   = (const float*)d_in[16];
    const float* mlp_W1 = (const float*)d_in[17];
    const float* mlp_b1 = (const float*)d_in[18];
    const float* bn_g   = (const float*)d_in[19];
    const float* bn_b   = (const float*)d_in[20];
    const float* mlp_W2 = (const float*)d_in[21];
    const float* mlp_b2 = (const float*)d_in[22];

    float *pn, *pb, *aggn, *aggb, *On, *Ob, *xn0, *xn1, *xb0, *xb1, *cntf;
    int *rowp, *colx;
    cudaGetSymbolAddress((void**)&pn, g_pn);       cudaGetSymbolAddress((void**)&pb, g_pb);
    cudaGetSymbolAddress((void**)&aggn, g_aggn);   cudaGetSymbolAddress((void**)&aggb, g_aggb);
    cudaGetSymbolAddress((void**)&On, g_On);       cudaGetSymbolAddress((void**)&Ob, g_Ob);
    cudaGetSymbolAddress((void**)&xn0, g_xn0);     cudaGetSymbolAddress((void**)&xn1, g_xn1);
    cudaGetSymbolAddress((void**)&xb0, g_xb0);     cudaGetSymbolAddress((void**)&xb1, g_xb1);
    cudaGetSymbolAddress((void**)&cntf, g_cnt);
    cudaGetSymbolAddress((void**)&rowp, g_rowp);   cudaGetSymbolAddress((void**)&colx, g_col);

    float *pbCatN, *pbCatB, *l0blCatN, *l0blCatB, *b1SumN, *b1SumB, *b2SumN, *bnS;
    cudaGetSymbolAddress((void**)&pbCatN, g_pbCatN);     cudaGetSymbolAddress((void**)&pbCatB, g_pbCatB);
    cudaGetSymbolAddress((void**)&l0blCatN, g_l0blCatN); cudaGetSymbolAddress((void**)&l0blCatB, g_l0blCatB);
    cudaGetSymbolAddress((void**)&b1SumN, g_b1SumN);     cudaGetSymbolAddress((void**)&b1SumB, g_b1SumB);
    cudaGetSymbolAddress((void**)&b2SumN, g_b2SumN);     cudaGetSymbolAddress((void**)&bnS, g_bnS);

    __nv_bfloat16 *BtProjN[2], *BtProjB[2], *BtL0[2], *BtL1N[2], *BtL1B[2], *BtL2N[2], *BtM1[2], *BtM2[2];
    {
        __nv_bfloat16* p;
        cudaGetSymbolAddress((void**)&p, g_BtProjN); BtProjN[0] = p; BtProjN[1] = p + 256 * 64;
        cudaGetSymbolAddress((void**)&p, g_BtProjB); BtProjB[0] = p; BtProjB[1] = p + 128 * 64;
        cudaGetSymbolAddress((void**)&p, g_BtL0);    BtL0[0] = p;    BtL0[1] = p + 5 * 128 * 128;
        cudaGetSymbolAddress((void**)&p, g_BtL1N);   BtL1N[0] = p;   BtL1N[1] = p + 128 * 512;
        cudaGetSymbolAddress((void**)&p, g_BtL1B);   BtL1B[0] = p;   BtL1B[1] = p + 128 * 384;
        cudaGetSymbolAddress((void**)&p, g_BtL2N);   BtL2N[0] = p;   BtL2N[1] = p + 128 * 512;
        cudaGetSymbolAddress((void**)&p, g_BtM1);    BtM1[0] = p;    BtM1[1] = p + 128 * 128;
        cudaGetSymbolAddress((void**)&p, g_BtM2);    BtM2[0] = p;    BtM2[1] = p + 128 * 128;
    }

    int ebase[5];
    { int acc = 0; for (int r = 0; r < 5; r++) { ebase[r] = acc; acc += E[r]; } }
    int maxE = 0;
    for (int r = 0; r < 5; r++) maxE = (E[r] > maxE) ? E[r] : maxE;

    // ---- prep (weights + biases + emode + zero counters), then CSR build ----
    prep_k<<<(PREP_TOTAL + 255) / 256, 256>>>(proj_W, proj_b, l0_Wl, l0_bl, l0_Wr,
                                              Wl, bl, Wr, mlp_W1, mlp_W2, bn_g, e[0]);
    counti5_k<<<dim3((maxE + 255) / 256, 5), 256>>>(e[0], e[1], e[2], e[3], e[4],
                                                    E[0], E[1], E[2], E[3], E[4]);
    scan1_k<<<dim3(NBX, 5), 256>>>();
    scan3_k<<<dim3(NBX, 5), 256>>>();
    fill5_k<<<dim3((maxE + 255) / 256, 5), 256>>>(e[0], e[1], e[2], e[3], e[4],
                                                  E[0], E[1], E[2], E[3], E[4],
                                                  ebase[0], ebase[1], ebase[2], ebase[3], ebase[4]);
    const int* rp[5]; const int* cx[5]; const float* ic[5];
    for (int r = 0; r < 5; r++) {
        rp[r] = rowp + r * (NN + 1);
        cx[r] = colx + ebase[r];
        ic[r] = cntf + r * NN;
    }

    const int NBLK_N = (NN + 7) / 8;
    const int NBLK_B = (NB + 7) / 8;

    auto mkjob = [&](Agg5& J, int s, const float* xf, int lds, int soff, int rel,
                     float* agg, int ldd, int doff, int n) {
        J.xf[s] = xf; J.lds[s] = lds; J.soff[s] = soff;
        J.rowp[s] = rp[rel]; J.col[s] = cx[rel]; J.invc[s] = ic[rel];
        J.agg[s] = agg; J.ldd[s] = ldd; J.doff[s] = doff; J.n[s] = n;
    };

    // ==================== layer 0 ====================
    {
        TGJob G;
        setslot(G, 0, x_note, 64, 64, nullptr, 0, 0, BtProjN[0], BtProjN[1], 64,
                pbCatN, pn, 192, 0, NN, 192, 1.f);
        setslot(G, 1, x_beat, 64, 64, nullptr, 0, 0, BtProjB[0], BtProjB[1], 64,
                pbCatB, pb, 128, 0, NB, 128, 1.f);
        tgemmJ(1, G, 2, nullptr, nullptr);
    }
    {
        Agg5 J; J.nslots = 5;
        mkjob(J, 0, pn, 192, 0,   0, aggn, 192, 0,   NN);
        mkjob(J, 1, pn, 192, 64,  1, aggn, 192, 64,  NN);
        mkjob(J, 2, pb, 128, 0,   3, aggn, 192, 128, NN);
        mkjob(J, 3, pn, 192, 128, 2, aggb, 128, 0,   NB);
        mkjob(J, 4, pb, 128, 64,  4, aggb, 128, 64,  NB);
        J.boff[0] = 0; J.boff[1] = NBLK_N; J.boff[2] = 2 * NBLK_N; J.boff[3] = 3 * NBLK_N;
        J.boff[4] = 3 * NBLK_N + NBLK_B; J.boff[5] = 3 * NBLK_N + 2 * NBLK_B;
        aggmulti_k<2><<<J.boff[5], 256>>>(J);
    }
    {
        TGJob G;
        for (int j = 0; j < 3; j++)
            setslot(G, j, x_note, 64, 64, aggn + j * 64, 192, 64,
                    BtL0[0] + j * 16384, BtL0[1] + j * 16384, 128,
                    l0blCatN + j * 128, On, 384, j * 128, NN, 128, 1.f);
        for (int j = 0; j < 2; j++)
            setslot(G, 3 + j, x_beat, 64, 64, aggb + j * 64, 128, 64,
                    BtL0[0] + (3 + j) * 16384, BtL0[1] + (3 + j) * 16384, 128,
                    l0blCatB + j * 128, Ob, 256, j * 128, NB, 128, 1.f);
        tgemmJ(0, G, 5, nullptr, nullptr);
    }
    l0post2_k<<<NBLK_N + NBLK_B, 256>>>(On, Ob, ln_g, ln_b, xn0, xb0, NBLK_N);

    // ==================== layer 1 (GEMM with fused relu+LN epilogue) =========
    {
        Agg5 J; J.nslots = 5;
        mkjob(J, 0, xn0, 128, 0, 0, aggn, 384, 0,   NN);
        mkjob(J, 1, xn0, 128, 0, 1, aggn, 384, 128, NN);
        mkjob(J, 2, xb0, 128, 0, 3, aggn, 384, 256, NN);
        mkjob(J, 3, xn0, 128, 0, 2, aggb, 256, 0,   NB);
        mkjob(J, 4, xb0, 128, 0, 4, aggb, 256, 128, NB);
        J.boff[0] = 0; J.boff[1] = NBLK_N; J.boff[2] = 2 * NBLK_N; J.boff[3] = 3 * NBLK_N;
        J.boff[4] = 3 * NBLK_N + NBLK_B; J.boff[5] = 3 * NBLK_N + 2 * NBLK_B;
        aggmulti_k<4><<<J.boff[5], 256>>>(J);
    }
    {
        TGJob G;
        setslot(G, 0, aggn, 384, 384, xn0, 128, 128, BtL1N[0], BtL1N[1], 512,
                b1SumN, xn1, 128, 0, NN, 128, 1.f, 1.f / 3.f);
        setslot(G, 1, aggb, 256, 256, xb0, 128, 128, BtL1B[0], BtL1B[1], 384,
                b1SumB, xb1, 128, 0, NB, 128, 1.f, 1.f / 2.f);
        tgemmJ(3, G, 2, ln_g + 128, ln_b + 128);
    }

    // ==================== layer 2 + final MLP (one fused kernel) =============
    {
        Agg5 J; J.nslots = 3;
        mkjob(J, 0, xn1, 128, 0, 0, aggn, 384, 0,   NN);
        mkjob(J, 1, xn1, 128, 0, 1, aggn, 384, 128, NN);
        mkjob(J, 2, xb1, 128, 0, 3, aggn, 384, 256, NN);
        J.boff[0] = 0; J.boff[1] = NBLK_N; J.boff[2] = 2 * NBLK_N; J.boff[3] = 3 * NBLK_N;
        J.boff[4] = 3 * NBLK_N; J.boff[5] = 3 * NBLK_N;
        aggmulti_k<4><<<J.boff[3], 256>>>(J);
    }
    {
        TGJob G;
        setslot(G, 0, aggn, 384, 384, xn1, 128, 128, BtL2N[0], BtL2N[1], 512,
                b2SumN, nullptr, 128, 0, NN, 128, 1.f, 1.f / 3.f);
        G.W1h = BtM1[0]; G.W1l = BtM1[1]; G.b1 = mlp_b1;
        G.W2h = BtM2[0]; G.W2l = BtM2[1]; G.b2 = mlp_b2;
        G.Cout = (float*)d_out;
        tgemmJ(5, G, 1, bnS, bn_b);
    }
}

// round 14
// speedup vs baseline: 1.0590x; 1.0590x over previous
#include <cuda_runtime.h>
#include <cuda_bf16.h>
#include <mma.h>
#include <cstdint>

using namespace nvcuda;

#define NN 100000
#define NB 20000
#define INC 64
#define HID 128
#define NBX 49
#define MAXE 3000000

// ================= scratch (device globals; no runtime allocation) ==========
__device__ float g_pn  [(size_t)NN * 192];
__device__ float g_pb  [(size_t)NB * 128];
__device__ float g_aggn[(size_t)NN * 384];
__device__ float g_aggb[(size_t)NB * 256];
__device__ float g_On  [(size_t)NN * 384];
__device__ float g_Ob  [(size_t)NB * 256];
__device__ float g_xn0 [(size_t)NN * HID];
__device__ float g_xn1 [(size_t)NN * HID];
__device__ float g_xb0 [(size_t)NB * HID];
__device__ float g_xb1 [(size_t)NB * HID];
__device__ float g_outn[(size_t)NN * HID];
__device__ float g_cnt [5][NN];
__device__ int   g_cnti[5][NN];
__device__ int   g_rowp[5][NN + 1];
__device__ int   g_bsum[5][64];
__device__ int   g_col [MAXE];
__device__ int   g_emode;

// bias scratch
__device__ float g_pbCatN[192];
__device__ float g_pbCatB[128];
__device__ float g_l0blCatN[384];
__device__ float g_l0blCatB[256];
__device__ float g_b1SumN[128];
__device__ float g_b1SumB[128];
__device__ float g_b2SumN[128];
__device__ float g_bnS[128];
// bf16 transposed+split weights [Npad x K], hi/lo
__device__ __nv_bfloat16 g_BtProjN[2][256 * 64];
__device__ __nv_bfloat16 g_BtProjB[2][128 * 64];
__device__ __nv_bfloat16 g_BtL0  [2][5][128 * 128];
__device__ __nv_bfloat16 g_BtL1N [2][128 * 512];
__device__ __nv_bfloat16 g_BtL1B [2][128 * 384];
__device__ __nv_bfloat16 g_BtL2N [2][128 * 512];
__device__ __nv_bfloat16 g_BtM1  [2][128 * 128];
__device__ __nv_bfloat16 g_BtM2  [2][128 * 128];

__device__ __forceinline__ int edge_at(const int* e, long long i) {
    if (g_emode) return (int)((const long long*)e)[i];
    return e[i];
}
__global__ void counti5_k(const int* e0, const int* e1, const int* e2,
                          const int* e3, const int* e4,
                          int E0, int E1, int E2, int E3, int E4) {
    int r = blockIdx.y;
    const int* e; int E;
    switch (r) {
        case 0: e = e0; E = E0; break;
        case 1: e = e1; E = E1; break;
        case 2: e = e2; E = E2; break;
        case 3: e = e3; E = E3; break;
        default: e = e4; E = E4; break;
    }
    int i = blockIdx.x * 256 + threadIdx.x;
    if (i >= E) return;
    atomicAdd(&g_cnti[r][edge_at(e, (long long)E + i)], 1);
}
__global__ void scan1_k() {
    int r = blockIdx.y;
    int n = (r == 2 || r == 4) ? NB : NN;
    int t = threadIdx.x;
    int base = blockIdx.x * 2048 + t * 8;
    int vals[8];
#pragma unroll
    for (int j = 0; j < 8; j++) {
        int idx = base + j;
        vals[j] = (idx < n) ? g_cnti[r][idx] : 0;
        if (idx < n) g_cnt[r][idx] = 1.0f / (float)max(vals[j], 1);
    }
    int tot = 0;
#pragma unroll
    for (int j = 0; j < 8; j++) tot += vals[j];
    int lane = t & 31, wid = t >> 5;
    int x = tot;
#pragma unroll
    for (int o = 1; o < 32; o <<= 1) {
        int y = __shfl_up_sync(0xffffffffu, x, o);
        if (lane >= o) x += y;
    }
    __shared__ int wsum[8];
    if (lane == 31) wsum[wid] = x;
    __syncthreads();
    if (t == 0) {
        int run = 0;
#pragma unroll
        for (int i = 0; i < 8; i++) { int v = wsum[i]; wsum[i] = run; run += v; }
        g_bsum[r][blockIdx.x] = run;
    }
    __syncthreads();
    int run = (x - tot) + wsum[wid];
#pragma unroll
    for (int j = 0; j < 8; j++) {
        int idx = base + j;
        if (idx < n) g_rowp[r][idx] = run;
        run += vals[j];
    }
}
__global__ void scan3_k() {
    int r = blockIdx.y;
    int n = (r == 2 || r == 4) ? NB : NN;
    int bx = blockIdx.x;
    int t = threadIdx.x;
    __shared__ int sb[64];
    __shared__ int s_add;
    if (t < 64) sb[t] = (t < NBX) ? g_bsum[r][t] : 0;
    __syncthreads();
    if (t == 0) {
        int a = 0;
        for (int i = 0; i < bx; i++) a += sb[i];
        s_add = a;
        if (bx == NBX - 1) g_rowp[r][n] = a + sb[NBX - 1];
    }
    __syncthreads();
    int add = s_add;
    int base = bx * 2048 + t * 8;
#pragma unroll
    for (int j = 0; j < 8; j++) {
        int idx = base + j;
        if (idx < n) {
            int v = g_rowp[r][idx] + add;
            g_rowp[r][idx] = v;
            g_cnti[r][idx] = v;
        }
    }
}
__global__ void fill5_k(const int* e0, const int* e1, const int* e2,
                        const int* e3, const int* e4,
                        int E0, int E1, int E2, int E3, int E4,
                        int b0, int b1, int b2, int b3, int b4) {
    int r = blockIdx.y;
    const int* e; int E; int eb;
    switch (r) {
        case 0: e = e0; E = E0; eb = b0; break;
        case 1: e = e1; E = E1; eb = b1; break;
        case 2: e = e2; E = E2; eb = b2; break;
        case 3: e = e3; E = E3; eb = b3; break;
        default: e = e4; E = E4; eb = b4; break;
    }
    int i = blockIdx.x * 256 + threadIdx.x;
    if (i >= E) return;
    int s = edge_at(e, i);
    int d = edge_at(e, (long long)E + i);
    int pos = atomicAdd(&g_cnti[r][d], 1);
    g_col[eb + pos] = s;
}

// ---- merged CSR seg-mean aggregation (job table, warp per dst row) ---------
struct Agg5 {
    const float* xf[5];
    const int* rowp[5];
    const int* col[5];
    const float* invc[5];
    float* agg[5];
    int lds[5], soff[5], ldd[5], doff[5], n[5];
    int boff[6];
    int nslots;
};

template <int V>
__global__ void aggmulti_k(Agg5 J) {
    int b = blockIdx.x;
    int s = 0;
    while (s + 1 < J.nslots && b >= J.boff[s + 1]) s++;
    int row = (b - J.boff[s]) * 8 + (threadIdx.x >> 5);
    if (row >= J.n[s]) return;
    int lane = threadIdx.x & 31;
    const float* xf = J.xf[s];
    const int* col = J.col[s];
    int lds = J.lds[s], soff = J.soff[s];
    int beg = J.rowp[s][row], end = J.rowp[s][row + 1];
    float acc[V];
#pragma unroll
    for (int j = 0; j < V; j++) acc[j] = 0.0f;
    int e = beg;
    for (; e + 7 < end; e += 8) {
        int si[8];
#pragma unroll
        for (int u = 0; u < 8; u++) si[u] = __ldg(&col[e + u]);
        if (V == 4) {
            float4 vv[8];
#pragma unroll
            for (int u = 0; u < 8; u++)
                vv[u] = *(const float4*)(xf + (size_t)si[u] * lds + soff + lane * V);
#pragma unroll
            for (int u = 0; u < 8; u++) {
                acc[0] += vv[u].x; acc[1] += vv[u].y;
                acc[2] += vv[u].z; acc[3] += vv[u].w;
            }
        } else {
            float2 vv[8];
#pragma unroll
            for (int u = 0; u < 8; u++)
                vv[u] = *(const float2*)(xf + (size_t)si[u] * lds + soff + lane * V);
#pragma unroll
            for (int u = 0; u < 8; u++) {
                acc[0] += vv[u].x; acc[1] += vv[u].y;
            }
        }
    }
    for (; e < end; e++) {
        int s0 = __ldg(&col[e]);
        const float* p0 = xf + (size_t)s0 * lds + soff + lane * V;
        if (V == 4) {
            float4 a = *(const float4*)p0;
            acc[0] += a.x; acc[1] += a.y; acc[2] += a.z; acc[3] += a.w;
        } else {
            float2 a = *(const float2*)p0;
            acc[0] += a.x; acc[1] += a.y;
        }
    }
    float inv = J.invc[s][row];
    float* q = J.agg[s] + (size_t)row * J.ldd[s] + J.doff[s] + lane * V;
    if (V == 4) {
        *(float4*)q = make_float4(acc[0] * inv, acc[1] * inv, acc[2] * inv, acc[3] * inv);
    } else {
        *(float2*)q = make_float2(acc[0] * inv, acc[1] * inv);
    }
}

// ================= cp.async helpers =========================================
__device__ __forceinline__ void cp16(uint32_t dst, const void* src) {
    asm volatile("cp.async.ca.shared.global [%0], [%1], 16;" :: "r"(dst), "l"(src));
}
__device__ __forceinline__ void cp_commit() {
    asm volatile("cp.async.commit_group;");
}
__device__ __forceinline__ void cp_wait0() {
    asm volatile("cp.async.wait_group 0;" ::: "memory");
}

__device__ __forceinline__ void bsplit(float x, __nv_bfloat16& h, __nv_bfloat16& l) {
    h = __float2bfloat16_rn(x);
    l = __float2bfloat16_rn(x - __bfloat162float(h));
}

// ================= wmma bf16 split GEMM (job table, cp.async B) =============
// EPI: 0 plain, 1 relu, 3 relu+LN fused (Nfull==128),
//      4 relu+BN -> h@W2+b2 -> Cout (fused MLP).
struct TGJob {
    const float* A1[5];
    const float* A2[5];
    const __nv_bfloat16* Bhi[5];
    const __nv_bfloat16* Blo[5];
    const float* bias[5];
    float* C[5];
    int lda1[5], K1[5], lda2[5], K2[5], ldK[5], ldc[5], coff[5], M[5], Nfull[5];
    float alpha[5];
    float invr[5];
    // EPI=4 extras (slot 0 only)
    const __nv_bfloat16* W2h;
    const __nv_bfloat16* W2l;
    const float* b2;
    float* Cout;
};
#define TG_DSM 81920
template <int EPI>
__global__ __launch_bounds__(256) void tgemm_k(
    TGJob J, const float* __restrict__ bnS, const float* __restrict__ bnB)
{
    extern __shared__ char dynsmem[];
    __nv_bfloat16* Asm = reinterpret_cast<__nv_bfloat16*>(dynsmem);
    __nv_bfloat16* Bsm = reinterpret_cast<__nv_bfloat16*>(dynsmem + 40960);
    uint32_t Bu32 = (uint32_t)__cvta_generic_to_shared(Bsm);

    int z = blockIdx.z;
    const float* A1 = J.A1[z];
    const float* A2 = J.A2[z];
    const __nv_bfloat16* Bhi = J.Bhi[z];
    const __nv_bfloat16* Blo = J.Blo[z];
    const float* bias = J.bias[z];
    float* C = J.C[z];
    int lda1 = J.lda1[z], K1 = J.K1[z], lda2 = J.lda2[z], K2 = J.K2[z];
    int ldK = J.ldK[z], ldc = J.ldc[z], coff = J.coff[z];
    int M = J.M[z], Nfull = J.Nfull[z];
    float alpha = J.alpha[z];

    int m0 = blockIdx.x * 128;
    int n0 = blockIdx.y * 128;
    if (m0 >= M || n0 >= Nfull) return;

    int tid = threadIdx.x;
    int wid = tid >> 5, lane = tid & 31;
    int wm = wid >> 2, wn = wid & 3;
    int mw = m0 + wm * 64;
    int nw = n0 + wn * 32;
    int nl = wn * 32;
    bool active = (nw < Nfull);
    int K = K1 + K2;
    int nkt = K >> 5;

    wmma::fragment<wmma::accumulator, 16, 16, 16, float> acc[4][2];
#pragma unroll
    for (int i = 0; i < 4; i++)
#pragma unroll
        for (int j = 0; j < 2; j++) wmma::fill_fragment(acc[i][j], 0.0f);

    int row = tid >> 1, half = tid & 1;
    int m = m0 + row;
    bool mok = (m < M);
    int brow = row, bhalf = half;

    // ---- prologue ----
    float4 v[4];
    {
        const float* Ap; int ld, kl;
        if (0 < K1) { Ap = A1; ld = lda1; kl = 0; }
        else        { Ap = A2; ld = lda2; kl = -K1; }
        const float* src = Ap + (size_t)m * ld + kl + half * 16;
#pragma unroll
        for (int i = 0; i < 4; i++)
            v[i] = mok ? *(const float4*)(src + i * 4) : make_float4(0.f, 0.f, 0.f, 0.f);
    }
    {
        const __nv_bfloat16* sH = Bhi + (size_t)(n0 + brow) * ldK + bhalf * 16;
        const __nv_bfloat16* sL = Blo + (size_t)(n0 + brow) * ldK + bhalf * 16;
        uint32_t dH = Bu32 + (uint32_t)(((0 * 2 + 0) * 128 + brow) * 40 + bhalf * 16) * 2;
        uint32_t dL = Bu32 + (uint32_t)(((0 * 2 + 1) * 128 + brow) * 40 + bhalf * 16) * 2;
        cp16(dH, sH); cp16(dH + 16, sH + 8);
        cp16(dL, sL); cp16(dL + 16, sL + 8);
        cp_commit();
    }

    int buf = 0;
    for (int kt = 0; kt < nkt; kt++) {
        {
            __nv_bfloat162* ah = reinterpret_cast<__nv_bfloat162*>(
                Asm + ((buf * 2 + 0) * 128 + row) * 40);
            __nv_bfloat162* al = reinterpret_cast<__nv_bfloat162*>(
                Asm + ((buf * 2 + 1) * 128 + row) * 40);
#pragma unroll
            for (int i = 0; i < 4; i++) {
                int col = half * 16 + i * 4;
                float4 x = v[i];
                __nv_bfloat16 hx = __float2bfloat16_rn(x.x);
                __nv_bfloat16 hy = __float2bfloat16_rn(x.y);
                __nv_bfloat16 hz = __float2bfloat16_rn(x.z);
                __nv_bfloat16 hw = __float2bfloat16_rn(x.w);
                __nv_bfloat162 h01; h01.x = hx; h01.y = hy;
                __nv_bfloat162 h23; h23.x = hz; h23.y = hw;
                ah[(col >> 1) + 0] = h01;
                ah[(col >> 1) + 1] = h23;
                __nv_bfloat162 l01, l23;
                l01.x = __float2bfloat16_rn(x.x - __bfloat162float(hx));
                l01.y = __float2bfloat16_rn(x.y - __bfloat162float(hy));
                l23.x = __float2bfloat16_rn(x.z - __bfloat162float(hz));
                l23.y = __float2bfloat16_rn(x.w - __bfloat162float(hw));
                al[(col >> 1) + 0] = l01;
                al[(col >> 1) + 1] = l23;
            }
        }
        cp_wait0();
        __syncthreads();
        if (kt + 1 < nkt) {
            int k0n = (kt + 1) << 5;
            const __nv_bfloat16* sH = Bhi + (size_t)(n0 + brow) * ldK + k0n + bhalf * 16;
            const __nv_bfloat16* sL = Blo + (size_t)(n0 + brow) * ldK + k0n + bhalf * 16;
            int ob = buf ^ 1;
            uint32_t dH = Bu32 + (uint32_t)(((ob * 2 + 0) * 128 + brow) * 40 + bhalf * 16) * 2;
            uint32_t dL = Bu32 + (uint32_t)(((ob * 2 + 1) * 128 + brow) * 40 + bhalf * 16) * 2;
            cp16(dH, sH); cp16(dH + 16, sH + 8);
            cp16(dL, sL); cp16(dL + 16, sL + 8);
            cp_commit();
            const float* Ap; int ld, kl;
            if (k0n < K1) { Ap = A1; ld = lda1; kl = k0n; }
            else          { Ap = A2; ld = lda2; kl = k0n - K1; }
            const float* src = Ap + (size_t)m * ld + kl + half * 16;
#pragma unroll
            for (int i = 0; i < 4; i++)
                v[i] = mok ? *(const float4*)(src + i * 4) : make_float4(0.f, 0.f, 0.f, 0.f);
        }
        if (active) {
            const __nv_bfloat16* BsH = Bsm + (buf * 2 + 0) * 128 * 40;
            const __nv_bfloat16* BsL = Bsm + (buf * 2 + 1) * 128 * 40;
#pragma unroll
            for (int kk = 0; kk < 32; kk += 16) {
                wmma::fragment<wmma::matrix_b, 16, 16, 16, __nv_bfloat16, wmma::col_major> bh[2], bl2[2];
#pragma unroll
                for (int j = 0; j < 2; j++) {
                    wmma::load_matrix_sync(bh[j],  BsH + (nl + j * 16) * 40 + kk, 40u);
                    wmma::load_matrix_sync(bl2[j], BsL + (nl + j * 16) * 40 + kk, 40u);
                }
#pragma unroll
                for (int i = 0; i < 4; i++) {
                    wmma::fragment<wmma::matrix_a, 16, 16, 16, __nv_bfloat16, wmma::row_major> ah, al;
                    wmma::load_matrix_sync(ah, Asm + ((buf * 2 + 0) * 128 + wm * 64 + i * 16) * 40 + kk, 40u);
                    wmma::load_matrix_sync(al, Asm + ((buf * 2 + 1) * 128 + wm * 64 + i * 16) * 40 + kk, 40u);
#pragma unroll
                    for (int j = 0; j < 2; j++) {
                        wmma::mma_sync(acc[i][j], ah, bh[j],  acc[i][j]);
                        wmma::mma_sync(acc[i][j], ah, bl2[j], acc[i][j]);
                        wmma::mma_sync(acc[i][j], al, bh[j],  acc[i][j]);
                    }
                }
            }
        }
        buf ^= 1;
    }
    __syncthreads();

    if (EPI == 3) {
        // ---- fused relu -> LayerNorm epilogue (Nfull == 128) ----
        float* obuf = reinterpret_cast<float*>(dynsmem);   // 128 x 132 f32
#pragma unroll
        for (int i = 0; i < 4; i++)
#pragma unroll
            for (int j = 0; j < 2; j++)
                wmma::store_matrix_sync(obuf + (wm * 64 + i * 16) * 132 + nl + j * 16,
                                        acc[i][j], 132u, wmma::mem_row_major);
        __syncthreads();
        float invr = J.invr[z];
        int r0 = wid * 16;
        for (int rr = 0; rr < 16; rr++) {
            int rloc = r0 + rr;
            int mm = m0 + rloc;
            if (mm >= M) continue;
            float vv[4]; float s = 0.f;
#pragma unroll
            for (int j = 0; j < 4; j++) {
                int c = lane + 32 * j;
                float val = obuf[rloc * 132 + c] * alpha + bias[c];
                vv[j] = fmaxf(val * invr, 0.f);
                s += vv[j];
            }
#pragma unroll
            for (int o = 16; o; o >>= 1) s += __shfl_xor_sync(0xffffffffu, s, o);
            float mean = s * (1.0f / 128.0f);
            float ss = 0.f;
#pragma unroll
            for (int j = 0; j < 4; j++) { float d = vv[j] - mean; ss += d * d; }
#pragma unroll
            for (int o = 16; o; o >>= 1) ss += __shfl_xor_sync(0xffffffffu, ss, o);
            float inv = rsqrtf(ss * (1.0f / 128.0f) + 1e-5f);
            float* q = C + (size_t)mm * ldc;
#pragma unroll
            for (int j = 0; j < 4; j++) {
                int c = lane + 32 * j;
                q[c] = (vv[j] - mean) * inv * bnS[c] + bnB[c];
            }
        }
    } else if (EPI == 4) {
        // ---- relu+BN -> h (bf16 hi/lo, stride 136) -> h@W2+b2 -> Cout ----
        // smem: hHb/hLb = 2*128*136*2 = 69632 at 0; patch 8*320 f32 at 69632;
        // total 79872 <= 81920.
        __nv_bfloat16* hHb = reinterpret_cast<__nv_bfloat16*>(dynsmem);
        __nv_bfloat16* hLb = hHb + 128 * 136;
        float* myp = reinterpret_cast<float*>(dynsmem + 69632) + wid * 320;
        int base = lane * 8;
        int pr = base >> 4, pc = base & 15;
#pragma unroll
        for (int i = 0; i < 4; i++) {
#pragma unroll
            for (int j = 0; j < 2; j++) {
                wmma::store_matrix_sync(myp, acc[i][j], 20u, wmma::mem_row_major);
                __syncwarp();
                int rloc = wm * 64 + i * 16 + pr;
                int nb = nl + j * 16;
                bool rok = (m0 + rloc < M);
#pragma unroll
                for (int t = 0; t < 8; t++) {
                    int n = nb + pc + t;
                    float val = rok ? (myp[pr * 20 + pc + t] * alpha + bias[n]) : 0.f;
                    val = fmaxf(val, 0.f) * bnS[n] + bnB[n];
                    __nv_bfloat16 hh, ll;
                    bsplit(val, hh, ll);
                    hHb[rloc * 136 + n] = hh;
                    hLb[rloc * 136 + n] = ll;
                }
                __syncwarp();
            }
        }
        __syncthreads();
        wmma::fragment<wmma::accumulator, 16, 16, 16, float> acc2[2];
#pragma unroll
        for (int j = 0; j < 2; j++) wmma::fill_fragment(acc2[j], 0.0f);
        const __nv_bfloat16* W2h = J.W2h;
        const __nv_bfloat16* W2l = J.W2l;
        int r0 = wid * 16;
#pragma unroll
        for (int kf = 0; kf < 8; kf++) {
            wmma::fragment<wmma::matrix_a, 16, 16, 16, __nv_bfloat16, wmma::row_major> ah, al;
            wmma::load_matrix_sync(ah, hHb + r0 * 136 + kf * 16, 136u);
            wmma::load_matrix_sync(al, hLb + r0 * 136 + kf * 16, 136u);
#pragma unroll
            for (int j = 0; j < 2; j++) {
                wmma::fragment<wmma::matrix_b, 16, 16, 16, __nv_bfloat16, wmma::col_major> bh, bl2;
                wmma::load_matrix_sync(bh,  W2h + (size_t)(j * 16) * 128 + kf * 16, 128u);
                wmma::load_matrix_sync(bl2, W2l + (size_t)(j * 16) * 128 + kf * 16, 128u);
                wmma::mma_sync(acc2[j], ah, bh,  acc2[j]);
                wmma::mma_sync(acc2[j], ah, bl2, acc2[j]);
                wmma::mma_sync(acc2[j], al, bh,  acc2[j]);
            }
        }
        const float* b2 = J.b2;
        float* Cout = J.Cout;
#pragma unroll
        for (int j = 0; j < 2; j++) {
            wmma::store_matrix_sync(myp, acc2[j], 20u, wmma::mem_row_major);
            __syncwarp();
            int mm = m0 + r0 + pr;
            if (mm < M) {
                float out[8];
#pragma unroll
                for (int t = 0; t < 8; t++) {
                    int n = j * 16 + pc + t;
                    out[t] = myp[pr * 20 + pc + t] + b2[n];
                }
                float* dst = Cout + (size_t)mm * 32 + j * 16 + pc;
                *(float4*)dst = *(float4*)&out[0];
                *(float4*)(dst + 4) = *(float4*)&out[4];
            }
            __syncwarp();
        }
    } else if (active) {
        float* myp = reinterpret_cast<float*>(dynsmem) + wid * 320;
        int base = lane * 8;
        int pr = base >> 4, pc = base & 15;
#pragma unroll
        for (int i = 0; i < 4; i++) {
#pragma unroll
            for (int j = 0; j < 2; j++) {
                wmma::store_matrix_sync(myp, acc[i][j], 20u, wmma::mem_row_major);
                __syncwarp();
                int mb = mw + i * 16, nb = nw + j * 16;
                if (mb + pr < M) {
                    float out[8];
#pragma unroll
                    for (int t = 0; t < 8; t++) {
                        int n = nb + pc + t;
                        float val = myp[pr * 20 + pc + t] * alpha + bias[n];
                        if (EPI >= 1) val = fmaxf(val, 0.0f);
                        out[t] = val;
                    }
                    float* dst = C + (size_t)(mb + pr) * ldc + coff + nb + pc;
                    *(float4*)dst = *(float4*)&out[0];
                    *(float4*)(dst + 4) = *(float4*)&out[4];
                }
                __syncwarp();
            }
        }
    }
}

// ================= merged elementwise: layer-0 post ==========================
__global__ void l0post2_k(const float* __restrict__ On, const float* __restrict__ Ob,
                          const float* __restrict__ gg, const float* __restrict__ bb,
                          float* __restrict__ xn, float* __restrict__ xb, int nblkN) {
    int b = blockIdx.x;
    const float* O; float* xout; int ldo, M, R;
    if (b < nblkN) { O = On; xout = xn; ldo = 384; M = NN; R = 3; }
    else           { O = Ob; xout = xb; ldo = 256; M = NB; R = 2; b -= nblkN; }
    int row = b * 8 + (threadIdx.x >> 5);
    if (row >= M) return;
    int lane = threadIdx.x & 31;
    float acc[4] = {0.f, 0.f, 0.f, 0.f};
    for (int rb = 0; rb < R; rb++) {
        const float* p = O + (size_t)row * ldo + rb * 128;
        float v[4]; float ss = 0.f;
#pragma unroll
        for (int j = 0; j < 4; j++) { v[j] = p[lane + 32 * j]; ss += v[j] * v[j]; }
#pragma unroll
        for (int s = 16; s; s >>= 1) ss += __shfl_xor_sync(0xffffffffu, ss, s);
        float inv = 1.0f / fmaxf(sqrtf(ss), 1e-12f);
#pragma unroll
        for (int j = 0; j < 4; j++) acc[j] += v[j] * inv;
    }
    const float invR = 1.0f / R;
    float s = 0.f;
#pragma unroll
    for (int j = 0; j < 4; j++) { acc[j] = fmaxf(acc[j] * invR, 0.f); s += acc[j]; }
#pragma unroll
    for (int o = 16; o; o >>= 1) s += __shfl_xor_sync(0xffffffffu, s, o);
    float m = s * (1.0f / 128.0f);
    float ss = 0.f;
#pragma unroll
    for (int j = 0; j < 4; j++) { float d = acc[j] - m; ss += d * d; }
#pragma unroll
    for (int o = 16; o; o >>= 1) ss += __shfl_xor_sync(0xffffffffu, ss, o);
    float inv = rsqrtf(ss * (1.0f / 128.0f) + 1e-5f);
    float* q = xout + (size_t)row * 128;
#pragma unroll
    for (int j = 0; j < 4; j++) {
        int c = lane + 32 * j;
        q[c] = (acc[j] - m) * inv * gg[c] + bb[c];
    }
}

// ================= fused weight-prep + init kernel ===========================
__device__ __forceinline__ void lsplit_body(__nv_bfloat16* hi, __nv_bfloat16* lo,
                                            const float* WlL, const float* WrL,
                                            int r0, int r1, int r2, int nrel, int idx) {
    int K = nrel * 128 + 128;
    int n = idx / K, k = idx - n * K;
    float x;
    if (k < nrel * 128) {
        int j = k >> 7, kk = k & 127;
        int r = (j == 0) ? r0 : (j == 1) ? r1 : r2;
        x = WlL[(size_t)r * 16384 + kk * 128 + n];
    } else {
        int kk = k - nrel * 128;
        x = WrL[(size_t)r0 * 16384 + kk * 128 + n] + WrL[(size_t)r1 * 16384 + kk * 128 + n];
        if (nrel == 3) x += WrL[(size_t)r2 * 16384 + kk * 128 + n];
    }
    __nv_bfloat16 h, l;
    bsplit(x, h, l);
    hi[idx] = h;
    lo[idx] = l;
}
#define PREP_TOTAL (305152 + 5 * NN)
__global__ void prep_k(const float* __restrict__ proj_W, const float* __restrict__ proj_b,
                       const float* __restrict__ l0_Wl, const float* __restrict__ l0_bl,
                       const float* __restrict__ l0_Wr,
                       const float* __restrict__ Wl, const float* __restrict__ bl,
                       const float* __restrict__ Wr,
                       const float* __restrict__ mlp_W1, const float* __restrict__ mlp_W2,
                       const float* __restrict__ bn_g, const int* __restrict__ e0) {
    int idx = blockIdx.x * 256 + threadIdx.x;
    __nv_bfloat16 h, l;
    if (idx < 12288) {
        int j = idx >> 12, rem = idx & 4095;
        int k = rem >> 6, c = rem & 63;
        float x = proj_W[(size_t)j * 4096 + k * 64 + c];
        int n = j * 64 + c;
        bsplit(x, h, l);
        g_BtProjN[0][n * 64 + k] = h; g_BtProjN[1][n * 64 + k] = l;
        return;
    }
    idx -= 12288;
    if (idx < 8192) {
        int j = idx >> 12, rem = idx & 4095;
        int k = rem >> 6, c = rem & 63;
        int r = (j == 0) ? 3 : 4;
        float x = proj_W[(size_t)r * 4096 + k * 64 + c];
        int n = j * 64 + c;
        bsplit(x, h, l);
        g_BtProjB[0][n * 64 + k] = h; g_BtProjB[1][n * 64 + k] = l;
        return;
    }
    idx -= 8192;
    if (idx < 81920) {
        int s = idx >> 14, rem = idx & 16383;
        int n = rem >> 7, k = rem & 127;
        const int rels[5] = {0, 1, 3, 2, 4};
        int r = rels[s];
        float x = (k < 64) ? l0_Wr[(size_t)r * 8192 + k * 128 + n]
                           : l0_Wl[(size_t)r * 8192 + (k - 64) * 128 + n];
        bsplit(x, h, l);
        g_BtL0[0][s][rem] = h; g_BtL0[1][s][rem] = l;
        return;
    }
    idx -= 81920;
    if (idx < 65536) { lsplit_body(g_BtL1N[0], g_BtL1N[1], Wl, Wr, 0, 1, 3, 3, idx); return; }
    idx -= 65536;
    if (idx < 49152) { lsplit_body(g_BtL1B[0], g_BtL1B[1], Wl, Wr, 2, 4, 0, 2, idx); return; }
    idx -= 49152;
    if (idx < 65536) { lsplit_body(g_BtL2N[0], g_BtL2N[1], Wl + 5 * 16384, Wr + 5 * 16384, 0, 1, 3, 3, idx); return; }
    idx -= 65536;
    if (idx < 16384) {
        int k = idx >> 7, n = idx & 127;
        bsplit(mlp_W1[idx], h, l);
        g_BtM1[0][n * 128 + k] = h; g_BtM1[1][n * 128 + k] = l;
        return;
    }
    idx -= 16384;
    if (idx < 4096) {
        int k = idx / 32, n = idx - (idx / 32) * 32;
        bsplit(mlp_W2[idx], h, l);
        g_BtM2[0][n * 128 + k] = h; g_BtM2[1][n * 128 + k] = l;
        return;
    }
    idx -= 4096;
    if (idx < 2048) {
        int t = idx;
        if (t < 192) {
            int j = t / 64;
            g_pbCatN[t] = proj_b[(size_t)j * 64 + (t - j * 64)];
        } else if (t < 320) {
            int local = t - 192; int j = local / 64;
            int r = (j == 0) ? 3 : 4;
            g_pbCatB[local] = proj_b[(size_t)r * 64 + (local - j * 64)];
        } else if (t < 704) {
            int local = t - 320; int j = local / 128;
            int r = (j == 0) ? 0 : (j == 1) ? 1 : 3;
            g_l0blCatN[local] = l0_bl[(size_t)r * 128 + (local - j * 128)];
        } else if (t < 960) {
            int local = t - 704; int j = local / 128;
            int r = (j == 0) ? 2 : 4;
            g_l0blCatB[local] = l0_bl[(size_t)r * 128 + (local - j * 128)];
        } else if (t < 1088) {
            int i = t - 960;
            g_b1SumN[i] = bl[i] + bl[128 + i] + bl[3 * 128 + i];
        } else if (t < 1216) {
            int i = t - 1088;
            g_b1SumB[i] = bl[2 * 128 + i] + bl[4 * 128 + i];
        } else if (t < 1344) {
            int i = t - 1216;
            g_b2SumN[i] = bl[(5 + 0) * 128 + i] + bl[(5 + 1) * 128 + i] + bl[(5 + 3) * 128 + i];
        } else if (t < 1472) {
            int i = t - 1344;
            g_bnS[i] = bn_g[i] * rsqrtf(1.0f + 1e-5f);
        } else if (t == 1472) {
            int z = 1;
            for (int i = 1; i < 64; i += 2)
                if (e0[i] != 0) z = 0;
            g_emode = z;
        }
        return;
    }
    idx -= 2048;
    if (idx < 5 * NN) ((int*)g_cnti)[idx] = 0;
}

// ================= host dispatch =============================================
static void tgemmJ(int epi, const TGJob& J, int nslots, const float* p0, const float* p1) {
    int maxM = 0, maxN = 0;
    for (int s = 0; s < nslots; s++) {
        if (J.M[s] > maxM) maxM = J.M[s];
        if (J.Nfull[s] > maxN) maxN = J.Nfull[s];
    }
    dim3 g((maxM + 127) / 128, (maxN + 127) / 128, nslots);
    if (epi == 0) {
        cudaFuncSetAttribute(tgemm_k<0>, cudaFuncAttributeMaxDynamicSharedMemorySize, TG_DSM);
        tgemm_k<0><<<g, 256, TG_DSM>>>(J, p0, p1);
    } else if (epi == 1) {
        cudaFuncSetAttribute(tgemm_k<1>, cudaFuncAttributeMaxDynamicSharedMemorySize, TG_DSM);
        tgemm_k<1><<<g, 256, TG_DSM>>>(J, p0, p1);
    } else if (epi == 3) {
        cudaFuncSetAttribute(tgemm_k<3>, cudaFuncAttributeMaxDynamicSharedMemorySize, TG_DSM);
        tgemm_k<3><<<g, 256, TG_DSM>>>(J, p0, p1);
    } else {
        cudaFuncSetAttribute(tgemm_k<4>, cudaFuncAttributeMaxDynamicSharedMemorySize, TG_DSM);
        tgemm_k<4><<<g, 256, TG_DSM>>>(J, p0, p1);
    }
}
static void setslot(TGJob& J, int s, const float* A1, int lda1, int K1,
                    const float* A2, int lda2, int K2,
                    const __nv_bfloat16* Bh, const __nv_bfloat16* Bl, int ldK,
                    const float* bias, float* C, int ldc, int coff,
                    int M, int Nfull, float alpha, float invr = 1.0f) {
    J.A1[s] = A1; J.lda1[s] = lda1; J.K1[s] = K1;
    J.A2[s] = A2; J.lda2[s] = lda2; J.K2[s] = K2;
    J.Bhi[s] = Bh; J.Blo[s] = Bl; J.ldK[s] = ldK;
    J.bias[s] = bias; J.C[s] = C; J.ldc[s] = ldc; J.coff[s] = coff;
    J.M[s] = M; J.Nfull[s] = Nfull; J.alpha[s] = alpha; J.invr[s] = invr;
}

extern "C" void kernel_launch(void* const* d_in, const int* in_sizes, int n_in,
                              void* d_out, int out_size) {
    const float* x_note = (const float*)d_in[0];
    const float* x_beat = (const float*)d_in[1];
    const int* e[5] = {(const int*)d_in[2], (const int*)d_in[3], (const int*)d_in[4],
                       (const int*)d_in[5], (const int*)d_in[6]};
    int E[5];
    for (int r = 0; r < 5; r++) E[r] = in_sizes[2 + r] / 2;
    const float* proj_W = (const float*)d_in[7];
    const float* proj_b = (const float*)d_in[8];
    const float* l0_Wl  = (const float*)d_in[9];
    const float* l0_bl  = (const float*)d_in[10];
    const float* l0_Wr  = (const float*)d_in[11];
    const float* Wl     = (const float*)d_in[12];
    const float* bl     = (const float*)d_in[13];
    const float* Wr     = (const float*)d_in[14];
    const float* ln_g   = (const float*)d_in[15];
    const float* ln_b   = (const float*)d_in[16];
    const float* mlp_W1 = (const float*)d_in[17];
    const float* mlp_b1 = (const float*)d_in[18];
    const float* bn_g   = (const float*)d_in[19];
    const float* bn_b   = (const float*)d_in[20];
    const float* mlp_W2 = (const float*)d_in[21];
    const float* mlp_b2 = (const float*)d_in[22];

    float *pn, *pb, *aggn, *aggb, *On, *Ob, *xn0, *xn1, *xb0, *xb1, *outn, *cntf;
    int *rowp, *colx;
    cudaGetSymbolAddress((void**)&pn, g_pn);       cudaGetSymbolAddress((void**)&pb, g_pb);
    cudaGetSymbolAddress((void**)&aggn, g_aggn);   cudaGetSymbolAddress((void**)&aggb, g_aggb);
    cudaGetSymbolAddress((void**)&On, g_On);       cudaGetSymbolAddress((void**)&Ob, g_Ob);
    cudaGetSymbolAddress((void**)&xn0, g_xn0);     cudaGetSymbolAddress((void**)&xn1, g_xn1);
    cudaGetSymbolAddress((void**)&xb0, g_xb0);     cudaGetSymbolAddress((void**)&xb1, g_xb1);
    cudaGetSymbolAddress((void**)&outn, g_outn);
    cudaGetSymbolAddress((void**)&cntf, g_cnt);
    cudaGetSymbolAddress((void**)&rowp, g_rowp);   cudaGetSymbolAddress((void**)&colx, g_col);

    float *pbCatN, *pbCatB, *l0blCatN, *l0blCatB, *b1SumN, *b1SumB, *b2SumN, *bnS;
    cudaGetSymbolAddress((void**)&pbCatN, g_pbCatN);     cudaGetSymbolAddress((void**)&pbCatB, g_pbCatB);
    cudaGetSymbolAddress((void**)&l0blCatN, g_l0blCatN); cudaGetSymbolAddress((void**)&l0blCatB, g_l0blCatB);
    cudaGetSymbolAddress((void**)&b1SumN, g_b1SumN);     cudaGetSymbolAddress((void**)&b1SumB, g_b1SumB);
    cudaGetSymbolAddress((void**)&b2SumN, g_b2SumN);     cudaGetSymbolAddress((void**)&bnS, g_bnS);

    __nv_bfloat16 *BtProjN[2], *BtProjB[2], *BtL0[2], *BtL1N[2], *BtL1B[2], *BtL2N[2], *BtM1[2], *BtM2[2];
    {
        __nv_bfloat16* p;
        cudaGetSymbolAddress((void**)&p, g_BtProjN); BtProjN[0] = p; BtProjN[1] = p + 256 * 64;
        cudaGetSymbolAddress((void**)&p, g_BtProjB); BtProjB[0] = p; BtProjB[1] = p + 128 * 64;
        cudaGetSymbolAddress((void**)&p, g_BtL0);    BtL0[0] = p;    BtL0[1] = p + 5 * 128 * 128;
        cudaGetSymbolAddress((void**)&p, g_BtL1N);   BtL1N[0] = p;   BtL1N[1] = p + 128 * 512;
        cudaGetSymbolAddress((void**)&p, g_BtL1B);   BtL1B[0] = p;   BtL1B[1] = p + 128 * 384;
        cudaGetSymbolAddress((void**)&p, g_BtL2N);   BtL2N[0] = p;   BtL2N[1] = p + 128 * 512;
        cudaGetSymbolAddress((void**)&p, g_BtM1);    BtM1[0] = p;    BtM1[1] = p + 128 * 128;
        cudaGetSymbolAddress((void**)&p, g_BtM2);    BtM2[0] = p;    BtM2[1] = p + 128 * 128;
    }

    int ebase[5];
    { int acc = 0; for (int r = 0; r < 5; r++) { ebase[r] = acc; acc += E[r]; } }
    int maxE = 0;
    for (int r = 0; r < 5; r++) maxE = (E[r] > maxE) ? E[r] : maxE;

    // ---- prep (weights + biases + emode + zero counters), then CSR build ----
    prep_k<<<(PREP_TOTAL + 255) / 256, 256>>>(proj_W, proj_b, l0_Wl, l0_bl, l0_Wr,
                                              Wl, bl, Wr, mlp_W1, mlp_W2, bn_g, e[0]);
    counti5_k<<<dim3((maxE + 255) / 256, 5), 256>>>(e[0], e[1], e[2], e[3], e[4],
                                                    E[0], E[1], E[2], E[3], E[4]);
    scan1_k<<<dim3(NBX, 5), 256>>>();
    scan3_k<<<dim3(NBX, 5), 256>>>();
    fill5_k<<<dim3((maxE + 255) / 256, 5), 256>>>(e[0], e[1], e[2], e[3], e[4],
                                                  E[0], E[1], E[2], E[3], E[4],
                                                  ebase[0], ebase[1], ebase[2], ebase[3], ebase[4]);
    const int* rp[5]; const int* cx[5]; const float* ic[5];
    for (int r = 0; r < 5; r++) {
        rp[r] = rowp + r * (NN + 1);
        cx[r] = colx + ebase[r];
        ic[r] = cntf + r * NN;
    }

    const int NBLK_N = (NN + 7) / 8;
    const int NBLK_B = (NB + 7) / 8;

    auto mkjob = [&](Agg5& J, int s, const float* xf, int lds, int soff, int rel,
                     float* agg, int ldd, int doff, int n) {
        J.xf[s] = xf; J.lds[s] = lds; J.soff[s] = soff;
        J.rowp[s] = rp[rel]; J.col[s] = cx[rel]; J.invc[s] = ic[rel];
        J.agg[s] = agg; J.ldd[s] = ldd; J.doff[s] = doff; J.n[s] = n;
    };

    // ==================== layer 0 ====================
    {
        TGJob G;
        setslot(G, 0, x_note, 64, 64, nullptr, 0, 0, BtProjN[0], BtProjN[1], 64,
                pbCatN, pn, 192, 0, NN, 192, 1.f);
        setslot(G, 1, x_beat, 64, 64, nullptr, 0, 0, BtProjB[0], BtProjB[1], 64,
                pbCatB, pb, 128, 0, NB, 128, 1.f);
        tgemmJ(1, G, 2, nullptr, nullptr);
    }
    {
        Agg5 J; J.nslots = 5;
        mkjob(J, 0, pn, 192, 0,   0, aggn, 192, 0,   NN);
        mkjob(J, 1, pn, 192, 64,  1, aggn, 192, 64,  NN);
        mkjob(J, 2, pb, 128, 0,   3, aggn, 192, 128, NN);
        mkjob(J, 3, pn, 192, 128, 2, aggb, 128, 0,   NB);
        mkjob(J, 4, pb, 128, 64,  4, aggb, 128, 64,  NB);
        J.boff[0] = 0; J.boff[1] = NBLK_N; J.boff[2] = 2 * NBLK_N; J.boff[3] = 3 * NBLK_N;
        J.boff[4] = 3 * NBLK_N + NBLK_B; J.boff[5] = 3 * NBLK_N + 2 * NBLK_B;
        aggmulti_k<2><<<J.boff[5], 256>>>(J);
    }
    {
        TGJob G;
        for (int j = 0; j < 3; j++)
            setslot(G, j, x_note, 64, 64, aggn + j * 64, 192, 64,
                    BtL0[0] + j * 16384, BtL0[1] + j * 16384, 128,
                    l0blCatN + j * 128, On, 384, j * 128, NN, 128, 1.f);
        for (int j = 0; j < 2; j++)
            setslot(G, 3 + j, x_beat, 64, 64, aggb + j * 64, 128, 64,
                    BtL0[0] + (3 + j) * 16384, BtL0[1] + (3 + j) * 16384, 128,
                    l0blCatB + j * 128, Ob, 256, j * 128, NB, 128, 1.f);
        tgemmJ(0, G, 5, nullptr, nullptr);
    }
    l0post2_k<<<NBLK_N + NBLK_B, 256>>>(On, Ob, ln_g, ln_b, xn0, xb0, NBLK_N);

    // ==================== layer 1 (GEMM with fused relu+LN epilogue) =========
    {
        Agg5 J; J.nslots = 5;
        mkjob(J, 0, xn0, 128, 0, 0, aggn, 384, 0,   NN);
        mkjob(J, 1, xn0, 128, 0, 1, aggn, 384, 128, NN);
        mkjob(J, 2, xb0, 128, 0, 3, aggn, 384, 256, NN);
        mkjob(J, 3, xn0, 128, 0, 2, aggb, 256, 0,   NB);
        mkjob(J, 4, xb0, 128, 0, 4, aggb, 256, 128, NB);
        J.boff[0] = 0; J.boff[1] = NBLK_N; J.boff[2] = 2 * NBLK_N; J.boff[3] = 3 * NBLK_N;
        J.boff[4] = 3 * NBLK_N + NBLK_B; J.boff[5] = 3 * NBLK_N + 2 * NBLK_B;
        aggmulti_k<4><<<J.boff[5], 256>>>(J);
    }
    {
        TGJob G;
        setslot(G, 0, aggn, 384, 384, xn0, 128, 128, BtL1N[0], BtL1N[1], 512,
                b1SumN, xn1, 128, 0, NN, 128, 1.f, 1.f / 3.f);
        setslot(G, 1, aggb, 256, 256, xb0, 128, 128, BtL1B[0], BtL1B[1], 384,
                b1SumB, xb1, 128, 0, NB, 128, 1.f, 1.f / 2.f);
        tgemmJ(3, G, 2, ln_g + 128, ln_b + 128);
    }

    // ==================== layer 2 (note dst only) ====================
    {
        Agg5 J; J.nslots = 3;
        mkjob(J, 0, xn1, 128, 0, 0, aggn, 384, 0,   NN);
        mkjob(J, 1, xn1, 128, 0, 1, aggn, 384, 128, NN);
        mkjob(J, 2, xb1, 128, 0, 3, aggn, 384, 256, NN);
        J.boff[0] = 0; J.boff[1] = NBLK_N; J.boff[2] = 2 * NBLK_N; J.boff[3] = 3 * NBLK_N;
        J.boff[4] = 3 * NBLK_N; J.boff[5] = 3 * NBLK_N;
        aggmulti_k<4><<<J.boff[3], 256>>>(J);
    }
    {
        TGJob G;
        setslot(G, 0, aggn, 384, 384, xn1, 128, 128, BtL2N[0], BtL2N[1], 512,
                b2SumN, outn, 128, 0, NN, 128, 1.f);
        tgemmJ(0, G, 1, nullptr, nullptr);
    }

    // ==================== final MLP (fused MLP1+BN+MLP2, writes d_out) =======
    {
        TGJob G;
        setslot(G, 0, outn, 128, 128, nullptr, 0, 0, BtM1[0], BtM1[1], 128,
                mlp_b1, On, 128, 0, NN, 128, 1.f / 3.f);
        G.W2h = BtM2[0]; G.W2l = BtM2[1]; G.b2 = mlp_b2; G.Cout = (float*)d_out;
        tgemmJ(4, G, 1, bnS, bn_b);
    }
}

// round 15
// speedup vs baseline: 1.0968x; 1.0358x over previous
#include <cuda_runtime.h>
#include <cuda_bf16.h>
#include <mma.h>
#include <cstdint>

using namespace nvcuda;

#define NN 100000
#define NB 20000
#define INC 64
#define HID 128
#define NBX 49
#define MAXE 3000000

// ================= scratch (device globals; no runtime allocation) ==========
__device__ float g_pn  [(size_t)NN * 192];
__device__ float g_pb  [(size_t)NB * 128];
__device__ float g_aggn[(size_t)NN * 384];
__device__ float g_aggb[(size_t)NB * 256];
__device__ float g_On  [(size_t)NN * 384];
__device__ float g_Ob  [(size_t)NB * 256];
__device__ float g_xn0 [(size_t)NN * HID];
__device__ float g_xn1 [(size_t)NN * HID];
__device__ float g_xb0 [(size_t)NB * HID];
__device__ float g_xb1 [(size_t)NB * HID];
__device__ float g_outn[(size_t)NN * HID];
__device__ float g_cnt [5][NN];
__device__ int   g_cnti[5][NN];
__device__ int   g_rowp[5][NN + 1];
__device__ int   g_bsum[5][64];
__device__ int   g_col [MAXE];
__device__ int   g_emode;

// bias scratch
__device__ float g_pbCatN[192];
__device__ float g_pbCatB[128];
__device__ float g_l0blCatN[384];
__device__ float g_l0blCatB[256];
__device__ float g_b1SumN[128];
__device__ float g_b1SumB[128];
__device__ float g_b2SumN[128];
__device__ float g_bnS[128];
// bf16 transposed+split weights [Npad x K], hi/lo
__device__ __nv_bfloat16 g_BtProjN[2][256 * 64];
__device__ __nv_bfloat16 g_BtProjB[2][128 * 64];
__device__ __nv_bfloat16 g_BtL0  [2][5][128 * 128];
__device__ __nv_bfloat16 g_BtL1N [2][128 * 512];
__device__ __nv_bfloat16 g_BtL1B [2][128 * 384];
__device__ __nv_bfloat16 g_BtL2N [2][128 * 512];
__device__ __nv_bfloat16 g_BtM1  [2][128 * 128];
__device__ __nv_bfloat16 g_BtM2  [2][128 * 128];

__device__ __forceinline__ int edge_at(const int* e, long long i) {
    if (g_emode) return (int)((const long long*)e)[i];
    return e[i];
}
__global__ void counti5_k(const int* e0, const int* e1, const int* e2,
                          const int* e3, const int* e4,
                          int E0, int E1, int E2, int E3, int E4) {
    int r = blockIdx.y;
    const int* e; int E;
    switch (r) {
        case 0: e = e0; E = E0; break;
        case 1: e = e1; E = E1; break;
        case 2: e = e2; E = E2; break;
        case 3: e = e3; E = E3; break;
        default: e = e4; E = E4; break;
    }
    int i = blockIdx.x * 256 + threadIdx.x;
    if (i >= E) return;
    atomicAdd(&g_cnti[r][edge_at(e, (long long)E + i)], 1);
}
__global__ void scan1_k() {
    int r = blockIdx.y;
    int n = (r == 2 || r == 4) ? NB : NN;
    int t = threadIdx.x;
    int base = blockIdx.x * 2048 + t * 8;
    int vals[8];
#pragma unroll
    for (int j = 0; j < 8; j++) {
        int idx = base + j;
        vals[j] = (idx < n) ? g_cnti[r][idx] : 0;
        if (idx < n) g_cnt[r][idx] = 1.0f / (float)max(vals[j], 1);
    }
    int tot = 0;
#pragma unroll
    for (int j = 0; j < 8; j++) tot += vals[j];
    int lane = t & 31, wid = t >> 5;
    int x = tot;
#pragma unroll
    for (int o = 1; o < 32; o <<= 1) {
        int y = __shfl_up_sync(0xffffffffu, x, o);
        if (lane >= o) x += y;
    }
    __shared__ int wsum[8];
    if (lane == 31) wsum[wid] = x;
    __syncthreads();
    if (t == 0) {
        int run = 0;
#pragma unroll
        for (int i = 0; i < 8; i++) { int v = wsum[i]; wsum[i] = run; run += v; }
        g_bsum[r][blockIdx.x] = run;
    }
    __syncthreads();
    int run = (x - tot) + wsum[wid];
#pragma unroll
    for (int j = 0; j < 8; j++) {
        int idx = base + j;
        if (idx < n) g_rowp[r][idx] = run;
        run += vals[j];
    }
}
__global__ void scan3_k() {
    int r = blockIdx.y;
    int n = (r == 2 || r == 4) ? NB : NN;
    int bx = blockIdx.x;
    int t = threadIdx.x;
    __shared__ int sb[64];
    __shared__ int s_add;
    if (t < 64) sb[t] = (t < NBX) ? g_bsum[r][t] : 0;
    __syncthreads();
    if (t == 0) {
        int a = 0;
        for (int i = 0; i < bx; i++) a += sb[i];
        s_add = a;
        if (bx == NBX - 1) g_rowp[r][n] = a + sb[NBX - 1];
    }
    __syncthreads();
    int add = s_add;
    int base = bx * 2048 + t * 8;
#pragma unroll
    for (int j = 0; j < 8; j++) {
        int idx = base + j;
        if (idx < n) {
            int v = g_rowp[r][idx] + add;
            g_rowp[r][idx] = v;
            g_cnti[r][idx] = v;
        }
    }
}
__global__ void fill5_k(const int* e0, const int* e1, const int* e2,
                        const int* e3, const int* e4,
                        int E0, int E1, int E2, int E3, int E4,
                        int b0, int b1, int b2, int b3, int b4) {
    int r = blockIdx.y;
    const int* e; int E; int eb;
    switch (r) {
        case 0: e = e0; E = E0; eb = b0; break;
        case 1: e = e1; E = E1; eb = b1; break;
        case 2: e = e2; E = E2; eb = b2; break;
        case 3: e = e3; E = E3; eb = b3; break;
        default: e = e4; E = E4; eb = b4; break;
    }
    int i = blockIdx.x * 256 + threadIdx.x;
    if (i >= E) return;
    int s = edge_at(e, i);
    int d = edge_at(e, (long long)E + i);
    int pos = atomicAdd(&g_cnti[r][d], 1);
    g_col[eb + pos] = s;
}

// ---- merged CSR seg-mean aggregation (job table, warp per dst row) ---------
struct Agg5 {
    const float* xf[5];
    const int* rowp[5];
    const int* col[5];
    const float* invc[5];
    float* agg[5];
    int lds[5], soff[5], ldd[5], doff[5], n[5];
    int boff[6];
    int nslots;
};

template <int V>
__global__ void aggmulti_k(Agg5 J) {
    int b = blockIdx.x;
    int s = 0;
    while (s + 1 < J.nslots && b >= J.boff[s + 1]) s++;
    int row = (b - J.boff[s]) * 8 + (threadIdx.x >> 5);
    if (row >= J.n[s]) return;
    int lane = threadIdx.x & 31;
    const float* xf = J.xf[s];
    const int* col = J.col[s];
    int lds = J.lds[s], soff = J.soff[s];
    int beg = J.rowp[s][row], end = J.rowp[s][row + 1];
    float acc[V];
#pragma unroll
    for (int j = 0; j < V; j++) acc[j] = 0.0f;
    int e = beg;
    for (; e + 7 < end; e += 8) {
        int si[8];
#pragma unroll
        for (int u = 0; u < 8; u++) si[u] = __ldg(&col[e + u]);
        if (V == 4) {
            float4 vv[8];
#pragma unroll
            for (int u = 0; u < 8; u++)
                vv[u] = *(const float4*)(xf + (size_t)si[u] * lds + soff + lane * V);
#pragma unroll
            for (int u = 0; u < 8; u++) {
                acc[0] += vv[u].x; acc[1] += vv[u].y;
                acc[2] += vv[u].z; acc[3] += vv[u].w;
            }
        } else {
            float2 vv[8];
#pragma unroll
            for (int u = 0; u < 8; u++)
                vv[u] = *(const float2*)(xf + (size_t)si[u] * lds + soff + lane * V);
#pragma unroll
            for (int u = 0; u < 8; u++) {
                acc[0] += vv[u].x; acc[1] += vv[u].y;
            }
        }
    }
    for (; e < end; e++) {
        int s0 = __ldg(&col[e]);
        const float* p0 = xf + (size_t)s0 * lds + soff + lane * V;
        if (V == 4) {
            float4 a = *(const float4*)p0;
            acc[0] += a.x; acc[1] += a.y; acc[2] += a.z; acc[3] += a.w;
        } else {
            float2 a = *(const float2*)p0;
            acc[0] += a.x; acc[1] += a.y;
        }
    }
    float inv = J.invc[s][row];
    float* q = J.agg[s] + (size_t)row * J.ldd[s] + J.doff[s] + lane * V;
    if (V == 4) {
        *(float4*)q = make_float4(acc[0] * inv, acc[1] * inv, acc[2] * inv, acc[3] * inv);
    } else {
        *(float2*)q = make_float2(acc[0] * inv, acc[1] * inv);
    }
}

// ================= cp.async helpers =========================================
__device__ __forceinline__ void cp16(uint32_t dst, const void* src) {
    asm volatile("cp.async.ca.shared.global [%0], [%1], 16;" :: "r"(dst), "l"(src));
}
__device__ __forceinline__ void cp_commit() {
    asm volatile("cp.async.commit_group;");
}
__device__ __forceinline__ void cp_wait0() {
    asm volatile("cp.async.wait_group 0;" ::: "memory");
}

__device__ __forceinline__ void bsplit(float x, __nv_bfloat16& h, __nv_bfloat16& l) {
    h = __float2bfloat16_rn(x);
    l = __float2bfloat16_rn(x - __bfloat162float(h));
}

// ================= wmma bf16 split GEMM (job table, cp.async B) =============
// EPI: 0 plain, 1 relu, 3 relu+LN fused (Nfull==128),
//      4 relu+BN -> h@W2+b2 -> Cout (fused MLP).
struct TGJob {
    const float* A1[5];
    const float* A2[5];
    const __nv_bfloat16* Bhi[5];
    const __nv_bfloat16* Blo[5];
    const float* bias[5];
    float* C[5];
    int lda1[5], K1[5], lda2[5], K2[5], ldK[5], ldc[5], coff[5], M[5], Nfull[5];
    float alpha[5];
    float invr[5];
    // EPI=4 extras (slot 0 only)
    const __nv_bfloat16* W2h;
    const __nv_bfloat16* W2l;
    const float* b2;
    float* Cout;
};
#define TG_DSM 81920
template <int EPI>
__global__ __launch_bounds__(256, 2) void tgemm_k(
    TGJob J, const float* __restrict__ bnS, const float* __restrict__ bnB)
{
    extern __shared__ char dynsmem[];
    __nv_bfloat16* Asm = reinterpret_cast<__nv_bfloat16*>(dynsmem);
    __nv_bfloat16* Bsm = reinterpret_cast<__nv_bfloat16*>(dynsmem + 40960);
    uint32_t Bu32 = (uint32_t)__cvta_generic_to_shared(Bsm);

    int z = blockIdx.z;
    const float* A1 = J.A1[z];
    const float* A2 = J.A2[z];
    const __nv_bfloat16* Bhi = J.Bhi[z];
    const __nv_bfloat16* Blo = J.Blo[z];
    const float* bias = J.bias[z];
    float* C = J.C[z];
    int lda1 = J.lda1[z], K1 = J.K1[z], lda2 = J.lda2[z], K2 = J.K2[z];
    int ldK = J.ldK[z], ldc = J.ldc[z], coff = J.coff[z];
    int M = J.M[z], Nfull = J.Nfull[z];
    float alpha = J.alpha[z];

    int m0 = blockIdx.x * 128;
    int n0 = blockIdx.y * 128;
    if (m0 >= M || n0 >= Nfull) return;

    int tid = threadIdx.x;
    int wid = tid >> 5, lane = tid & 31;
    int wm = wid >> 2, wn = wid & 3;
    int mw = m0 + wm * 64;
    int nw = n0 + wn * 32;
    int nl = wn * 32;
    bool active = (nw < Nfull);
    int K = K1 + K2;
    int nkt = K >> 5;

    wmma::fragment<wmma::accumulator, 16, 16, 16, float> acc[4][2];
#pragma unroll
    for (int i = 0; i < 4; i++)
#pragma unroll
        for (int j = 0; j < 2; j++) wmma::fill_fragment(acc[i][j], 0.0f);

    int row = tid >> 1, half = tid & 1;
    int m = m0 + row;
    bool mok = (m < M);
    int brow = row, bhalf = half;

    // ---- prologue ----
    float4 v[4];
    {
        const float* Ap; int ld, kl;
        if (0 < K1) { Ap = A1; ld = lda1; kl = 0; }
        else        { Ap = A2; ld = lda2; kl = -K1; }
        const float* src = Ap + (size_t)m * ld + kl + half * 16;
#pragma unroll
        for (int i = 0; i < 4; i++)
            v[i] = mok ? *(const float4*)(src + i * 4) : make_float4(0.f, 0.f, 0.f, 0.f);
    }
    {
        const __nv_bfloat16* sH = Bhi + (size_t)(n0 + brow) * ldK + bhalf * 16;
        const __nv_bfloat16* sL = Blo + (size_t)(n0 + brow) * ldK + bhalf * 16;
        uint32_t dH = Bu32 + (uint32_t)(((0 * 2 + 0) * 128 + brow) * 40 + bhalf * 16) * 2;
        uint32_t dL = Bu32 + (uint32_t)(((0 * 2 + 1) * 128 + brow) * 40 + bhalf * 16) * 2;
        cp16(dH, sH); cp16(dH + 16, sH + 8);
        cp16(dL, sL); cp16(dL + 16, sL + 8);
        cp_commit();
    }

    int buf = 0;
    for (int kt = 0; kt < nkt; kt++) {
        {
            __nv_bfloat162* ah = reinterpret_cast<__nv_bfloat162*>(
                Asm + ((buf * 2 + 0) * 128 + row) * 40);
            __nv_bfloat162* al = reinterpret_cast<__nv_bfloat162*>(
                Asm + ((buf * 2 + 1) * 128 + row) * 40);
#pragma unroll
            for (int i = 0; i < 4; i++) {
                int col = half * 16 + i * 4;
                float4 x = v[i];
                __nv_bfloat16 hx = __float2bfloat16_rn(x.x);
                __nv_bfloat16 hy = __float2bfloat16_rn(x.y);
                __nv_bfloat16 hz = __float2bfloat16_rn(x.z);
                __nv_bfloat16 hw = __float2bfloat16_rn(x.w);
                __nv_bfloat162 h01; h01.x = hx; h01.y = hy;
                __nv_bfloat162 h23; h23.x = hz; h23.y = hw;
                ah[(col >> 1) + 0] = h01;
                ah[(col >> 1) + 1] = h23;
                __nv_bfloat162 l01, l23;
                l01.x = __float2bfloat16_rn(x.x - __bfloat162float(hx));
                l01.y = __float2bfloat16_rn(x.y - __bfloat162float(hy));
                l23.x = __float2bfloat16_rn(x.z - __bfloat162float(hz));
                l23.y = __float2bfloat16_rn(x.w - __bfloat162float(hw));
                al[(col >> 1) + 0] = l01;
                al[(col >> 1) + 1] = l23;
            }
        }
        cp_wait0();
        __syncthreads();
        if (kt + 1 < nkt) {
            int k0n = (kt + 1) << 5;
            const __nv_bfloat16* sH = Bhi + (size_t)(n0 + brow) * ldK + k0n + bhalf * 16;
            const __nv_bfloat16* sL = Blo + (size_t)(n0 + brow) * ldK + k0n + bhalf * 16;
            int ob = buf ^ 1;
            uint32_t dH = Bu32 + (uint32_t)(((ob * 2 + 0) * 128 + brow) * 40 + bhalf * 16) * 2;
            uint32_t dL = Bu32 + (uint32_t)(((ob * 2 + 1) * 128 + brow) * 40 + bhalf * 16) * 2;
            cp16(dH, sH); cp16(dH + 16, sH + 8);
            cp16(dL, sL); cp16(dL + 16, sL + 8);
            cp_commit();
            const float* Ap; int ld, kl;
            if (k0n < K1) { Ap = A1; ld = lda1; kl = k0n; }
            else          { Ap = A2; ld = lda2; kl = k0n - K1; }
            const float* src = Ap + (size_t)m * ld + kl + half * 16;
#pragma unroll
            for (int i = 0; i < 4; i++)
                v[i] = mok ? *(const float4*)(src + i * 4) : make_float4(0.f, 0.f, 0.f, 0.f);
        }
        if (active) {
            const __nv_bfloat16* BsH = Bsm + (buf * 2 + 0) * 128 * 40;
            const __nv_bfloat16* BsL = Bsm + (buf * 2 + 1) * 128 * 40;
#pragma unroll
            for (int kk = 0; kk < 32; kk += 16) {
                wmma::fragment<wmma::matrix_b, 16, 16, 16, __nv_bfloat16, wmma::col_major> bh[2], bl2[2];
#pragma unroll
                for (int j = 0; j < 2; j++) {
                    wmma::load_matrix_sync(bh[j],  BsH + (nl + j * 16) * 40 + kk, 40u);
                    wmma::load_matrix_sync(bl2[j], BsL + (nl + j * 16) * 40 + kk, 40u);
                }
#pragma unroll
                for (int i = 0; i < 4; i++) {
                    wmma::fragment<wmma::matrix_a, 16, 16, 16, __nv_bfloat16, wmma::row_major> ah, al;
                    wmma::load_matrix_sync(ah, Asm + ((buf * 2 + 0) * 128 + wm * 64 + i * 16) * 40 + kk, 40u);
                    wmma::load_matrix_sync(al, Asm + ((buf * 2 + 1) * 128 + wm * 64 + i * 16) * 40 + kk, 40u);
#pragma unroll
                    for (int j = 0; j < 2; j++) {
                        wmma::mma_sync(acc[i][j], ah, bh[j],  acc[i][j]);
                        wmma::mma_sync(acc[i][j], ah, bl2[j], acc[i][j]);
                        wmma::mma_sync(acc[i][j], al, bh[j],  acc[i][j]);
                    }
                }
            }
        }
        buf ^= 1;
    }
    __syncthreads();

    if (EPI == 3) {
        // ---- fused relu -> LayerNorm epilogue (Nfull == 128) ----
        float* obuf = reinterpret_cast<float*>(dynsmem);   // 128 x 132 f32
#pragma unroll
        for (int i = 0; i < 4; i++)
#pragma unroll
            for (int j = 0; j < 2; j++)
                wmma::store_matrix_sync(obuf + (wm * 64 + i * 16) * 132 + nl + j * 16,
                                        acc[i][j], 132u, wmma::mem_row_major);
        __syncthreads();
        float invr = J.invr[z];
        int r0 = wid * 16;
        for (int rr = 0; rr < 16; rr++) {
            int rloc = r0 + rr;
            int mm = m0 + rloc;
            if (mm >= M) continue;
            float vv[4]; float s = 0.f;
#pragma unroll
            for (int j = 0; j < 4; j++) {
                int c = lane + 32 * j;
                float val = obuf[rloc * 132 + c] * alpha + bias[c];
                vv[j] = fmaxf(val * invr, 0.f);
                s += vv[j];
            }
#pragma unroll
            for (int o = 16; o; o >>= 1) s += __shfl_xor_sync(0xffffffffu, s, o);
            float mean = s * (1.0f / 128.0f);
            float ss = 0.f;
#pragma unroll
            for (int j = 0; j < 4; j++) { float d = vv[j] - mean; ss += d * d; }
#pragma unroll
            for (int o = 16; o; o >>= 1) ss += __shfl_xor_sync(0xffffffffu, ss, o);
            float inv = rsqrtf(ss * (1.0f / 128.0f) + 1e-5f);
            float* q = C + (size_t)mm * ldc;
#pragma unroll
            for (int j = 0; j < 4; j++) {
                int c = lane + 32 * j;
                q[c] = (vv[j] - mean) * inv * bnS[c] + bnB[c];
            }
        }
    } else if (EPI == 4) {
        // ---- relu+BN -> h (bf16 hi/lo, stride 136) -> h@W2+b2 -> Cout ----
        __nv_bfloat16* hHb = reinterpret_cast<__nv_bfloat16*>(dynsmem);
        __nv_bfloat16* hLb = hHb + 128 * 136;
        float* myp = reinterpret_cast<float*>(dynsmem + 69632) + wid * 320;
        int base = lane * 8;
        int pr = base >> 4, pc = base & 15;
#pragma unroll
        for (int i = 0; i < 4; i++) {
#pragma unroll
            for (int j = 0; j < 2; j++) {
                wmma::store_matrix_sync(myp, acc[i][j], 20u, wmma::mem_row_major);
                __syncwarp();
                int rloc = wm * 64 + i * 16 + pr;
                int nb = nl + j * 16;
                bool rok = (m0 + rloc < M);
#pragma unroll
                for (int t = 0; t < 8; t++) {
                    int n = nb + pc + t;
                    float val = rok ? (myp[pr * 20 + pc + t] * alpha + bias[n]) : 0.f;
                    val = fmaxf(val, 0.f) * bnS[n] + bnB[n];
                    __nv_bfloat16 hh, ll;
                    bsplit(val, hh, ll);
                    hHb[rloc * 136 + n] = hh;
                    hLb[rloc * 136 + n] = ll;
                }
                __syncwarp();
            }
        }
        __syncthreads();
        wmma::fragment<wmma::accumulator, 16, 16, 16, float> acc2[2];
#pragma unroll
        for (int j = 0; j < 2; j++) wmma::fill_fragment(acc2[j], 0.0f);
        const __nv_bfloat16* W2h = J.W2h;
        const __nv_bfloat16* W2l = J.W2l;
        int r0 = wid * 16;
#pragma unroll
        for (int kf = 0; kf < 8; kf++) {
            wmma::fragment<wmma::matrix_a, 16, 16, 16, __nv_bfloat16, wmma::row_major> ah, al;
            wmma::load_matrix_sync(ah, hHb + r0 * 136 + kf * 16, 136u);
            wmma::load_matrix_sync(al, hLb + r0 * 136 + kf * 16, 136u);
#pragma unroll
            for (int j = 0; j < 2; j++) {
                wmma::fragment<wmma::matrix_b, 16, 16, 16, __nv_bfloat16, wmma::col_major> bh, bl2;
                wmma::load_matrix_sync(bh,  W2h + (size_t)(j * 16) * 128 + kf * 16, 128u);
                wmma::load_matrix_sync(bl2, W2l + (size_t)(j * 16) * 128 + kf * 16, 128u);
                wmma::mma_sync(acc2[j], ah, bh,  acc2[j]);
                wmma::mma_sync(acc2[j], ah, bl2, acc2[j]);
                wmma::mma_sync(acc2[j], al, bh,  acc2[j]);
            }
        }
        const float* b2 = J.b2;
        float* Cout = J.Cout;
#pragma unroll
        for (int j = 0; j < 2; j++) {
            wmma::store_matrix_sync(myp, acc2[j], 20u, wmma::mem_row_major);
            __syncwarp();
            int mm = m0 + r0 + pr;
            if (mm < M) {
                float out[8];
#pragma unroll
                for (int t = 0; t < 8; t++) {
                    int n = j * 16 + pc + t;
                    out[t] = myp[pr * 20 + pc + t] + b2[n];
                }
                float* dst = Cout + (size_t)mm * 32 + j * 16 + pc;
                *(float4*)dst = *(float4*)&out[0];
                *(float4*)(dst + 4) = *(float4*)&out[4];
            }
            __syncwarp();
        }
    } else if (active) {
        float* myp = reinterpret_cast<float*>(dynsmem) + wid * 320;
        int base = lane * 8;
        int pr = base >> 4, pc = base & 15;
#pragma unroll
        for (int i = 0; i < 4; i++) {
#pragma unroll
            for (int j = 0; j < 2; j++) {
                wmma::store_matrix_sync(myp, acc[i][j], 20u, wmma::mem_row_major);
                __syncwarp();
                int mb = mw + i * 16, nb = nw + j * 16;
                if (mb + pr < M) {
                    float out[8];
#pragma unroll
                    for (int t = 0; t < 8; t++) {
                        int n = nb + pc + t;
                        float val = myp[pr * 20 + pc + t] * alpha + bias[n];
                        if (EPI >= 1) val = fmaxf(val, 0.0f);
                        out[t] = val;
                    }
                    float* dst = C + (size_t)(mb + pr) * ldc + coff + nb + pc;
                    *(float4*)dst = *(float4*)&out[0];
                    *(float4*)(dst + 4) = *(float4*)&out[4];
                }
                __syncwarp();
            }
        }
    }
}

// ================= merged elementwise: layer-0 post ==========================
__global__ void l0post2_k(const float* __restrict__ On, const float* __restrict__ Ob,
                          const float* __restrict__ gg, const float* __restrict__ bb,
                          float* __restrict__ xn, float* __restrict__ xb, int nblkN) {
    int b = blockIdx.x;
    const float* O; float* xout; int ldo, M, R;
    if (b < nblkN) { O = On; xout = xn; ldo = 384; M = NN; R = 3; }
    else           { O = Ob; xout = xb; ldo = 256; M = NB; R = 2; b -= nblkN; }
    int row = b * 8 + (threadIdx.x >> 5);
    if (row >= M) return;
    int lane = threadIdx.x & 31;
    float acc[4] = {0.f, 0.f, 0.f, 0.f};
    for (int rb = 0; rb < R; rb++) {
        const float* p = O + (size_t)row * ldo + rb * 128;
        float v[4]; float ss = 0.f;
#pragma unroll
        for (int j = 0; j < 4; j++) { v[j] = p[lane + 32 * j]; ss += v[j] * v[j]; }
#pragma unroll
        for (int s = 16; s; s >>= 1) ss += __shfl_xor_sync(0xffffffffu, ss, s);
        float inv = 1.0f / fmaxf(sqrtf(ss), 1e-12f);
#pragma unroll
        for (int j = 0; j < 4; j++) acc[j] += v[j] * inv;
    }
    const float invR = 1.0f / R;
    float s = 0.f;
#pragma unroll
    for (int j = 0; j < 4; j++) { acc[j] = fmaxf(acc[j] * invR, 0.f); s += acc[j]; }
#pragma unroll
    for (int o = 16; o; o >>= 1) s += __shfl_xor_sync(0xffffffffu, s, o);
    float m = s * (1.0f / 128.0f);
    float ss = 0.f;
#pragma unroll
    for (int j = 0; j < 4; j++) { float d = acc[j] - m; ss += d * d; }
#pragma unroll
    for (int o = 16; o; o >>= 1) ss += __shfl_xor_sync(0xffffffffu, ss, o);
    float inv = rsqrtf(ss * (1.0f / 128.0f) + 1e-5f);
    float* q = xout + (size_t)row * 128;
#pragma unroll
    for (int j = 0; j < 4; j++) {
        int c = lane + 32 * j;
        q[c] = (acc[j] - m) * inv * gg[c] + bb[c];
    }
}

// ================= fused weight-prep + init kernel ===========================
__device__ __forceinline__ void lsplit_body(__nv_bfloat16* hi, __nv_bfloat16* lo,
                                            const float* WlL, const float* WrL,
                                            int r0, int r1, int r2, int nrel, int idx) {
    int K = nrel * 128 + 128;
    int n = idx / K, k = idx - n * K;
    float x;
    if (k < nrel * 128) {
        int j = k >> 7, kk = k & 127;
        int r = (j == 0) ? r0 : (j == 1) ? r1 : r2;
        x = WlL[(size_t)r * 16384 + kk * 128 + n];
    } else {
        int kk = k - nrel * 128;
        x = WrL[(size_t)r0 * 16384 + kk * 128 + n] + WrL[(size_t)r1 * 16384 + kk * 128 + n];
        if (nrel == 3) x += WrL[(size_t)r2 * 16384 + kk * 128 + n];
    }
    __nv_bfloat16 h, l;
    bsplit(x, h, l);
    hi[idx] = h;
    lo[idx] = l;
}
#define PREP_TOTAL (305152 + 5 * NN)
__global__ void prep_k(const float* __restrict__ proj_W, const float* __restrict__ proj_b,
                       const float* __restrict__ l0_Wl, const float* __restrict__ l0_bl,
                       const float* __restrict__ l0_Wr,
                       const float* __restrict__ Wl, const float* __restrict__ bl,
                       const float* __restrict__ Wr,
                       const float* __restrict__ mlp_W1, const float* __restrict__ mlp_W2,
                       const float* __restrict__ bn_g, const int* __restrict__ e0) {
    int idx = blockIdx.x * 256 + threadIdx.x;
    __nv_bfloat16 h, l;
    if (idx < 12288) {
        int j = idx >> 12, rem = idx & 4095;
        int k = rem >> 6, c = rem & 63;
        float x = proj_W[(size_t)j * 4096 + k * 64 + c];
        int n = j * 64 + c;
        bsplit(x, h, l);
        g_BtProjN[0][n * 64 + k] = h; g_BtProjN[1][n * 64 + k] = l;
        return;
    }
    idx -= 12288;
    if (idx < 8192) {
        int j = idx >> 12, rem = idx & 4095;
        int k = rem >> 6, c = rem & 63;
        int r = (j == 0) ? 3 : 4;
        float x = proj_W[(size_t)r * 4096 + k * 64 + c];
        int n = j * 64 + c;
        bsplit(x, h, l);
        g_BtProjB[0][n * 64 + k] = h; g_BtProjB[1][n * 64 + k] = l;
        return;
    }
    idx -= 8192;
    if (idx < 81920) {
        int s = idx >> 14, rem = idx & 16383;
        int n = rem >> 7, k = rem & 127;
        const int rels[5] = {0, 1, 3, 2, 4};
        int r = rels[s];
        float x = (k < 64) ? l0_Wr[(size_t)r * 8192 + k * 128 + n]
                           : l0_Wl[(size_t)r * 8192 + (k - 64) * 128 + n];
        bsplit(x, h, l);
        g_BtL0[0][s][rem] = h; g_BtL0[1][s][rem] = l;
        return;
    }
    idx -= 81920;
    if (idx < 65536) { lsplit_body(g_BtL1N[0], g_BtL1N[1], Wl, Wr, 0, 1, 3, 3, idx); return; }
    idx -= 65536;
    if (idx < 49152) { lsplit_body(g_BtL1B[0], g_BtL1B[1], Wl, Wr, 2, 4, 0, 2, idx); return; }
    idx -= 49152;
    if (idx < 65536) { lsplit_body(g_BtL2N[0], g_BtL2N[1], Wl + 5 * 16384, Wr + 5 * 16384, 0, 1, 3, 3, idx); return; }
    idx -= 65536;
    if (idx < 16384) {
        int k = idx >> 7, n = idx & 127;
        bsplit(mlp_W1[idx], h, l);
        g_BtM1[0][n * 128 + k] = h; g_BtM1[1][n * 128 + k] = l;
        return;
    }
    idx -= 16384;
    if (idx < 4096) {
        int k = idx / 32, n = idx - (idx / 32) * 32;
        bsplit(mlp_W2[idx], h, l);
        g_BtM2[0][n * 128 + k] = h; g_BtM2[1][n * 128 + k] = l;
        return;
    }
    idx -= 4096;
    if (idx < 2048) {
        int t = idx;
        if (t < 192) {
            int j = t / 64;
            g_pbCatN[t] = proj_b[(size_t)j * 64 + (t - j * 64)];
        } else if (t < 320) {
            int local = t - 192; int j = local / 64;
            int r = (j == 0) ? 3 : 4;
            g_pbCatB[local] = proj_b[(size_t)r * 64 + (local - j * 64)];
        } else if (t < 704) {
            int local = t - 320; int j = local / 128;
            int r = (j == 0) ? 0 : (j == 1) ? 1 : 3;
            g_l0blCatN[local] = l0_bl[(size_t)r * 128 + (local - j * 128)];
        } else if (t < 960) {
            int local = t - 704; int j = local / 128;
            int r = (j == 0) ? 2 : 4;
            g_l0blCatB[local] = l0_bl[(size_t)r * 128 + (local - j * 128)];
        } else if (t < 1088) {
            int i = t - 960;
            g_b1SumN[i] = bl[i] + bl[128 + i] + bl[3 * 128 + i];
        } else if (t < 1216) {
            int i = t - 1088;
            g_b1SumB[i] = bl[2 * 128 + i] + bl[4 * 128 + i];
        } else if (t < 1344) {
            int i = t - 1216;
            g_b2SumN[i] = bl[(5 + 0) * 128 + i] + bl[(5 + 1) * 128 + i] + bl[(5 + 3) * 128 + i];
        } else if (t < 1472) {
            int i = t - 1344;
            g_bnS[i] = bn_g[i] * rsqrtf(1.0f + 1e-5f);
        } else if (t == 1472) {
            int z = 1;
            for (int i = 1; i < 64; i += 2)
                if (e0[i] != 0) z = 0;
            g_emode = z;
        }
        return;
    }
    idx -= 2048;
    if (idx < 5 * NN) ((int*)g_cnti)[idx] = 0;
}

// ================= host dispatch =============================================
static void tgemmJ(int epi, const TGJob& J, int nslots, const float* p0, const float* p1) {
    int maxM = 0, maxN = 0;
    for (int s = 0; s < nslots; s++) {
        if (J.M[s] > maxM) maxM = J.M[s];
        if (J.Nfull[s] > maxN) maxN = J.Nfull[s];
    }
    dim3 g((maxM + 127) / 128, (maxN + 127) / 128, nslots);
    if (epi == 0) {
        cudaFuncSetAttribute(tgemm_k<0>, cudaFuncAttributeMaxDynamicSharedMemorySize, TG_DSM);
        tgemm_k<0><<<g, 256, TG_DSM>>>(J, p0, p1);
    } else if (epi == 1) {
        cudaFuncSetAttribute(tgemm_k<1>, cudaFuncAttributeMaxDynamicSharedMemorySize, TG_DSM);
        tgemm_k<1><<<g, 256, TG_DSM>>>(J, p0, p1);
    } else if (epi == 3) {
        cudaFuncSetAttribute(tgemm_k<3>, cudaFuncAttributeMaxDynamicSharedMemorySize, TG_DSM);
        tgemm_k<3><<<g, 256, TG_DSM>>>(J, p0, p1);
    } else {
        cudaFuncSetAttribute(tgemm_k<4>, cudaFuncAttributeMaxDynamicSharedMemorySize, TG_DSM);
        tgemm_k<4><<<g, 256, TG_DSM>>>(J, p0, p1);
    }
}
static void setslot(TGJob& J, int s, const float* A1, int lda1, int K1,
                    const float* A2, int lda2, int K2,
                    const __nv_bfloat16* Bh, const __nv_bfloat16* Bl, int ldK,
                    const float* bias, float* C, int ldc, int coff,
                    int M, int Nfull, float alpha, float invr = 1.0f) {
    J.A1[s] = A1; J.lda1[s] = lda1; J.K1[s] = K1;
    J.A2[s] = A2; J.lda2[s] = lda2; J.K2[s] = K2;
    J.Bhi[s] = Bh; J.Blo[s] = Bl; J.ldK[s] = ldK;
    J.bias[s] = bias; J.C[s] = C; J.ldc[s] = ldc; J.coff[s] = coff;
    J.M[s] = M; J.Nfull[s] = Nfull; J.alpha[s] = alpha; J.invr[s] = invr;
}

extern "C" void kernel_launch(void* const* d_in, const int* in_sizes, int n_in,
                              void* d_out, int out_size) {
    const float* x_note = (const float*)d_in[0];
    const float* x_beat = (const float*)d_in[1];
    const int* e[5] = {(const int*)d_in[2], (const int*)d_in[3], (const int*)d_in[4],
                       (const int*)d_in[5], (const int*)d_in[6]};
    int E[5];
    for (int r = 0; r < 5; r++) E[r] = in_sizes[2 + r] / 2;
    const float* proj_W = (const float*)d_in[7];
    const float* proj_b = (const float*)d_in[8];
    const float* l0_Wl  = (const float*)d_in[9];
    const float* l0_bl  = (const float*)d_in[10];
    const float* l0_Wr  = (const float*)d_in[11];
    const float* Wl     = (const float*)d_in[12];
    const float* bl     = (const float*)d_in[13];
    const float* Wr     = (const float*)d_in[14];
    const float* ln_g   = (const float*)d_in[15];
    const float* ln_b   = (const float*)d_in[16];
    const float* mlp_W1 = (const float*)d_in[17];
    const float* mlp_b1 = (const float*)d_in[18];
    const float* bn_g   = (const float*)d_in[19];
    const float* bn_b   = (const float*)d_in[20];
    const float* mlp_W2 = (const float*)d_in[21];
    const float* mlp_b2 = (const float*)d_in[22];

    float *pn, *pb, *aggn, *aggb, *On, *Ob, *xn0, *xn1, *xb0, *xb1, *outn, *cntf;
    int *rowp, *colx;
    cudaGetSymbolAddress((void**)&pn, g_pn);       cudaGetSymbolAddress((void**)&pb, g_pb);
    cudaGetSymbolAddress((void**)&aggn, g_aggn);   cudaGetSymbolAddress((void**)&aggb, g_aggb);
    cudaGetSymbolAddress((void**)&On, g_On);       cudaGetSymbolAddress((void**)&Ob, g_Ob);
    cudaGetSymbolAddress((void**)&xn0, g_xn0);     cudaGetSymbolAddress((void**)&xn1, g_xn1);
    cudaGetSymbolAddress((void**)&xb0, g_xb0);     cudaGetSymbolAddress((void**)&xb1, g_xb1);
    cudaGetSymbolAddress((void**)&outn, g_outn);
    cudaGetSymbolAddress((void**)&cntf, g_cnt);
    cudaGetSymbolAddress((void**)&rowp, g_rowp);   cudaGetSymbolAddress((void**)&colx, g_col);

    float *pbCatN, *pbCatB, *l0blCatN, *l0blCatB, *b1SumN, *b1SumB, *b2SumN, *bnS;
    cudaGetSymbolAddress((void**)&pbCatN, g_pbCatN);     cudaGetSymbolAddress((void**)&pbCatB, g_pbCatB);
    cudaGetSymbolAddress((void**)&l0blCatN, g_l0blCatN); cudaGetSymbolAddress((void**)&l0blCatB, g_l0blCatB);
    cudaGetSymbolAddress((void**)&b1SumN, g_b1SumN);     cudaGetSymbolAddress((void**)&b1SumB, g_b1SumB);
    cudaGetSymbolAddress((void**)&b2SumN, g_b2SumN);     cudaGetSymbolAddress((void**)&bnS, g_bnS);

    __nv_bfloat16 *BtProjN[2], *BtProjB[2], *BtL0[2], *BtL1N[2], *BtL1B[2], *BtL2N[2], *BtM1[2], *BtM2[2];
    {
        __nv_bfloat16* p;
        cudaGetSymbolAddress((void**)&p, g_BtProjN); BtProjN[0] = p; BtProjN[1] = p + 256 * 64;
        cudaGetSymbolAddress((void**)&p, g_BtProjB); BtProjB[0] = p; BtProjB[1] = p + 128 * 64;
        cudaGetSymbolAddress((void**)&p, g_BtL0);    BtL0[0] = p;    BtL0[1] = p + 5 * 128 * 128;
        cudaGetSymbolAddress((void**)&p, g_BtL1N);   BtL1N[0] = p;   BtL1N[1] = p + 128 * 512;
        cudaGetSymbolAddress((void**)&p, g_BtL1B);   BtL1B[0] = p;   BtL1B[1] = p + 128 * 384;
        cudaGetSymbolAddress((void**)&p, g_BtL2N);   BtL2N[0] = p;   BtL2N[1] = p + 128 * 512;
        cudaGetSymbolAddress((void**)&p, g_BtM1);    BtM1[0] = p;    BtM1[1] = p + 128 * 128;
        cudaGetSymbolAddress((void**)&p, g_BtM2);    BtM2[0] = p;    BtM2[1] = p + 128 * 128;
    }

    int ebase[5];
    { int acc = 0; for (int r = 0; r < 5; r++) { ebase[r] = acc; acc += E[r]; } }
    int maxE = 0;
    for (int r = 0; r < 5; r++) maxE = (E[r] > maxE) ? E[r] : maxE;

    // ---- prep (weights + biases + emode + zero counters), then CSR build ----
    prep_k<<<(PREP_TOTAL + 255) / 256, 256>>>(proj_W, proj_b, l0_Wl, l0_bl, l0_Wr,
                                              Wl, bl, Wr, mlp_W1, mlp_W2, bn_g, e[0]);
    counti5_k<<<dim3((maxE + 255) / 256, 5), 256>>>(e[0], e[1], e[2], e[3], e[4],
                                                    E[0], E[1], E[2], E[3], E[4]);
    scan1_k<<<dim3(NBX, 5), 256>>>();
    scan3_k<<<dim3(NBX, 5), 256>>>();
    fill5_k<<<dim3((maxE + 255) / 256, 5), 256>>>(e[0], e[1], e[2], e[3], e[4],
                                                  E[0], E[1], E[2], E[3], E[4],
                                                  ebase[0], ebase[1], ebase[2], ebase[3], ebase[4]);
    const int* rp[5]; const int* cx[5]; const float* ic[5];
    for (int r = 0; r < 5; r++) {
        rp[r] = rowp + r * (NN + 1);
        cx[r] = colx + ebase[r];
        ic[r] = cntf + r * NN;
    }

    const int NBLK_N = (NN + 7) / 8;
    const int NBLK_B = (NB + 7) / 8;

    auto mkjob = [&](Agg5& J, int s, const float* xf, int lds, int soff, int rel,
                     float* agg, int ldd, int doff, int n) {
        J.xf[s] = xf; J.lds[s] = lds; J.soff[s] = soff;
        J.rowp[s] = rp[rel]; J.col[s] = cx[rel]; J.invc[s] = ic[rel];
        J.agg[s] = agg; J.ldd[s] = ldd; J.doff[s] = doff; J.n[s] = n;
    };

    // ==================== layer 0 ====================
    {
        TGJob G;
        setslot(G, 0, x_note, 64, 64, nullptr, 0, 0, BtProjN[0], BtProjN[1], 64,
                pbCatN, pn, 192, 0, NN, 192, 1.f);
        setslot(G, 1, x_beat, 64, 64, nullptr, 0, 0, BtProjB[0], BtProjB[1], 64,
                pbCatB, pb, 128, 0, NB, 128, 1.f);
        tgemmJ(1, G, 2, nullptr, nullptr);
    }
    {
        Agg5 J; J.nslots = 5;
        mkjob(J, 0, pn, 192, 0,   0, aggn, 192, 0,   NN);
        mkjob(J, 1, pn, 192, 64,  1, aggn, 192, 64,  NN);
        mkjob(J, 2, pb, 128, 0,   3, aggn, 192, 128, NN);
        mkjob(J, 3, pn, 192, 128, 2, aggb, 128, 0,   NB);
        mkjob(J, 4, pb, 128, 64,  4, aggb, 128, 64,  NB);
        J.boff[0] = 0; J.boff[1] = NBLK_N; J.boff[2] = 2 * NBLK_N; J.boff[3] = 3 * NBLK_N;
        J.boff[4] = 3 * NBLK_N + NBLK_B; J.boff[5] = 3 * NBLK_N + 2 * NBLK_B;
        aggmulti_k<2><<<J.boff[5], 256>>>(J);
    }
    {
        TGJob G;
        for (int j = 0; j < 3; j++)
            setslot(G, j, x_note, 64, 64, aggn + j * 64, 192, 64,
                    BtL0[0] + j * 16384, BtL0[1] + j * 16384, 128,
                    l0blCatN + j * 128, On, 384, j * 128, NN, 128, 1.f);
        for (int j = 0; j < 2; j++)
            setslot(G, 3 + j, x_beat, 64, 64, aggb + j * 64, 128, 64,
                    BtL0[0] + (3 + j) * 16384, BtL0[1] + (3 + j) * 16384, 128,
                    l0blCatB + j * 128, Ob, 256, j * 128, NB, 128, 1.f);
        tgemmJ(0, G, 5, nullptr, nullptr);
    }
    l0post2_k<<<NBLK_N + NBLK_B, 256>>>(On, Ob, ln_g, ln_b, xn0, xb0, NBLK_N);

    // ==================== layer 1 (GEMM with fused relu+LN epilogue) =========
    {
        Agg5 J; J.nslots = 5;
        mkjob(J, 0, xn0, 128, 0, 0, aggn, 384, 0,   NN);
        mkjob(J, 1, xn0, 128, 0, 1, aggn, 384, 128, NN);
        mkjob(J, 2, xb0, 128, 0, 3, aggn, 384, 256, NN);
        mkjob(J, 3, xn0, 128, 0, 2, aggb, 256, 0,   NB);
        mkjob(J, 4, xb0, 128, 0, 4, aggb, 256, 128, NB);
        J.boff[0] = 0; J.boff[1] = NBLK_N; J.boff[2] = 2 * NBLK_N; J.boff[3] = 3 * NBLK_N;
        J.boff[4] = 3 * NBLK_N + NBLK_B; J.boff[5] = 3 * NBLK_N + 2 * NBLK_B;
        aggmulti_k<4><<<J.boff[5], 256>>>(J);
    }
    {
        TGJob G;
        setslot(G, 0, aggn, 384, 384, xn0, 128, 128, BtL1N[0], BtL1N[1], 512,
                b1SumN, xn1, 128, 0, NN, 128, 1.f, 1.f / 3.f);
        setslot(G, 1, aggb, 256, 256, xb0, 128, 128, BtL1B[0], BtL1B[1], 384,
                b1SumB, xb1, 128, 0, NB, 128, 1.f, 1.f / 2.f);
        tgemmJ(3, G, 2, ln_g + 128, ln_b + 128);
    }

    // ==================== layer 2 (note dst only) ====================
    {
        Agg5 J; J.nslots = 3;
        mkjob(J, 0, xn1, 128, 0, 0, aggn, 384, 0,   NN);
        mkjob(J, 1, xn1, 128, 0, 1, aggn, 384, 128, NN);
        mkjob(J, 2, xb1, 128, 0, 3, aggn, 384, 256, NN);
        J.boff[0] = 0; J.boff[1] = NBLK_N; J.boff[2] = 2 * NBLK_N; J.boff[3] = 3 * NBLK_N;
        J.boff[4] = 3 * NBLK_N; J.boff[5] = 3 * NBLK_N;
        aggmulti_k<4><<<J.boff[3], 256>>>(J);
    }
    {
        TGJob G;
        setslot(G, 0, aggn, 384, 384, xn1, 128, 128, BtL2N[0], BtL2N[1], 512,
                b2SumN, outn, 128, 0, NN, 128, 1.f);
        tgemmJ(0, G, 1, nullptr, nullptr);
    }

    // ==================== final MLP (fused MLP1+BN+MLP2, writes d_out) =======
    {
        TGJob G;
        setslot(G, 0, outn, 128, 128, nullptr, 0, 0, BtM1[0], BtM1[1], 128,
                mlp_b1, On, 128, 0, NN, 128, 1.f / 3.f);
        G.W2h = BtM2[0]; G.W2l = BtM2[1]; G.b2 = mlp_b2; G.Cout = (float*)d_out;
        tgemmJ(4, G, 1, bnS, bn_b);
    }
}

// round 16
// speedup vs baseline: 1.1067x; 1.0090x over previous
#include <cuda_runtime.h>
#include <cuda_bf16.h>
#include <mma.h>
#include <cstdint>

using namespace nvcuda;

#define NN 100000
#define NB 20000
#define INC 64
#define HID 128
#define NBX 49
#define MAXE 3000000

// ================= scratch (device globals; no runtime allocation) ==========
__device__ float g_pn  [(size_t)NN * 192];
__device__ float g_pb  [(size_t)NB * 128];
__device__ float g_aggn[(size_t)NN * 384];
__device__ float g_aggb[(size_t)NB * 256];
__device__ float g_On  [(size_t)NN * 384];
__device__ float g_Ob  [(size_t)NB * 256];
__device__ float g_xn0 [(size_t)NN * HID];
__device__ float g_xn1 [(size_t)NN * HID];
__device__ float g_xb0 [(size_t)NB * HID];
__device__ float g_xb1 [(size_t)NB * HID];
__device__ float g_outn[(size_t)NN * HID];
__device__ float g_cnt [5][NN];
__device__ int   g_cnti[5][NN];
__device__ int   g_rowp[5][NN + 1];
__device__ int   g_bsum[5][64];
__device__ int   g_col [MAXE];
__device__ int   g_emode;

// bias scratch
__device__ float g_pbCatN[192];
__device__ float g_pbCatB[128];
__device__ float g_l0blCatN[384];
__device__ float g_l0blCatB[256];
__device__ float g_b1SumN[128];
__device__ float g_b1SumB[128];
__device__ float g_b2SumN[128];
__device__ float g_bnS[128];
// bf16 transposed+split weights [Npad x K], hi/lo
__device__ __nv_bfloat16 g_BtProjN[2][256 * 64];
__device__ __nv_bfloat16 g_BtProjB[2][128 * 64];
__device__ __nv_bfloat16 g_BtL0  [2][5][128 * 128];
__device__ __nv_bfloat16 g_BtL1N [2][128 * 512];
__device__ __nv_bfloat16 g_BtL1B [2][128 * 384];
__device__ __nv_bfloat16 g_BtL2N [2][128 * 512];
__device__ __nv_bfloat16 g_BtM1  [2][128 * 128];
__device__ __nv_bfloat16 g_BtM2  [2][128 * 128];

__device__ __forceinline__ int edge_at(const int* e, long long i) {
    if (g_emode) return (int)((const long long*)e)[i];
    return e[i];
}
__global__ void counti5_k(const int* e0, const int* e1, const int* e2,
                          const int* e3, const int* e4,
                          int E0, int E1, int E2, int E3, int E4) {
    int r = blockIdx.y;
    const int* e; int E;
    switch (r) {
        case 0: e = e0; E = E0; break;
        case 1: e = e1; E = E1; break;
        case 2: e = e2; E = E2; break;
        case 3: e = e3; E = E3; break;
        default: e = e4; E = E4; break;
    }
    int i = blockIdx.x * 256 + threadIdx.x;
    if (i >= E) return;
    atomicAdd(&g_cnti[r][edge_at(e, (long long)E + i)], 1);
}
__global__ void scan1_k() {
    int r = blockIdx.y;
    int n = (r == 2 || r == 4) ? NB : NN;
    int t = threadIdx.x;
    int base = blockIdx.x * 2048 + t * 8;
    int vals[8];
#pragma unroll
    for (int j = 0; j < 8; j++) {
        int idx = base + j;
        vals[j] = (idx < n) ? g_cnti[r][idx] : 0;
        if (idx < n) g_cnt[r][idx] = 1.0f / (float)max(vals[j], 1);
    }
    int tot = 0;
#pragma unroll
    for (int j = 0; j < 8; j++) tot += vals[j];
    int lane = t & 31, wid = t >> 5;
    int x = tot;
#pragma unroll
    for (int o = 1; o < 32; o <<= 1) {
        int y = __shfl_up_sync(0xffffffffu, x, o);
        if (lane >= o) x += y;
    }
    __shared__ int wsum[8];
    if (lane == 31) wsum[wid] = x;
    __syncthreads();
    if (t == 0) {
        int run = 0;
#pragma unroll
        for (int i = 0; i < 8; i++) { int v = wsum[i]; wsum[i] = run; run += v; }
        g_bsum[r][blockIdx.x] = run;
    }
    __syncthreads();
    int run = (x - tot) + wsum[wid];
#pragma unroll
    for (int j = 0; j < 8; j++) {
        int idx = base + j;
        if (idx < n) g_rowp[r][idx] = run;
        run += vals[j];
    }
}
__global__ void scan3_k() {
    int r = blockIdx.y;
    int n = (r == 2 || r == 4) ? NB : NN;
    int bx = blockIdx.x;
    int t = threadIdx.x;
    __shared__ int sb[64];
    __shared__ int s_add;
    if (t < 64) sb[t] = (t < NBX) ? g_bsum[r][t] : 0;
    __syncthreads();
    if (t == 0) {
        int a = 0;
        for (int i = 0; i < bx; i++) a += sb[i];
        s_add = a;
        if (bx == NBX - 1) g_rowp[r][n] = a + sb[NBX - 1];
    }
    __syncthreads();
    int add = s_add;
    int base = bx * 2048 + t * 8;
#pragma unroll
    for (int j = 0; j < 8; j++) {
        int idx = base + j;
        if (idx < n) {
            int v = g_rowp[r][idx] + add;
            g_rowp[r][idx] = v;
            g_cnti[r][idx] = v;
        }
    }
}
__global__ void fill5_k(const int* e0, const int* e1, const int* e2,
                        const int* e3, const int* e4,
                        int E0, int E1, int E2, int E3, int E4,
                        int b0, int b1, int b2, int b3, int b4) {
    int r = blockIdx.y;
    const int* e; int E; int eb;
    switch (r) {
        case 0: e = e0; E = E0; eb = b0; break;
        case 1: e = e1; E = E1; eb = b1; break;
        case 2: e = e2; E = E2; eb = b2; break;
        case 3: e = e3; E = E3; eb = b3; break;
        default: e = e4; E = E4; eb = b4; break;
    }
    int i = blockIdx.x * 256 + threadIdx.x;
    if (i >= E) return;
    int s = edge_at(e, i);
    int d = edge_at(e, (long long)E + i);
    int pos = atomicAdd(&g_cnti[r][d], 1);
    g_col[eb + pos] = s;
}

// ---- merged CSR seg-mean aggregation (job table, warp per dst row) ---------
struct Agg5 {
    const float* xf[5];
    const int* rowp[5];
    const int* col[5];
    const float* invc[5];
    float* agg[5];
    int lds[5], soff[5], ldd[5], doff[5], n[5];
    int boff[6];
    int nslots;
};

template <int V>
__global__ void aggmulti_k(Agg5 J) {
    int b = blockIdx.x;
    int s = 0;
    while (s + 1 < J.nslots && b >= J.boff[s + 1]) s++;
    int row = (b - J.boff[s]) * 8 + (threadIdx.x >> 5);
    if (row >= J.n[s]) return;
    int lane = threadIdx.x & 31;
    const float* xf = J.xf[s];
    const int* col = J.col[s];
    int lds = J.lds[s], soff = J.soff[s];
    int beg = J.rowp[s][row], end = J.rowp[s][row + 1];
    float acc[V];
#pragma unroll
    for (int j = 0; j < V; j++) acc[j] = 0.0f;
    int e = beg;
    for (; e + 7 < end; e += 8) {
        int si[8];
#pragma unroll
        for (int u = 0; u < 8; u++) si[u] = __ldg(&col[e + u]);
        if (V == 4) {
            float4 vv[8];
#pragma unroll
            for (int u = 0; u < 8; u++)
                vv[u] = *(const float4*)(xf + (size_t)si[u] * lds + soff + lane * V);
#pragma unroll
            for (int u = 0; u < 8; u++) {
                acc[0] += vv[u].x; acc[1] += vv[u].y;
                acc[2] += vv[u].z; acc[3] += vv[u].w;
            }
        } else {
            float2 vv[8];
#pragma unroll
            for (int u = 0; u < 8; u++)
                vv[u] = *(const float2*)(xf + (size_t)si[u] * lds + soff + lane * V);
#pragma unroll
            for (int u = 0; u < 8; u++) {
                acc[0] += vv[u].x; acc[1] += vv[u].y;
            }
        }
    }
    // predicated-parallel remainder: all residual loads issue independently
    {
        int rem = end - e;   // 0..7
        if (rem > 0) {
            if (V == 4) {
                float4 vv[7];
#pragma unroll
                for (int u = 0; u < 7; u++) {
                    if (u < rem) {
                        int s0 = __ldg(&col[e + u]);
                        vv[u] = *(const float4*)(xf + (size_t)s0 * lds + soff + lane * V);
                    } else {
                        vv[u] = make_float4(0.f, 0.f, 0.f, 0.f);
                    }
                }
#pragma unroll
                for (int u = 0; u < 7; u++) {
                    acc[0] += vv[u].x; acc[1] += vv[u].y;
                    acc[2] += vv[u].z; acc[3] += vv[u].w;
                }
            } else {
                float2 vv[7];
#pragma unroll
                for (int u = 0; u < 7; u++) {
                    if (u < rem) {
                        int s0 = __ldg(&col[e + u]);
                        vv[u] = *(const float2*)(xf + (size_t)s0 * lds + soff + lane * V);
                    } else {
                        vv[u] = make_float2(0.f, 0.f);
                    }
                }
#pragma unroll
                for (int u = 0; u < 7; u++) {
                    acc[0] += vv[u].x; acc[1] += vv[u].y;
                }
            }
        }
    }
    float inv = J.invc[s][row];
    float* q = J.agg[s] + (size_t)row * J.ldd[s] + J.doff[s] + lane * V;
    if (V == 4) {
        *(float4*)q = make_float4(acc[0] * inv, acc[1] * inv, acc[2] * inv, acc[3] * inv);
    } else {
        *(float2*)q = make_float2(acc[0] * inv, acc[1] * inv);
    }
}

// ================= cp.async helpers =========================================
__device__ __forceinline__ void cp16(uint32_t dst, const void* src) {
    asm volatile("cp.async.ca.shared.global [%0], [%1], 16;" :: "r"(dst), "l"(src));
}
__device__ __forceinline__ void cp_commit() {
    asm volatile("cp.async.commit_group;");
}
__device__ __forceinline__ void cp_wait0() {
    asm volatile("cp.async.wait_group 0;" ::: "memory");
}

__device__ __forceinline__ void bsplit(float x, __nv_bfloat16& h, __nv_bfloat16& l) {
    h = __float2bfloat16_rn(x);
    l = __float2bfloat16_rn(x - __bfloat162float(h));
}

// ================= wmma bf16 split GEMM (job table, cp.async B) =============
// EPI: 0 plain, 1 relu, 3 relu+LN fused (Nfull==128),
//      4 relu+BN -> h@W2+b2 -> Cout (fused MLP).
struct TGJob {
    const float* A1[5];
    const float* A2[5];
    const __nv_bfloat16* Bhi[5];
    const __nv_bfloat16* Blo[5];
    const float* bias[5];
    float* C[5];
    int lda1[5], K1[5], lda2[5], K2[5], ldK[5], ldc[5], coff[5], M[5], Nfull[5];
    float alpha[5];
    float invr[5];
    // EPI=4 extras (slot 0 only)
    const __nv_bfloat16* W2h;
    const __nv_bfloat16* W2l;
    const float* b2;
    float* Cout;
};
#define TG_DSM 81920
template <int EPI>
__global__ __launch_bounds__(256, 2) void tgemm_k(
    TGJob J, const float* __restrict__ bnS, const float* __restrict__ bnB)
{
    extern __shared__ char dynsmem[];
    __nv_bfloat16* Asm = reinterpret_cast<__nv_bfloat16*>(dynsmem);
    __nv_bfloat16* Bsm = reinterpret_cast<__nv_bfloat16*>(dynsmem + 40960);
    uint32_t Bu32 = (uint32_t)__cvta_generic_to_shared(Bsm);

    int z = blockIdx.z;
    const float* A1 = J.A1[z];
    const float* A2 = J.A2[z];
    const __nv_bfloat16* Bhi = J.Bhi[z];
    const __nv_bfloat16* Blo = J.Blo[z];
    const float* bias = J.bias[z];
    float* C = J.C[z];
    int lda1 = J.lda1[z], K1 = J.K1[z], lda2 = J.lda2[z], K2 = J.K2[z];
    int ldK = J.ldK[z], ldc = J.ldc[z], coff = J.coff[z];
    int M = J.M[z], Nfull = J.Nfull[z];
    float alpha = J.alpha[z];

    int m0 = blockIdx.x * 128;
    int n0 = blockIdx.y * 128;
    if (m0 >= M || n0 >= Nfull) return;

    int tid = threadIdx.x;
    int wid = tid >> 5, lane = tid & 31;
    int wm = wid >> 2, wn = wid & 3;
    int mw = m0 + wm * 64;
    int nw = n0 + wn * 32;
    int nl = wn * 32;
    bool active = (nw < Nfull);
    int K = K1 + K2;
    int nkt = K >> 5;

    wmma::fragment<wmma::accumulator, 16, 16, 16, float> acc[4][2];
#pragma unroll
    for (int i = 0; i < 4; i++)
#pragma unroll
        for (int j = 0; j < 2; j++) wmma::fill_fragment(acc[i][j], 0.0f);

    int row = tid >> 1, half = tid & 1;
    int m = m0 + row;
    bool mok = (m < M);
    int brow = row, bhalf = half;

    // ---- prologue ----
    float4 v[4];
    {
        const float* Ap; int ld, kl;
        if (0 < K1) { Ap = A1; ld = lda1; kl = 0; }
        else        { Ap = A2; ld = lda2; kl = -K1; }
        const float* src = Ap + (size_t)m * ld + kl + half * 16;
#pragma unroll
        for (int i = 0; i < 4; i++)
            v[i] = mok ? *(const float4*)(src + i * 4) : make_float4(0.f, 0.f, 0.f, 0.f);
    }
    {
        const __nv_bfloat16* sH = Bhi + (size_t)(n0 + brow) * ldK + bhalf * 16;
        const __nv_bfloat16* sL = Blo + (size_t)(n0 + brow) * ldK + bhalf * 16;
        uint32_t dH = Bu32 + (uint32_t)(((0 * 2 + 0) * 128 + brow) * 40 + bhalf * 16) * 2;
        uint32_t dL = Bu32 + (uint32_t)(((0 * 2 + 1) * 128 + brow) * 40 + bhalf * 16) * 2;
        cp16(dH, sH); cp16(dH + 16, sH + 8);
        cp16(dL, sL); cp16(dL + 16, sL + 8);
        cp_commit();
    }

    int buf = 0;
    for (int kt = 0; kt < nkt; kt++) {
        {
            __nv_bfloat162* ah = reinterpret_cast<__nv_bfloat162*>(
                Asm + ((buf * 2 + 0) * 128 + row) * 40);
            __nv_bfloat162* al = reinterpret_cast<__nv_bfloat162*>(
                Asm + ((buf * 2 + 1) * 128 + row) * 40);
#pragma unroll
            for (int i = 0; i < 4; i++) {
                int col = half * 16 + i * 4;
                float4 x = v[i];
                __nv_bfloat16 hx = __float2bfloat16_rn(x.x);
                __nv_bfloat16 hy = __float2bfloat16_rn(x.y);
                __nv_bfloat16 hz = __float2bfloat16_rn(x.z);
                __nv_bfloat16 hw = __float2bfloat16_rn(x.w);
                __nv_bfloat162 h01; h01.x = hx; h01.y = hy;
                __nv_bfloat162 h23; h23.x = hz; h23.y = hw;
                ah[(col >> 1) + 0] = h01;
                ah[(col >> 1) + 1] = h23;
                __nv_bfloat162 l01, l23;
                l01.x = __float2bfloat16_rn(x.x - __bfloat162float(hx));
                l01.y = __float2bfloat16_rn(x.y - __bfloat162float(hy));
                l23.x = __float2bfloat16_rn(x.z - __bfloat162float(hz));
                l23.y = __float2bfloat16_rn(x.w - __bfloat162float(hw));
                al[(col >> 1) + 0] = l01;
                al[(col >> 1) + 1] = l23;
            }
        }
        cp_wait0();
        __syncthreads();
        if (kt + 1 < nkt) {
            int k0n = (kt + 1) << 5;
            const __nv_bfloat16* sH = Bhi + (size_t)(n0 + brow) * ldK + k0n + bhalf * 16;
            const __nv_bfloat16* sL = Blo + (size_t)(n0 + brow) * ldK + k0n + bhalf * 16;
            int ob = buf ^ 1;
            uint32_t dH = Bu32 + (uint32_t)(((ob * 2 + 0) * 128 + brow) * 40 + bhalf * 16) * 2;
            uint32_t dL = Bu32 + (uint32_t)(((ob * 2 + 1) * 128 + brow) * 40 + bhalf * 16) * 2;
            cp16(dH, sH); cp16(dH + 16, sH + 8);
            cp16(dL, sL); cp16(dL + 16, sL + 8);
            cp_commit();
            const float* Ap; int ld, kl;
            if (k0n < K1) { Ap = A1; ld = lda1; kl = k0n; }
            else          { Ap = A2; ld = lda2; kl = k0n - K1; }
            const float* src = Ap + (size_t)m * ld + kl + half * 16;
#pragma unroll
            for (int i = 0; i < 4; i++)
                v[i] = mok ? *(const float4*)(src + i * 4) : make_float4(0.f, 0.f, 0.f, 0.f);
        }
        if (active) {
            const __nv_bfloat16* BsH = Bsm + (buf * 2 + 0) * 128 * 40;
            const __nv_bfloat16* BsL = Bsm + (buf * 2 + 1) * 128 * 40;
#pragma unroll
            for (int kk = 0; kk < 32; kk += 16) {
                wmma::fragment<wmma::matrix_b, 16, 16, 16, __nv_bfloat16, wmma::col_major> bh[2], bl2[2];
#pragma unroll
                for (int j = 0; j < 2; j++) {
                    wmma::load_matrix_sync(bh[j],  BsH + (nl + j * 16) * 40 + kk, 40u);
                    wmma::load_matrix_sync(bl2[j], BsL + (nl + j * 16) * 40 + kk, 40u);
                }
#pragma unroll
                for (int i = 0; i < 4; i++) {
                    wmma::fragment<wmma::matrix_a, 16, 16, 16, __nv_bfloat16, wmma::row_major> ah, al;
                    wmma::load_matrix_sync(ah, Asm + ((buf * 2 + 0) * 128 + wm * 64 + i * 16) * 40 + kk, 40u);
                    wmma::load_matrix_sync(al, Asm + ((buf * 2 + 1) * 128 + wm * 64 + i * 16) * 40 + kk, 40u);
#pragma unroll
                    for (int j = 0; j < 2; j++) {
                        wmma::mma_sync(acc[i][j], ah, bh[j],  acc[i][j]);
                        wmma::mma_sync(acc[i][j], ah, bl2[j], acc[i][j]);
                        wmma::mma_sync(acc[i][j], al, bh[j],  acc[i][j]);
                    }
                }
            }
        }
        buf ^= 1;
    }
    __syncthreads();

    if (EPI == 3) {
        // ---- fused relu -> LayerNorm epilogue (Nfull == 128) ----
        float* obuf = reinterpret_cast<float*>(dynsmem);   // 128 x 132 f32
#pragma unroll
        for (int i = 0; i < 4; i++)
#pragma unroll
            for (int j = 0; j < 2; j++)
                wmma::store_matrix_sync(obuf + (wm * 64 + i * 16) * 132 + nl + j * 16,
                                        acc[i][j], 132u, wmma::mem_row_major);
        __syncthreads();
        float invr = J.invr[z];
        int r0 = wid * 16;
        for (int rr = 0; rr < 16; rr++) {
            int rloc = r0 + rr;
            int mm = m0 + rloc;
            if (mm >= M) continue;
            float vv[4]; float s = 0.f;
#pragma unroll
            for (int j = 0; j < 4; j++) {
                int c = lane + 32 * j;
                float val = obuf[rloc * 132 + c] * alpha + bias[c];
                vv[j] = fmaxf(val * invr, 0.f);
                s += vv[j];
            }
#pragma unroll
            for (int o = 16; o; o >>= 1) s += __shfl_xor_sync(0xffffffffu, s, o);
            float mean = s * (1.0f / 128.0f);
            float ss = 0.f;
#pragma unroll
            for (int j = 0; j < 4; j++) { float d = vv[j] - mean; ss += d * d; }
#pragma unroll
            for (int o = 16; o; o >>= 1) ss += __shfl_xor_sync(0xffffffffu, ss, o);
            float inv = rsqrtf(ss * (1.0f / 128.0f) + 1e-5f);
            float* q = C + (size_t)mm * ldc;
#pragma unroll
            for (int j = 0; j < 4; j++) {
                int c = lane + 32 * j;
                q[c] = (vv[j] - mean) * inv * bnS[c] + bnB[c];
            }
        }
    } else if (EPI == 4) {
        // ---- relu+BN -> h (bf16 hi/lo, stride 136) -> h@W2+b2 -> Cout ----
        __nv_bfloat16* hHb = reinterpret_cast<__nv_bfloat16*>(dynsmem);
        __nv_bfloat16* hLb = hHb + 128 * 136;
        float* myp = reinterpret_cast<float*>(dynsmem + 69632) + wid * 320;
        int base = lane * 8;
        int pr = base >> 4, pc = base & 15;
#pragma unroll
        for (int i = 0; i < 4; i++) {
#pragma unroll
            for (int j = 0; j < 2; j++) {
                wmma::store_matrix_sync(myp, acc[i][j], 20u, wmma::mem_row_major);
                __syncwarp();
                int rloc = wm * 64 + i * 16 + pr;
                int nb = nl + j * 16;
                bool rok = (m0 + rloc < M);
#pragma unroll
                for (int t = 0; t < 8; t++) {
                    int n = nb + pc + t;
                    float val = rok ? (myp[pr * 20 + pc + t] * alpha + bias[n]) : 0.f;
                    val = fmaxf(val, 0.f) * bnS[n] + bnB[n];
                    __nv_bfloat16 hh, ll;
                    bsplit(val, hh, ll);
                    hHb[rloc * 136 + n] = hh;
                    hLb[rloc * 136 + n] = ll;
                }
                __syncwarp();
            }
        }
        __syncthreads();
        wmma::fragment<wmma::accumulator, 16, 16, 16, float> acc2[2];
#pragma unroll
        for (int j = 0; j < 2; j++) wmma::fill_fragment(acc2[j], 0.0f);
        const __nv_bfloat16* W2h = J.W2h;
        const __nv_bfloat16* W2l = J.W2l;
        int r0 = wid * 16;
#pragma unroll
        for (int kf = 0; kf < 8; kf++) {
            wmma::fragment<wmma::matrix_a, 16, 16, 16, __nv_bfloat16, wmma::row_major> ah, al;
            wmma::load_matrix_sync(ah, hHb + r0 * 136 + kf * 16, 136u);
            wmma::load_matrix_sync(al, hLb + r0 * 136 + kf * 16, 136u);
#pragma unroll
            for (int j = 0; j < 2; j++) {
                wmma::fragment<wmma::matrix_b, 16, 16, 16, __nv_bfloat16, wmma::col_major> bh, bl2;
                wmma::load_matrix_sync(bh,  W2h + (size_t)(j * 16) * 128 + kf * 16, 128u);
                wmma::load_matrix_sync(bl2, W2l + (size_t)(j * 16) * 128 + kf * 16, 128u);
                wmma::mma_sync(acc2[j], ah, bh,  acc2[j]);
                wmma::mma_sync(acc2[j], ah, bl2, acc2[j]);
                wmma::mma_sync(acc2[j], al, bh,  acc2[j]);
            }
        }
        const float* b2 = J.b2;
        float* Cout = J.Cout;
#pragma unroll
        for (int j = 0; j < 2; j++) {
            wmma::store_matrix_sync(myp, acc2[j], 20u, wmma::mem_row_major);
            __syncwarp();
            int mm = m0 + r0 + pr;
            if (mm < M) {
                float out[8];
#pragma unroll
                for (int t = 0; t < 8; t++) {
                    int n = j * 16 + pc + t;
                    out[t] = myp[pr * 20 + pc + t] + b2[n];
                }
                float* dst = Cout + (size_t)mm * 32 + j * 16 + pc;
                *(float4*)dst = *(float4*)&out[0];
                *(float4*)(dst + 4) = *(float4*)&out[4];
            }
            __syncwarp();
        }
    } else if (active) {
        float* myp = reinterpret_cast<float*>(dynsmem) + wid * 320;
        int base = lane * 8;
        int pr = base >> 4, pc = base & 15;
#pragma unroll
        for (int i = 0; i < 4; i++) {
#pragma unroll
            for (int j = 0; j < 2; j++) {
                wmma::store_matrix_sync(myp, acc[i][j], 20u, wmma::mem_row_major);
                __syncwarp();
                int mb = mw + i * 16, nb = nw + j * 16;
                if (mb + pr < M) {
                    float out[8];
#pragma unroll
                    for (int t = 0; t < 8; t++) {
                        int n = nb + pc + t;
                        float val = myp[pr * 20 + pc + t] * alpha + bias[n];
                        if (EPI >= 1) val = fmaxf(val, 0.0f);
                        out[t] = val;
                    }
                    float* dst = C + (size_t)(mb + pr) * ldc + coff + nb + pc;
                    *(float4*)dst = *(float4*)&out[0];
                    *(float4*)(dst + 4) = *(float4*)&out[4];
                }
                __syncwarp();
            }
        }
    }
}

// ================= merged elementwise: layer-0 post ==========================
__global__ void l0post2_k(const float* __restrict__ On, const float* __restrict__ Ob,
                          const float* __restrict__ gg, const float* __restrict__ bb,
                          float* __restrict__ xn, float* __restrict__ xb, int nblkN) {
    int b = blockIdx.x;
    const float* O; float* xout; int ldo, M, R;
    if (b < nblkN) { O = On; xout = xn; ldo = 384; M = NN; R = 3; }
    else           { O = Ob; xout = xb; ldo = 256; M = NB; R = 2; b -= nblkN; }
    int row = b * 8 + (threadIdx.x >> 5);
    if (row >= M) return;
    int lane = threadIdx.x & 31;
    float acc[4] = {0.f, 0.f, 0.f, 0.f};
    for (int rb = 0; rb < R; rb++) {
        const float* p = O + (size_t)row * ldo + rb * 128;
        float v[4]; float ss = 0.f;
#pragma unroll
        for (int j = 0; j < 4; j++) { v[j] = p[lane + 32 * j]; ss += v[j] * v[j]; }
#pragma unroll
        for (int s = 16; s; s >>= 1) ss += __shfl_xor_sync(0xffffffffu, ss, s);
        float inv = 1.0f / fmaxf(sqrtf(ss), 1e-12f);
#pragma unroll
        for (int j = 0; j < 4; j++) acc[j] += v[j] * inv;
    }
    const float invR = 1.0f / R;
    float s = 0.f;
#pragma unroll
    for (int j = 0; j < 4; j++) { acc[j] = fmaxf(acc[j] * invR, 0.f); s += acc[j]; }
#pragma unroll
    for (int o = 16; o; o >>= 1) s += __shfl_xor_sync(0xffffffffu, s, o);
    float m = s * (1.0f / 128.0f);
    float ss = 0.f;
#pragma unroll
    for (int j = 0; j < 4; j++) { float d = acc[j] - m; ss += d * d; }
#pragma unroll
    for (int o = 16; o; o >>= 1) ss += __shfl_xor_sync(0xffffffffu, ss, o);
    float inv = rsqrtf(ss * (1.0f / 128.0f) + 1e-5f);
    float* q = xout + (size_t)row * 128;
#pragma unroll
    for (int j = 0; j < 4; j++) {
        int c = lane + 32 * j;
        q[c] = (acc[j] - m) * inv * gg[c] + bb[c];
    }
}

// ================= fused weight-prep + init kernel ===========================
__device__ __forceinline__ void lsplit_body(__nv_bfloat16* hi, __nv_bfloat16* lo,
                                            const float* WlL, const float* WrL,
                                            int r0, int r1, int r2, int nrel, int idx) {
    int K = nrel * 128 + 128;
    int n = idx / K, k = idx - n * K;
    float x;
    if (k < nrel * 128) {
        int j = k >> 7, kk = k & 127;
        int r = (j == 0) ? r0 : (j == 1) ? r1 : r2;
        x = WlL[(size_t)r * 16384 + kk * 128 + n];
    } else {
        int kk = k - nrel * 128;
        x = WrL[(size_t)r0 * 16384 + kk * 128 + n] + WrL[(size_t)r1 * 16384 + kk * 128 + n];
        if (nrel == 3) x += WrL[(size_t)r2 * 16384 + kk * 128 + n];
    }
    __nv_bfloat16 h, l;
    bsplit(x, h, l);
    hi[idx] = h;
    lo[idx] = l;
}
#define PREP_TOTAL (305152 + 5 * NN)
__global__ void prep_k(const float* __restrict__ proj_W, const float* __restrict__ proj_b,
                       const float* __restrict__ l0_Wl, const float* __restrict__ l0_bl,
                       const float* __restrict__ l0_Wr,
                       const float* __restrict__ Wl, const float* __restrict__ bl,
                       const float* __restrict__ Wr,
                       const float* __restrict__ mlp_W1, const float* __restrict__ mlp_W2,
                       const float* __restrict__ bn_g, const int* __restrict__ e0) {
    int idx = blockIdx.x * 256 + threadIdx.x;
    __nv_bfloat16 h, l;
    if (idx < 12288) {
        int j = idx >> 12, rem = idx & 4095;
        int k = rem >> 6, c = rem & 63;
        float x = proj_W[(size_t)j * 4096 + k * 64 + c];
        int n = j * 64 + c;
        bsplit(x, h, l);
        g_BtProjN[0][n * 64 + k] = h; g_BtProjN[1][n * 64 + k] = l;
        return;
    }
    idx -= 12288;
    if (idx < 8192) {
        int j = idx >> 12, rem = idx & 4095;
        int k = rem >> 6, c = rem & 63;
        int r = (j == 0) ? 3 : 4;
        float x = proj_W[(size_t)r * 4096 + k * 64 + c];
        int n = j * 64 + c;
        bsplit(x, h, l);
        g_BtProjB[0][n * 64 + k] = h; g_BtProjB[1][n * 64 + k] = l;
        return;
    }
    idx -= 8192;
    if (idx < 81920) {
        int s = idx >> 14, rem = idx & 16383;
        int n = rem >> 7, k = rem & 127;
        const int rels[5] = {0, 1, 3, 2, 4};
        int r = rels[s];
        float x = (k < 64) ? l0_Wr[(size_t)r * 8192 + k * 128 + n]
                           : l0_Wl[(size_t)r * 8192 + (k - 64) * 128 + n];
        bsplit(x, h, l);
        g_BtL0[0][s][rem] = h; g_BtL0[1][s][rem] = l;
        return;
    }
    idx -= 81920;
    if (idx < 65536) { lsplit_body(g_BtL1N[0], g_BtL1N[1], Wl, Wr, 0, 1, 3, 3, idx); return; }
    idx -= 65536;
    if (idx < 49152) { lsplit_body(g_BtL1B[0], g_BtL1B[1], Wl, Wr, 2, 4, 0, 2, idx); return; }
    idx -= 49152;
    if (idx < 65536) { lsplit_body(g_BtL2N[0], g_BtL2N[1], Wl + 5 * 16384, Wr + 5 * 16384, 0, 1, 3, 3, idx); return; }
    idx -= 65536;
    if (idx < 16384) {
        int k = idx >> 7, n = idx & 127;
        bsplit(mlp_W1[idx], h, l);
        g_BtM1[0][n * 128 + k] = h; g_BtM1[1][n * 128 + k] = l;
        return;
    }
    idx -= 16384;
    if (idx < 4096) {
        int k = idx / 32, n = idx - (idx / 32) * 32;
        bsplit(mlp_W2[idx], h, l);
        g_BtM2[0][n * 128 + k] = h; g_BtM2[1][n * 128 + k] = l;
        return;
    }
    idx -= 4096;
    if (idx < 2048) {
        int t = idx;
        if (t < 192) {
            int j = t / 64;
            g_pbCatN[t] = proj_b[(size_t)j * 64 + (t - j * 64)];
        } else if (t < 320) {
            int local = t - 192; int j = local / 64;
            int r = (j == 0) ? 3 : 4;
            g_pbCatB[local] = proj_b[(size_t)r * 64 + (local - j * 64)];
        } else if (t < 704) {
            int local = t - 320; int j = local / 128;
            int r = (j == 0) ? 0 : (j == 1) ? 1 : 3;
            g_l0blCatN[local] = l0_bl[(size_t)r * 128 + (local - j * 128)];
        } else if (t < 960) {
            int local = t - 704; int j = local / 128;
            int r = (j == 0) ? 2 : 4;
            g_l0blCatB[local] = l0_bl[(size_t)r * 128 + (local - j * 128)];
        } else if (t < 1088) {
            int i = t - 960;
            g_b1SumN[i] = bl[i] + bl[128 + i] + bl[3 * 128 + i];
        } else if (t < 1216) {
            int i = t - 1088;
            g_b1SumB[i] = bl[2 * 128 + i] + bl[4 * 128 + i];
        } else if (t < 1344) {
            int i = t - 1216;
            g_b2SumN[i] = bl[(5 + 0) * 128 + i] + bl[(5 + 1) * 128 + i] + bl[(5 + 3) * 128 + i];
        } else if (t < 1472) {
            int i = t - 1344;
            g_bnS[i] = bn_g[i] * rsqrtf(1.0f + 1e-5f);
        } else if (t == 1472) {
            int z = 1;
            for (int i = 1; i < 64; i += 2)
                if (e0[i] != 0) z = 0;
            g_emode = z;
        }
        return;
    }
    idx -= 2048;
    if (idx < 5 * NN) ((int*)g_cnti)[idx] = 0;
}

// ================= host dispatch =============================================
static void tgemmJ(int epi, const TGJob& J, int nslots, const float* p0, const float* p1) {
    int maxM = 0, maxN = 0;
    for (int s = 0; s < nslots; s++) {
        if (J.M[s] > maxM) maxM = J.M[s];
        if (J.Nfull[s] > maxN) maxN = J.Nfull[s];
    }
    dim3 g((maxM + 127) / 128, (maxN + 127) / 128, nslots);
    if (epi == 0) {
        cudaFuncSetAttribute(tgemm_k<0>, cudaFuncAttributeMaxDynamicSharedMemorySize, TG_DSM);
        tgemm_k<0><<<g, 256, TG_DSM>>>(J, p0, p1);
    } else if (epi == 1) {
        cudaFuncSetAttribute(tgemm_k<1>, cudaFuncAttributeMaxDynamicSharedMemorySize, TG_DSM);
        tgemm_k<1><<<g, 256, TG_DSM>>>(J, p0, p1);
    } else if (epi == 3) {
        cudaFuncSetAttribute(tgemm_k<3>, cudaFuncAttributeMaxDynamicSharedMemorySize, TG_DSM);
        tgemm_k<3><<<g, 256, TG_DSM>>>(J, p0, p1);
    } else {
        cudaFuncSetAttribute(tgemm_k<4>, cudaFuncAttributeMaxDynamicSharedMemorySize, TG_DSM);
        tgemm_k<4><<<g, 256, TG_DSM>>>(J, p0, p1);
    }
}
static void setslot(TGJob& J, int s, const float* A1, int lda1, int K1,
                    const float* A2, int lda2, int K2,
                    const __nv_bfloat16* Bh, const __nv_bfloat16* Bl, int ldK,
                    const float* bias, float* C, int ldc, int coff,
                    int M, int Nfull, float alpha, float invr = 1.0f) {
    J.A1[s] = A1; J.lda1[s] = lda1; J.K1[s] = K1;
    J.A2[s] = A2; J.lda2[s] = lda2; J.K2[s] = K2;
    J.Bhi[s] = Bh; J.Blo[s] = Bl; J.ldK[s] = ldK;
    J.bias[s] = bias; J.C[s] = C; J.ldc[s] = ldc; J.coff[s] = coff;
    J.M[s] = M; J.Nfull[s] = Nfull; J.alpha[s] = alpha; J.invr[s] = invr;
}

extern "C" void kernel_launch(void* const* d_in, const int* in_sizes, int n_in,
                              void* d_out, int out_size) {
    const float* x_note = (const float*)d_in[0];
    const float* x_beat = (const float*)d_in[1];
    const int* e[5] = {(const int*)d_in[2], (const int*)d_in[3], (const int*)d_in[4],
                       (const int*)d_in[5], (const int*)d_in[6]};
    int E[5];
    for (int r = 0; r < 5; r++) E[r] = in_sizes[2 + r] / 2;
    const float* proj_W = (const float*)d_in[7];
    const float* proj_b = (const float*)d_in[8];
    const float* l0_Wl  = (const float*)d_in[9];
    const float* l0_bl  = (const float*)d_in[10];
    const float* l0_Wr  = (const float*)d_in[11];
    const float* Wl     = (const float*)d_in[12];
    const float* bl     = (const float*)d_in[13];
    const float* Wr     = (const float*)d_in[14];
    const float* ln_g   = (const float*)d_in[15];
    const float* ln_b   = (const float*)d_in[16];
    const float* mlp_W1 = (const float*)d_in[17];
    const float* mlp_b1 = (const float*)d_in[18];
    const float* bn_g   = (const float*)d_in[19];
    const float* bn_b   = (const float*)d_in[20];
    const float* mlp_W2 = (const float*)d_in[21];
    const float* mlp_b2 = (const float*)d_in[22];

    float *pn, *pb, *aggn, *aggb, *On, *Ob, *xn0, *xn1, *xb0, *xb1, *outn, *cntf;
    int *rowp, *colx;
    cudaGetSymbolAddress((void**)&pn, g_pn);       cudaGetSymbolAddress((void**)&pb, g_pb);
    cudaGetSymbolAddress((void**)&aggn, g_aggn);   cudaGetSymbolAddress((void**)&aggb, g_aggb);
    cudaGetSymbolAddress((void**)&On, g_On);       cudaGetSymbolAddress((void**)&Ob, g_Ob);
    cudaGetSymbolAddress((void**)&xn0, g_xn0);     cudaGetSymbolAddress((void**)&xn1, g_xn1);
    cudaGetSymbolAddress((void**)&xb0, g_xb0);     cudaGetSymbolAddress((void**)&xb1, g_xb1);
    cudaGetSymbolAddress((void**)&outn, g_outn);
    cudaGetSymbolAddress((void**)&cntf, g_cnt);
    cudaGetSymbolAddress((void**)&rowp, g_rowp);   cudaGetSymbolAddress((void**)&colx, g_col);

    float *pbCatN, *pbCatB, *l0blCatN, *l0blCatB, *b1SumN, *b1SumB, *b2SumN, *bnS;
    cudaGetSymbolAddress((void**)&pbCatN, g_pbCatN);     cudaGetSymbolAddress((void**)&pbCatB, g_pbCatB);
    cudaGetSymbolAddress((void**)&l0blCatN, g_l0blCatN); cudaGetSymbolAddress((void**)&l0blCatB, g_l0blCatB);
    cudaGetSymbolAddress((void**)&b1SumN, g_b1SumN);     cudaGetSymbolAddress((void**)&b1SumB, g_b1SumB);
    cudaGetSymbolAddress((void**)&b2SumN, g_b2SumN);     cudaGetSymbolAddress((void**)&bnS, g_bnS);

    __nv_bfloat16 *BtProjN[2], *BtProjB[2], *BtL0[2], *BtL1N[2], *BtL1B[2], *BtL2N[2], *BtM1[2], *BtM2[2];
    {
        __nv_bfloat16* p;
        cudaGetSymbolAddress((void**)&p, g_BtProjN); BtProjN[0] = p; BtProjN[1] = p + 256 * 64;
        cudaGetSymbolAddress((void**)&p, g_BtProjB); BtProjB[0] = p; BtProjB[1] = p + 128 * 64;
        cudaGetSymbolAddress((void**)&p, g_BtL0);    BtL0[0] = p;    BtL0[1] = p + 5 * 128 * 128;
        cudaGetSymbolAddress((void**)&p, g_BtL1N);   BtL1N[0] = p;   BtL1N[1] = p + 128 * 512;
        cudaGetSymbolAddress((void**)&p, g_BtL1B);   BtL1B[0] = p;   BtL1B[1] = p + 128 * 384;
        cudaGetSymbolAddress((void**)&p, g_BtL2N);   BtL2N[0] = p;   BtL2N[1] = p + 128 * 512;
        cudaGetSymbolAddress((void**)&p, g_BtM1);    BtM1[0] = p;    BtM1[1] = p + 128 * 128;
        cudaGetSymbolAddress((void**)&p, g_BtM2);    BtM2[0] = p;    BtM2[1] = p + 128 * 128;
    }

    int ebase[5];
    { int acc = 0; for (int r = 0; r < 5; r++) { ebase[r] = acc; acc += E[r]; } }
    int maxE = 0;
    for (int r = 0; r < 5; r++) maxE = (E[r] > maxE) ? E[r] : maxE;

    // ---- prep (weights + biases + emode + zero counters), then CSR build ----
    prep_k<<<(PREP_TOTAL + 255) / 256, 256>>>(proj_W, proj_b, l0_Wl, l0_bl, l0_Wr,
                                              Wl, bl, Wr, mlp_W1, mlp_W2, bn_g, e[0]);
    counti5_k<<<dim3((maxE + 255) / 256, 5), 256>>>(e[0], e[1], e[2], e[3], e[4],
                                                    E[0], E[1], E[2], E[3], E[4]);
    scan1_k<<<dim3(NBX, 5), 256>>>();
    scan3_k<<<dim3(NBX, 5), 256>>>();
    fill5_k<<<dim3((maxE + 255) / 256, 5), 256>>>(e[0], e[1], e[2], e[3], e[4],
                                                  E[0], E[1], E[2], E[3], E[4],
                                                  ebase[0], ebase[1], ebase[2], ebase[3], ebase[4]);
    const int* rp[5]; const int* cx[5]; const float* ic[5];
    for (int r = 0; r < 5; r++) {
        rp[r] = rowp + r * (NN + 1);
        cx[r] = colx + ebase[r];
        ic[r] = cntf + r * NN;
    }

    const int NBLK_N = (NN + 7) / 8;
    const int NBLK_B = (NB + 7) / 8;

    auto mkjob = [&](Agg5& J, int s, const float* xf, int lds, int soff, int rel,
                     float* agg, int ldd, int doff, int n) {
        J.xf[s] = xf; J.lds[s] = lds; J.soff[s] = soff;
        J.rowp[s] = rp[rel]; J.col[s] = cx[rel]; J.invc[s] = ic[rel];
        J.agg[s] = agg; J.ldd[s] = ldd; J.doff[s] = doff; J.n[s] = n;
    };

    // ==================== layer 0 ====================
    {
        TGJob G;
        setslot(G, 0, x_note, 64, 64, nullptr, 0, 0, BtProjN[0], BtProjN[1], 64,
                pbCatN, pn, 192, 0, NN, 192, 1.f);
        setslot(G, 1, x_beat, 64, 64, nullptr, 0, 0, BtProjB[0], BtProjB[1], 64,
                pbCatB, pb, 128, 0, NB, 128, 1.f);
        tgemmJ(1, G, 2, nullptr, nullptr);
    }
    {
        Agg5 J; J.nslots = 5;
        mkjob(J, 0, pn, 192, 0,   0, aggn, 192, 0,   NN);
        mkjob(J, 1, pn, 192, 64,  1, aggn, 192, 64,  NN);
        mkjob(J, 2, pb, 128, 0,   3, aggn, 192, 128, NN);
        mkjob(J, 3, pn, 192, 128, 2, aggb, 128, 0,   NB);
        mkjob(J, 4, pb, 128, 64,  4, aggb, 128, 64,  NB);
        J.boff[0] = 0; J.boff[1] = NBLK_N; J.boff[2] = 2 * NBLK_N; J.boff[3] = 3 * NBLK_N;
        J.boff[4] = 3 * NBLK_N + NBLK_B; J.boff[5] = 3 * NBLK_N + 2 * NBLK_B;
        aggmulti_k<2><<<J.boff[5], 256>>>(J);
    }
    {
        TGJob G;
        for (int j = 0; j < 3; j++)
            setslot(G, j, x_note, 64, 64, aggn + j * 64, 192, 64,
                    BtL0[0] + j * 16384, BtL0[1] + j * 16384, 128,
                    l0blCatN + j * 128, On, 384, j * 128, NN, 128, 1.f);
        for (int j = 0; j < 2; j++)
            setslot(G, 3 + j, x_beat, 64, 64, aggb + j * 64, 128, 64,
                    BtL0[0] + (3 + j) * 16384, BtL0[1] + (3 + j) * 16384, 128,
                    l0blCatB + j * 128, Ob, 256, j * 128, NB, 128, 1.f);
        tgemmJ(0, G, 5, nullptr, nullptr);
    }
    l0post2_k<<<NBLK_N + NBLK_B, 256>>>(On, Ob, ln_g, ln_b, xn0, xb0, NBLK_N);

    // ==================== layer 1 (GEMM with fused relu+LN epilogue) =========
    {
        Agg5 J; J.nslots = 5;
        mkjob(J, 0, xn0, 128, 0, 0, aggn, 384, 0,   NN);
        mkjob(J, 1, xn0, 128, 0, 1, aggn, 384, 128, NN);
        mkjob(J, 2, xb0, 128, 0, 3, aggn, 384, 256, NN);
        mkjob(J, 3, xn0, 128, 0, 2, aggb, 256, 0,   NB);
        mkjob(J, 4, xb0, 128, 0, 4, aggb, 256, 128, NB);
        J.boff[0] = 0; J.boff[1] = NBLK_N; J.boff[2] = 2 * NBLK_N; J.boff[3] = 3 * NBLK_N;
        J.boff[4] = 3 * NBLK_N + NBLK_B; J.boff[5] = 3 * NBLK_N + 2 * NBLK_B;
        aggmulti_k<4><<<J.boff[5], 256>>>(J);
    }
    {
        TGJob G;
        setslot(G, 0, aggn, 384, 384, xn0, 128, 128, BtL1N[0], BtL1N[1], 512,
                b1SumN, xn1, 128, 0, NN, 128, 1.f, 1.f / 3.f);
        setslot(G, 1, aggb, 256, 256, xb0, 128, 128, BtL1B[0], BtL1B[1], 384,
                b1SumB, xb1, 128, 0, NB, 128, 1.f, 1.f / 2.f);
        tgemmJ(3, G, 2, ln_g + 128, ln_b + 128);
    }

    // ==================== layer 2 (note dst only) ====================
    {
        Agg5 J; J.nslots = 3;
        mkjob(J, 0, xn1, 128, 0, 0, aggn, 384, 0,   NN);
        mkjob(J, 1, xn1, 128, 0, 1, aggn, 384, 128, NN);
        mkjob(J, 2, xb1, 128, 0, 3, aggn, 384, 256, NN);
        J.boff[0] = 0; J.boff[1] = NBLK_N; J.boff[2] = 2 * NBLK_N; J.boff[3] = 3 * NBLK_N;
        J.boff[4] = 3 * NBLK_N; J.boff[5] = 3 * NBLK_N;
        aggmulti_k<4><<<J.boff[3], 256>>>(J);
    }
    {
        TGJob G;
        setslot(G, 0, aggn, 384, 384, xn1, 128, 128, BtL2N[0], BtL2N[1], 512,
                b2SumN, outn, 128, 0, NN, 128, 1.f);
        tgemmJ(0, G, 1, nullptr, nullptr);
    }

    // ==================== final MLP (fused MLP1+BN+MLP2, writes d_out) =======
    {
        TGJob G;
        setslot(G, 0, outn, 128, 128, nullptr, 0, 0, BtM1[0], BtM1[1], 128,
                mlp_b1, On, 128, 0, NN, 128, 1.f / 3.f);
        G.W2h = BtM2[0]; G.W2l = BtM2[1]; G.b2 = mlp_b2; G.Cout = (float*)d_out;
        tgemmJ(4, G, 1, bnS, bn_b);
    }
}

// round 17
// speedup vs baseline: 1.1123x; 1.0051x over previous
#include <cuda_runtime.h>
#include <cuda_bf16.h>
#include <mma.h>
#include <cstdint>

using namespace nvcuda;

#define NN 100000
#define NB 20000
#define INC 64
#define HID 128
#define NBX 49
#define MAXE 3000000

// ================= scratch (device globals; no runtime allocation) ==========
__device__ float g_pn  [(size_t)NN * 192];
__device__ float g_pb  [(size_t)NB * 128];
__device__ float g_aggn[(size_t)NN * 384];
__device__ float g_aggb[(size_t)NB * 256];
__device__ float g_On  [(size_t)NN * 384];
__device__ float g_Ob  [(size_t)NB * 256];
__device__ float g_xn0 [(size_t)NN * HID];
__device__ float g_xn1 [(size_t)NN * HID];
__device__ float g_xb0 [(size_t)NB * HID];
__device__ float g_xb1 [(size_t)NB * HID];
__device__ float g_outn[(size_t)NN * HID];
__device__ float g_cnt [5][NN];
__device__ int   g_cnti[5][NN];
__device__ int   g_rowp[5][NN + 1];
__device__ int   g_bsum[5][64];
__device__ int   g_col [MAXE];
__device__ int   g_emode;

// bias scratch
__device__ float g_pbCatN[192];
__device__ float g_pbCatB[128];
__device__ float g_l0blCatN[384];
__device__ float g_l0blCatB[256];
__device__ float g_b1SumN[128];
__device__ float g_b1SumB[128];
__device__ float g_b2SumN[128];
__device__ float g_bnS[128];
// bf16 transposed+split weights [Npad x K], hi/lo
__device__ __nv_bfloat16 g_BtProjN[2][256 * 64];
__device__ __nv_bfloat16 g_BtProjB[2][128 * 64];
__device__ __nv_bfloat16 g_BtL0  [2][5][128 * 128];
__device__ __nv_bfloat16 g_BtL1N [2][128 * 512];
__device__ __nv_bfloat16 g_BtL1B [2][128 * 384];
__device__ __nv_bfloat16 g_BtL2N [2][128 * 512];
__device__ __nv_bfloat16 g_BtM1  [2][128 * 128];
__device__ __nv_bfloat16 g_BtM2  [2][128 * 128];

// ================= init: zero counters + edge dtype detection ===============
__global__ void init_k(const int* e) {
    long long idx = (long long)blockIdx.x * 256 + threadIdx.x;
    if (idx < 5LL * NN) ((int*)g_cnti)[idx] = 0;
    if (idx == 0) {
        int z = 1;
        for (int i = 1; i < 64; i += 2)
            if (e[i] != 0) z = 0;
        g_emode = z;
    }
}
__device__ __forceinline__ int edge_at(const int* e, long long i) {
    if (g_emode) return (int)((const long long*)e)[i];
    return e[i];
}
__global__ void counti5_k(const int* e0, const int* e1, const int* e2,
                          const int* e3, const int* e4,
                          int E0, int E1, int E2, int E3, int E4) {
    int r = blockIdx.y;
    const int* e; int E;
    switch (r) {
        case 0: e = e0; E = E0; break;
        case 1: e = e1; E = E1; break;
        case 2: e = e2; E = E2; break;
        case 3: e = e3; E = E3; break;
        default: e = e4; E = E4; break;
    }
    int i = blockIdx.x * 256 + threadIdx.x;
    if (i >= E) return;
    atomicAdd(&g_cnti[r][edge_at(e, (long long)E + i)], 1);
}
__global__ void scan1_k() {
    int r = blockIdx.y;
    int n = (r == 2 || r == 4) ? NB : NN;
    int t = threadIdx.x;
    int base = blockIdx.x * 2048 + t * 8;
    int vals[8];
#pragma unroll
    for (int j = 0; j < 8; j++) {
        int idx = base + j;
        vals[j] = (idx < n) ? g_cnti[r][idx] : 0;
        if (idx < n) g_cnt[r][idx] = 1.0f / (float)max(vals[j], 1);
    }
    int tot = 0;
#pragma unroll
    for (int j = 0; j < 8; j++) tot += vals[j];
    int lane = t & 31, wid = t >> 5;
    int x = tot;
#pragma unroll
    for (int o = 1; o < 32; o <<= 1) {
        int y = __shfl_up_sync(0xffffffffu, x, o);
        if (lane >= o) x += y;
    }
    __shared__ int wsum[8];
    if (lane == 31) wsum[wid] = x;
    __syncthreads();
    if (t == 0) {
        int run = 0;
#pragma unroll
        for (int i = 0; i < 8; i++) { int v = wsum[i]; wsum[i] = run; run += v; }
        g_bsum[r][blockIdx.x] = run;
    }
    __syncthreads();
    int run = (x - tot) + wsum[wid];
#pragma unroll
    for (int j = 0; j < 8; j++) {
        int idx = base + j;
        if (idx < n) g_rowp[r][idx] = run;
        run += vals[j];
    }
}
__global__ void scan3_k() {
    int r = blockIdx.y;
    int n = (r == 2 || r == 4) ? NB : NN;
    int bx = blockIdx.x;
    int t = threadIdx.x;
    __shared__ int sb[64];
    __shared__ int s_add;
    if (t < 64) sb[t] = (t < NBX) ? g_bsum[r][t] : 0;
    __syncthreads();
    if (t == 0) {
        int a = 0;
        for (int i = 0; i < bx; i++) a += sb[i];
        s_add = a;
        if (bx == NBX - 1) g_rowp[r][n] = a + sb[NBX - 1];
    }
    __syncthreads();
    int add = s_add;
    int base = bx * 2048 + t * 8;
#pragma unroll
    for (int j = 0; j < 8; j++) {
        int idx = base + j;
        if (idx < n) {
            int v = g_rowp[r][idx] + add;
            g_rowp[r][idx] = v;
            g_cnti[r][idx] = v;
        }
    }
}
__global__ void fill5_k(const int* e0, const int* e1, const int* e2,
                        const int* e3, const int* e4,
                        int E0, int E1, int E2, int E3, int E4,
                        int b0, int b1, int b2, int b3, int b4) {
    int r = blockIdx.y;
    const int* e; int E; int eb;
    switch (r) {
        case 0: e = e0; E = E0; eb = b0; break;
        case 1: e = e1; E = E1; eb = b1; break;
        case 2: e = e2; E = E2; eb = b2; break;
        case 3: e = e3; E = E3; eb = b3; break;
        default: e = e4; E = E4; eb = b4; break;
    }
    int i = blockIdx.x * 256 + threadIdx.x;
    if (i >= E) return;
    int s = edge_at(e, i);
    int d = edge_at(e, (long long)E + i);
    int pos = atomicAdd(&g_cnti[r][d], 1);
    g_col[eb + pos] = s;
}

// ---- merged CSR seg-mean aggregation (job table, warp per dst row) ---------
struct Agg5 {
    const float* xf[5];
    const int* rowp[5];
    const int* col[5];
    const float* invc[5];
    float* agg[5];
    int lds[5], soff[5], ldd[5], doff[5], n[5];
    int boff[6];
    int nslots;
};

template <int V>
__global__ void aggmulti_k(Agg5 J) {
    int b = blockIdx.x;
    int s = 0;
    while (s + 1 < J.nslots && b >= J.boff[s + 1]) s++;
    int row = (b - J.boff[s]) * 8 + (threadIdx.x >> 5);
    if (row >= J.n[s]) return;
    int lane = threadIdx.x & 31;
    const float* xf = J.xf[s];
    const int* col = J.col[s];
    int lds = J.lds[s], soff = J.soff[s];
    int beg = J.rowp[s][row], end = J.rowp[s][row + 1];
    float acc[V];
#pragma unroll
    for (int j = 0; j < V; j++) acc[j] = 0.0f;
    int e = beg;
    for (; e + 7 < end; e += 8) {
        int si[8];
#pragma unroll
        for (int u = 0; u < 8; u++) si[u] = __ldg(&col[e + u]);
        if (V == 4) {
            float4 vv[8];
#pragma unroll
            for (int u = 0; u < 8; u++)
                vv[u] = *(const float4*)(xf + (size_t)si[u] * lds + soff + lane * V);
#pragma unroll
            for (int u = 0; u < 8; u++) {
                acc[0] += vv[u].x; acc[1] += vv[u].y;
                acc[2] += vv[u].z; acc[3] += vv[u].w;
            }
        } else {
            float2 vv[8];
#pragma unroll
            for (int u = 0; u < 8; u++)
                vv[u] = *(const float2*)(xf + (size_t)si[u] * lds + soff + lane * V);
#pragma unroll
            for (int u = 0; u < 8; u++) {
                acc[0] += vv[u].x; acc[1] += vv[u].y;
            }
        }
    }
    {
        int rem = end - e;   // 0..7
        if (rem > 0) {
            if (V == 4) {
                float4 vv[7];
#pragma unroll
                for (int u = 0; u < 7; u++) {
                    if (u < rem) {
                        int s0 = __ldg(&col[e + u]);
                        vv[u] = *(const float4*)(xf + (size_t)s0 * lds + soff + lane * V);
                    } else {
                        vv[u] = make_float4(0.f, 0.f, 0.f, 0.f);
                    }
                }
#pragma unroll
                for (int u = 0; u < 7; u++) {
                    acc[0] += vv[u].x; acc[1] += vv[u].y;
                    acc[2] += vv[u].z; acc[3] += vv[u].w;
                }
            } else {
                float2 vv[7];
#pragma unroll
                for (int u = 0; u < 7; u++) {
                    if (u < rem) {
                        int s0 = __ldg(&col[e + u]);
                        vv[u] = *(const float2*)(xf + (size_t)s0 * lds + soff + lane * V);
                    } else {
                        vv[u] = make_float2(0.f, 0.f);
                    }
                }
#pragma unroll
                for (int u = 0; u < 7; u++) {
                    acc[0] += vv[u].x; acc[1] += vv[u].y;
                }
            }
        }
    }
    float inv = J.invc[s][row];
    float* q = J.agg[s] + (size_t)row * J.ldd[s] + J.doff[s] + lane * V;
    if (V == 4) {
        *(float4*)q = make_float4(acc[0] * inv, acc[1] * inv, acc[2] * inv, acc[3] * inv);
    } else {
        *(float2*)q = make_float2(acc[0] * inv, acc[1] * inv);
    }
}

// ================= cp.async helpers =========================================
__device__ __forceinline__ void cp16(uint32_t dst, const void* src) {
    asm volatile("cp.async.ca.shared.global [%0], [%1], 16;" :: "r"(dst), "l"(src));
}
__device__ __forceinline__ void cp_commit() {
    asm volatile("cp.async.commit_group;");
}
__device__ __forceinline__ void cp_wait0() {
    asm volatile("cp.async.wait_group 0;" ::: "memory");
}

__device__ __forceinline__ void bsplit(float x, __nv_bfloat16& h, __nv_bfloat16& l) {
    h = __float2bfloat16_rn(x);
    l = __float2bfloat16_rn(x - __bfloat162float(h));
}

// ================= wmma bf16 split GEMM (job table, cp.async B) =============
// EPI: 0 plain, 1 relu, 3 relu+LN fused (Nfull==128),
//      4 relu+BN -> h@W2+b2 -> Cout (fused MLP).
struct TGJob {
    const float* A1[5];
    const float* A2[5];
    const __nv_bfloat16* Bhi[5];
    const __nv_bfloat16* Blo[5];
    const float* bias[5];
    float* C[5];
    int lda1[5], K1[5], lda2[5], K2[5], ldK[5], ldc[5], coff[5], M[5], Nfull[5];
    float alpha[5];
    float invr[5];
    // EPI=4 extras (slot 0 only)
    const __nv_bfloat16* W2h;
    const __nv_bfloat16* W2l;
    const float* b2;
    float* Cout;
};
#define TG_DSM 81920
template <int EPI>
__global__ __launch_bounds__(256, 2) void tgemm_k(
    TGJob J, const float* __restrict__ bnS, const float* __restrict__ bnB)
{
    extern __shared__ char dynsmem[];
    __nv_bfloat16* Asm = reinterpret_cast<__nv_bfloat16*>(dynsmem);
    __nv_bfloat16* Bsm = reinterpret_cast<__nv_bfloat16*>(dynsmem + 40960);
    uint32_t Bu32 = (uint32_t)__cvta_generic_to_shared(Bsm);

    int z = blockIdx.z;
    const float* A1 = J.A1[z];
    const float* A2 = J.A2[z];
    const __nv_bfloat16* Bhi = J.Bhi[z];
    const __nv_bfloat16* Blo = J.Blo[z];
    const float* bias = J.bias[z];
    float* C = J.C[z];
    int lda1 = J.lda1[z], K1 = J.K1[z], lda2 = J.lda2[z], K2 = J.K2[z];
    int ldK = J.ldK[z], ldc = J.ldc[z], coff = J.coff[z];
    int M = J.M[z], Nfull = J.Nfull[z];
    float alpha = J.alpha[z];

    int m0 = blockIdx.x * 128;
    int n0 = blockIdx.y * 128;
    if (m0 >= M || n0 >= Nfull) return;

    int tid = threadIdx.x;
    int wid = tid >> 5, lane = tid & 31;
    int wm = wid >> 2, wn = wid & 3;
    int mw = m0 + wm * 64;
    int nw = n0 + wn * 32;
    int nl = wn * 32;
    bool active = (nw < Nfull);
    int K = K1 + K2;
    int nkt = K >> 5;

    wmma::fragment<wmma::accumulator, 16, 16, 16, float> acc[4][2];
#pragma unroll
    for (int i = 0; i < 4; i++)
#pragma unroll
        for (int j = 0; j < 2; j++) wmma::fill_fragment(acc[i][j], 0.0f);

    int row = tid >> 1, half = tid & 1;
    int m = m0 + row;
    bool mok = (m < M);
    int brow = row, bhalf = half;

    // ---- prologue ----
    float4 v[4];
    {
        const float* Ap; int ld, kl;
        if (0 < K1) { Ap = A1; ld = lda1; kl = 0; }
        else        { Ap = A2; ld = lda2; kl = -K1; }
        const float* src = Ap + (size_t)m * ld + kl + half * 16;
#pragma unroll
        for (int i = 0; i < 4; i++)
            v[i] = mok ? *(const float4*)(src + i * 4) : make_float4(0.f, 0.f, 0.f, 0.f);
    }
    {
        const __nv_bfloat16* sH = Bhi + (size_t)(n0 + brow) * ldK + bhalf * 16;
        const __nv_bfloat16* sL = Blo + (size_t)(n0 + brow) * ldK + bhalf * 16;
        uint32_t dH = Bu32 + (uint32_t)(((0 * 2 + 0) * 128 + brow) * 40 + bhalf * 16) * 2;
        uint32_t dL = Bu32 + (uint32_t)(((0 * 2 + 1) * 128 + brow) * 40 + bhalf * 16) * 2;
        cp16(dH, sH); cp16(dH + 16, sH + 8);
        cp16(dL, sL); cp16(dL + 16, sL + 8);
        cp_commit();
    }

    int buf = 0;
    for (int kt = 0; kt < nkt; kt++) {
        {
            __nv_bfloat162* ah = reinterpret_cast<__nv_bfloat162*>(
                Asm + ((buf * 2 + 0) * 128 + row) * 40);
            __nv_bfloat162* al = reinterpret_cast<__nv_bfloat162*>(
                Asm + ((buf * 2 + 1) * 128 + row) * 40);
#pragma unroll
            for (int i = 0; i < 4; i++) {
                int col = half * 16 + i * 4;
                float4 x = v[i];
                __nv_bfloat16 hx = __float2bfloat16_rn(x.x);
                __nv_bfloat16 hy = __float2bfloat16_rn(x.y);
                __nv_bfloat16 hz = __float2bfloat16_rn(x.z);
                __nv_bfloat16 hw = __float2bfloat16_rn(x.w);
                __nv_bfloat162 h01; h01.x = hx; h01.y = hy;
                __nv_bfloat162 h23; h23.x = hz; h23.y = hw;
                ah[(col >> 1) + 0] = h01;
                ah[(col >> 1) + 1] = h23;
                __nv_bfloat162 l01, l23;
                l01.x = __float2bfloat16_rn(x.x - __bfloat162float(hx));
                l01.y = __float2bfloat16_rn(x.y - __bfloat162float(hy));
                l23.x = __float2bfloat16_rn(x.z - __bfloat162float(hz));
                l23.y = __float2bfloat16_rn(x.w - __bfloat162float(hw));
                al[(col >> 1) + 0] = l01;
                al[(col >> 1) + 1] = l23;
            }
        }
        cp_wait0();
        __syncthreads();
        if (kt + 1 < nkt) {
            int k0n = (kt + 1) << 5;
            const __nv_bfloat16* sH = Bhi + (size_t)(n0 + brow) * ldK + k0n + bhalf * 16;
            const __nv_bfloat16* sL = Blo + (size_t)(n0 + brow) * ldK + k0n + bhalf * 16;
            int ob = buf ^ 1;
            uint32_t dH = Bu32 + (uint32_t)(((ob * 2 + 0) * 128 + brow) * 40 + bhalf * 16) * 2;
            uint32_t dL = Bu32 + (uint32_t)(((ob * 2 + 1) * 128 + brow) * 40 + bhalf * 16) * 2;
            cp16(dH, sH); cp16(dH + 16, sH + 8);
            cp16(dL, sL); cp16(dL + 16, sL + 8);
            cp_commit();
            const float* Ap; int ld, kl;
            if (k0n < K1) { Ap = A1; ld = lda1; kl = k0n; }
            else          { Ap = A2; ld = lda2; kl = k0n - K1; }
            const float* src = Ap + (size_t)m * ld + kl + half * 16;
#pragma unroll
            for (int i = 0; i < 4; i++)
                v[i] = mok ? *(const float4*)(src + i * 4) : make_float4(0.f, 0.f, 0.f, 0.f);
        }
        if (active) {
            const __nv_bfloat16* BsH = Bsm + (buf * 2 + 0) * 128 * 40;
            const __nv_bfloat16* BsL = Bsm + (buf * 2 + 1) * 128 * 40;
#pragma unroll
            for (int kk = 0; kk < 32; kk += 16) {
                wmma::fragment<wmma::matrix_b, 16, 16, 16, __nv_bfloat16, wmma::col_major> bh[2], bl2[2];
#pragma unroll
                for (int j = 0; j < 2; j++) {
                    wmma::load_matrix_sync(bh[j],  BsH + (nl + j * 16) * 40 + kk, 40u);
                    wmma::load_matrix_sync(bl2[j], BsL + (nl + j * 16) * 40 + kk, 40u);
                }
#pragma unroll
                for (int i = 0; i < 4; i++) {
                    wmma::fragment<wmma::matrix_a, 16, 16, 16, __nv_bfloat16, wmma::row_major> ah, al;
                    wmma::load_matrix_sync(ah, Asm + ((buf * 2 + 0) * 128 + wm * 64 + i * 16) * 40 + kk, 40u);
                    wmma::load_matrix_sync(al, Asm + ((buf * 2 + 1) * 128 + wm * 64 + i * 16) * 40 + kk, 40u);
#pragma unroll
                    for (int j = 0; j < 2; j++) {
                        wmma::mma_sync(acc[i][j], ah, bh[j],  acc[i][j]);
                        wmma::mma_sync(acc[i][j], ah, bl2[j], acc[i][j]);
                        wmma::mma_sync(acc[i][j], al, bh[j],  acc[i][j]);
                    }
                }
            }
        }
        buf ^= 1;
    }
    __syncthreads();

    if (EPI == 3) {
        float* obuf = reinterpret_cast<float*>(dynsmem);   // 128 x 132 f32
#pragma unroll
        for (int i = 0; i < 4; i++)
#pragma unroll
            for (int j = 0; j < 2; j++)
                wmma::store_matrix_sync(obuf + (wm * 64 + i * 16) * 132 + nl + j * 16,
                                        acc[i][j], 132u, wmma::mem_row_major);
        __syncthreads();
        float invr = J.invr[z];
        int r0 = wid * 16;
        for (int rr = 0; rr < 16; rr++) {
            int rloc = r0 + rr;
            int mm = m0 + rloc;
            if (mm >= M) continue;
            float vv[4]; float s = 0.f;
#pragma unroll
            for (int j = 0; j < 4; j++) {
                int c = lane + 32 * j;
                float val = obuf[rloc * 132 + c] * alpha + bias[c];
                vv[j] = fmaxf(val * invr, 0.f);
                s += vv[j];
            }
#pragma unroll
            for (int o = 16; o; o >>= 1) s += __shfl_xor_sync(0xffffffffu, s, o);
            float mean = s * (1.0f / 128.0f);
            float ss = 0.f;
#pragma unroll
            for (int j = 0; j < 4; j++) { float d = vv[j] - mean; ss += d * d; }
#pragma unroll
            for (int o = 16; o; o >>= 1) ss += __shfl_xor_sync(0xffffffffu, ss, o);
            float inv = rsqrtf(ss * (1.0f / 128.0f) + 1e-5f);
            float* q = C + (size_t)mm * ldc;
#pragma unroll
            for (int j = 0; j < 4; j++) {
                int c = lane + 32 * j;
                q[c] = (vv[j] - mean) * inv * bnS[c] + bnB[c];
            }
        }
    } else if (EPI == 4) {
        __nv_bfloat16* hHb = reinterpret_cast<__nv_bfloat16*>(dynsmem);
        __nv_bfloat16* hLb = hHb + 128 * 136;
        float* myp = reinterpret_cast<float*>(dynsmem + 69632) + wid * 320;
        int base = lane * 8;
        int pr = base >> 4, pc = base & 15;
#pragma unroll
        for (int i = 0; i < 4; i++) {
#pragma unroll
            for (int j = 0; j < 2; j++) {
                wmma::store_matrix_sync(myp, acc[i][j], 20u, wmma::mem_row_major);
                __syncwarp();
                int rloc = wm * 64 + i * 16 + pr;
                int nb = nl + j * 16;
                bool rok = (m0 + rloc < M);
#pragma unroll
                for (int t = 0; t < 8; t++) {
                    int n = nb + pc + t;
                    float val = rok ? (myp[pr * 20 + pc + t] * alpha + bias[n]) : 0.f;
                    val = fmaxf(val, 0.f) * bnS[n] + bnB[n];
                    __nv_bfloat16 hh, ll;
                    bsplit(val, hh, ll);
                    hHb[rloc * 136 + n] = hh;
                    hLb[rloc * 136 + n] = ll;
                }
                __syncwarp();
            }
        }
        __syncthreads();
        wmma::fragment<wmma::accumulator, 16, 16, 16, float> acc2[2];
#pragma unroll
        for (int j = 0; j < 2; j++) wmma::fill_fragment(acc2[j], 0.0f);
        const __nv_bfloat16* W2h = J.W2h;
        const __nv_bfloat16* W2l = J.W2l;
        int r0 = wid * 16;
#pragma unroll
        for (int kf = 0; kf < 8; kf++) {
            wmma::fragment<wmma::matrix_a, 16, 16, 16, __nv_bfloat16, wmma::row_major> ah, al;
            wmma::load_matrix_sync(ah, hHb + r0 * 136 + kf * 16, 136u);
            wmma::load_matrix_sync(al, hLb + r0 * 136 + kf * 16, 136u);
#pragma unroll
            for (int j = 0; j < 2; j++) {
                wmma::fragment<wmma::matrix_b, 16, 16, 16, __nv_bfloat16, wmma::col_major> bh, bl2;
                wmma::load_matrix_sync(bh,  W2h + (size_t)(j * 16) * 128 + kf * 16, 128u);
                wmma::load_matrix_sync(bl2, W2l + (size_t)(j * 16) * 128 + kf * 16, 128u);
                wmma::mma_sync(acc2[j], ah, bh,  acc2[j]);
                wmma::mma_sync(acc2[j], ah, bl2, acc2[j]);
                wmma::mma_sync(acc2[j], al, bh,  acc2[j]);
            }
        }
        const float* b2 = J.b2;
        float* Cout = J.Cout;
#pragma unroll
        for (int j = 0; j < 2; j++) {
            wmma::store_matrix_sync(myp, acc2[j], 20u, wmma::mem_row_major);
            __syncwarp();
            int mm = m0 + r0 + pr;
            if (mm < M) {
                float out[8];
#pragma unroll
                for (int t = 0; t < 8; t++) {
                    int n = j * 16 + pc + t;
                    out[t] = myp[pr * 20 + pc + t] + b2[n];
                }
                float* dst = Cout + (size_t)mm * 32 + j * 16 + pc;
                *(float4*)dst = *(float4*)&out[0];
                *(float4*)(dst + 4) = *(float4*)&out[4];
            }
            __syncwarp();
        }
    } else if (active) {
        float* myp = reinterpret_cast<float*>(dynsmem) + wid * 320;
        int base = lane * 8;
        int pr = base >> 4, pc = base & 15;
#pragma unroll
        for (int i = 0; i < 4; i++) {
#pragma unroll
            for (int j = 0; j < 2; j++) {
                wmma::store_matrix_sync(myp, acc[i][j], 20u, wmma::mem_row_major);
                __syncwarp();
                int mb = mw + i * 16, nb = nw + j * 16;
                if (mb + pr < M) {
                    float out[8];
#pragma unroll
                    for (int t = 0; t < 8; t++) {
                        int n = nb + pc + t;
                        float val = myp[pr * 20 + pc + t] * alpha + bias[n];
                        if (EPI >= 1) val = fmaxf(val, 0.0f);
                        out[t] = val;
                    }
                    float* dst = C + (size_t)(mb + pr) * ldc + coff + nb + pc;
                    *(float4*)dst = *(float4*)&out[0];
                    *(float4*)(dst + 4) = *(float4*)&out[4];
                }
                __syncwarp();
            }
        }
    }
}

// ================= merged elementwise: layer-0 post ==========================
__global__ void l0post2_k(const float* __restrict__ On, const float* __restrict__ Ob,
                          const float* __restrict__ gg, const float* __restrict__ bb,
                          float* __restrict__ xn, float* __restrict__ xb, int nblkN) {
    int b = blockIdx.x;
    const float* O; float* xout; int ldo, M, R;
    if (b < nblkN) { O = On; xout = xn; ldo = 384; M = NN; R = 3; }
    else           { O = Ob; xout = xb; ldo = 256; M = NB; R = 2; b -= nblkN; }
    int row = b * 8 + (threadIdx.x >> 5);
    if (row >= M) return;
    int lane = threadIdx.x & 31;
    float acc[4] = {0.f, 0.f, 0.f, 0.f};
    for (int rb = 0; rb < R; rb++) {
        const float* p = O + (size_t)row * ldo + rb * 128;
        float v[4]; float ss = 0.f;
#pragma unroll
        for (int j = 0; j < 4; j++) { v[j] = p[lane + 32 * j]; ss += v[j] * v[j]; }
#pragma unroll
        for (int s = 16; s; s >>= 1) ss += __shfl_xor_sync(0xffffffffu, ss, s);
        float inv = 1.0f / fmaxf(sqrtf(ss), 1e-12f);
#pragma unroll
        for (int j = 0; j < 4; j++) acc[j] += v[j] * inv;
    }
    const float invR = 1.0f / R;
    float s = 0.f;
#pragma unroll
    for (int j = 0; j < 4; j++) { acc[j] = fmaxf(acc[j] * invR, 0.f); s += acc[j]; }
#pragma unroll
    for (int o = 16; o; o >>= 1) s += __shfl_xor_sync(0xffffffffu, s, o);
    float m = s * (1.0f / 128.0f);
    float ss = 0.f;
#pragma unroll
    for (int j = 0; j < 4; j++) { float d = acc[j] - m; ss += d * d; }
#pragma unroll
    for (int o = 16; o; o >>= 1) ss += __shfl_xor_sync(0xffffffffu, ss, o);
    float inv = rsqrtf(ss * (1.0f / 128.0f) + 1e-5f);
    float* q = xout + (size_t)row * 128;
#pragma unroll
    for (int j = 0; j < 4; j++) {
        int c = lane + 32 * j;
        q[c] = (acc[j] - m) * inv * gg[c] + bb[c];
    }
}

// ================= fused weight-prep kernel (weights + biases only) =========
__device__ __forceinline__ void lsplit_body(__nv_bfloat16* hi, __nv_bfloat16* lo,
                                            const float* WlL, const float* WrL,
                                            int r0, int r1, int r2, int nrel, int idx) {
    int K = nrel * 128 + 128;
    int n = idx / K, k = idx - n * K;
    float x;
    if (k < nrel * 128) {
        int j = k >> 7, kk = k & 127;
        int r = (j == 0) ? r0 : (j == 1) ? r1 : r2;
        x = WlL[(size_t)r * 16384 + kk * 128 + n];
    } else {
        int kk = k - nrel * 128;
        x = WrL[(size_t)r0 * 16384 + kk * 128 + n] + WrL[(size_t)r1 * 16384 + kk * 128 + n];
        if (nrel == 3) x += WrL[(size_t)r2 * 16384 + kk * 128 + n];
    }
    __nv_bfloat16 h, l;
    bsplit(x, h, l);
    hi[idx] = h;
    lo[idx] = l;
}
#define PREP_TOTAL 304576
__global__ void prep_k(const float* __restrict__ proj_W, const float* __restrict__ proj_b,
                       const float* __restrict__ l0_Wl, const float* __restrict__ l0_bl,
                       const float* __restrict__ l0_Wr,
                       const float* __restrict__ Wl, const float* __restrict__ bl,
                       const float* __restrict__ Wr,
                       const float* __restrict__ mlp_W1, const float* __restrict__ mlp_W2,
                       const float* __restrict__ bn_g) {
    int idx = blockIdx.x * 256 + threadIdx.x;
    __nv_bfloat16 h, l;
    if (idx < 12288) {
        int j = idx >> 12, rem = idx & 4095;
        int k = rem >> 6, c = rem & 63;
        float x = proj_W[(size_t)j * 4096 + k * 64 + c];
        int n = j * 64 + c;
        bsplit(x, h, l);
        g_BtProjN[0][n * 64 + k] = h; g_BtProjN[1][n * 64 + k] = l;
        return;
    }
    idx -= 12288;
    if (idx < 8192) {
        int j = idx >> 12, rem = idx & 4095;
        int k = rem >> 6, c = rem & 63;
        int r = (j == 0) ? 3 : 4;
        float x = proj_W[(size_t)r * 4096 + k * 64 + c];
        int n = j * 64 + c;
        bsplit(x, h, l);
        g_BtProjB[0][n * 64 + k] = h; g_BtProjB[1][n * 64 + k] = l;
        return;
    }
    idx -= 8192;
    if (idx < 81920) {
        int s = idx >> 14, rem = idx & 16383;
        int n = rem >> 7, k = rem & 127;
        const int rels[5] = {0, 1, 3, 2, 4};
        int r = rels[s];
        float x = (k < 64) ? l0_Wr[(size_t)r * 8192 + k * 128 + n]
                           : l0_Wl[(size_t)r * 8192 + (k - 64) * 128 + n];
        bsplit(x, h, l);
        g_BtL0[0][s][rem] = h; g_BtL0[1][s][rem] = l;
        return;
    }
    idx -= 81920;
    if (idx < 65536) { lsplit_body(g_BtL1N[0], g_BtL1N[1], Wl, Wr, 0, 1, 3, 3, idx); return; }
    idx -= 65536;
    if (idx < 49152) { lsplit_body(g_BtL1B[0], g_BtL1B[1], Wl, Wr, 2, 4, 0, 2, idx); return; }
    idx -= 49152;
    if (idx < 65536) { lsplit_body(g_BtL2N[0], g_BtL2N[1], Wl + 5 * 16384, Wr + 5 * 16384, 0, 1, 3, 3, idx); return; }
    idx -= 65536;
    if (idx < 16384) {
        int k = idx >> 7, n = idx & 127;
        bsplit(mlp_W1[idx], h, l);
        g_BtM1[0][n * 128 + k] = h; g_BtM1[1][n * 128 + k] = l;
        return;
    }
    idx -= 16384;
    if (idx < 4096) {
        int k = idx / 32, n = idx - (idx / 32) * 32;
        bsplit(mlp_W2[idx], h, l);
        g_BtM2[0][n * 128 + k] = h; g_BtM2[1][n * 128 + k] = l;
        return;
    }
    idx -= 4096;
    if (idx < 1472) {
        int t = idx;
        if (t < 192) {
            int j = t / 64;
            g_pbCatN[t] = proj_b[(size_t)j * 64 + (t - j * 64)];
        } else if (t < 320) {
            int local = t - 192; int j = local / 64;
            int r = (j == 0) ? 3 : 4;
            g_pbCatB[local] = proj_b[(size_t)r * 64 + (local - j * 64)];
        } else if (t < 704) {
            int local = t - 320; int j = local / 128;
            int r = (j == 0) ? 0 : (j == 1) ? 1 : 3;
            g_l0blCatN[local] = l0_bl[(size_t)r * 128 + (local - j * 128)];
        } else if (t < 960) {
            int local = t - 704; int j = local / 128;
            int r = (j == 0) ? 2 : 4;
            g_l0blCatB[local] = l0_bl[(size_t)r * 128 + (local - j * 128)];
        } else if (t < 1088) {
            int i = t - 960;
            g_b1SumN[i] = bl[i] + bl[128 + i] + bl[3 * 128 + i];
        } else if (t < 1216) {
            int i = t - 1088;
            g_b1SumB[i] = bl[2 * 128 + i] + bl[4 * 128 + i];
        } else if (t < 1344) {
            int i = t - 1216;
            g_b2SumN[i] = bl[(5 + 0) * 128 + i] + bl[(5 + 1) * 128 + i] + bl[(5 + 3) * 128 + i];
        } else {
            int i = t - 1344;
            g_bnS[i] = bn_g[i] * rsqrtf(1.0f + 1e-5f);
        }
    }
}

// ================= host dispatch =============================================
static void tgemmJ(int epi, const TGJob& J, int nslots, const float* p0, const float* p1) {
    int maxM = 0, maxN = 0;
    for (int s = 0; s < nslots; s++) {
        if (J.M[s] > maxM) maxM = J.M[s];
        if (J.Nfull[s] > maxN) maxN = J.Nfull[s];
    }
    dim3 g((maxM + 127) / 128, (maxN + 127) / 128, nslots);
    if (epi == 0) {
        cudaFuncSetAttribute(tgemm_k<0>, cudaFuncAttributeMaxDynamicSharedMemorySize, TG_DSM);
        tgemm_k<0><<<g, 256, TG_DSM>>>(J, p0, p1);
    } else if (epi == 1) {
        cudaFuncSetAttribute(tgemm_k<1>, cudaFuncAttributeMaxDynamicSharedMemorySize, TG_DSM);
        tgemm_k<1><<<g, 256, TG_DSM>>>(J, p0, p1);
    } else if (epi == 3) {
        cudaFuncSetAttribute(tgemm_k<3>, cudaFuncAttributeMaxDynamicSharedMemorySize, TG_DSM);
        tgemm_k<3><<<g, 256, TG_DSM>>>(J, p0, p1);
    } else {
        cudaFuncSetAttribute(tgemm_k<4>, cudaFuncAttributeMaxDynamicSharedMemorySize, TG_DSM);
        tgemm_k<4><<<g, 256, TG_DSM>>>(J, p0, p1);
    }
}
static void setslot(TGJob& J, int s, const float* A1, int lda1, int K1,
                    const float* A2, int lda2, int K2,
                    const __nv_bfloat16* Bh, const __nv_bfloat16* Bl, int ldK,
                    const float* bias, float* C, int ldc, int coff,
                    int M, int Nfull, float alpha, float invr = 1.0f) {
    J.A1[s] = A1; J.lda1[s] = lda1; J.K1[s] = K1;
    J.A2[s] = A2; J.lda2[s] = lda2; J.K2[s] = K2;
    J.Bhi[s] = Bh; J.Blo[s] = Bl; J.ldK[s] = ldK;
    J.bias[s] = bias; J.C[s] = C; J.ldc[s] = ldc; J.coff[s] = coff;
    J.M[s] = M; J.Nfull[s] = Nfull; J.alpha[s] = alpha; J.invr[s] = invr;
}

extern "C" void kernel_launch(void* const* d_in, const int* in_sizes, int n_in,
                              void* d_out, int out_size) {
    const float* x_note = (const float*)d_in[0];
    const float* x_beat = (const float*)d_in[1];
    const int* e[5] = {(const int*)d_in[2], (const int*)d_in[3], (const int*)d_in[4],
                       (const int*)d_in[5], (const int*)d_in[6]};
    int E[5];
    for (int r = 0; r < 5; r++) E[r] = in_sizes[2 + r] / 2;
    const float* proj_W = (const float*)d_in[7];
    const float* proj_b = (const float*)d_in[8];
    const float* l0_Wl  = (const float*)d_in[9];
    const float* l0_bl  = (const float*)d_in[10];
    const float* l0_Wr  = (const float*)d_in[11];
    const float* Wl     = (const float*)d_in[12];
    const float* bl     = (const float*)d_in[13];
    const float* Wr     = (const float*)d_in[14];
    const float* ln_g   = (const float*)d_in[15];
    const float* ln_b   = (const float*)d_in[16];
    const float* mlp_W1 = (const float*)d_in[17];
    const float* mlp_b1 = (const float*)d_in[18];
    const float* bn_g   = (const float*)d_in[19];
    const float* bn_b   = (const float*)d_in[20];
    const float* mlp_W2 = (const float*)d_in[21];
    const float* mlp_b2 = (const float*)d_in[22];

    // side stream + fork/join events (created once; captured work identical
    // on every call — no device memory is allocated by these objects)
    static cudaStream_t s2 = nullptr;
    static cudaEvent_t evF = nullptr, evJ = nullptr;
    if (s2 == nullptr) {
        cudaStreamCreateWithFlags(&s2, cudaStreamNonBlocking);
        cudaEventCreateWithFlags(&evF, cudaEventDisableTiming);
        cudaEventCreateWithFlags(&evJ, cudaEventDisableTiming);
    }

    float *pn, *pb, *aggn, *aggb, *On, *Ob, *xn0, *xn1, *xb0, *xb1, *outn, *cntf;
    int *rowp, *colx;
    cudaGetSymbolAddress((void**)&pn, g_pn);       cudaGetSymbolAddress((void**)&pb, g_pb);
    cudaGetSymbolAddress((void**)&aggn, g_aggn);   cudaGetSymbolAddress((void**)&aggb, g_aggb);
    cudaGetSymbolAddress((void**)&On, g_On);       cudaGetSymbolAddress((void**)&Ob, g_Ob);
    cudaGetSymbolAddress((void**)&xn0, g_xn0);     cudaGetSymbolAddress((void**)&xn1, g_xn1);
    cudaGetSymbolAddress((void**)&xb0, g_xb0);     cudaGetSymbolAddress((void**)&xb1, g_xb1);
    cudaGetSymbolAddress((void**)&outn, g_outn);
    cudaGetSymbolAddress((void**)&cntf, g_cnt);
    cudaGetSymbolAddress((void**)&rowp, g_rowp);   cudaGetSymbolAddress((void**)&colx, g_col);

    float *pbCatN, *pbCatB, *l0blCatN, *l0blCatB, *b1SumN, *b1SumB, *b2SumN, *bnS;
    cudaGetSymbolAddress((void**)&pbCatN, g_pbCatN);     cudaGetSymbolAddress((void**)&pbCatB, g_pbCatB);
    cudaGetSymbolAddress((void**)&l0blCatN, g_l0blCatN); cudaGetSymbolAddress((void**)&l0blCatB, g_l0blCatB);
    cudaGetSymbolAddress((void**)&b1SumN, g_b1SumN);     cudaGetSymbolAddress((void**)&b1SumB, g_b1SumB);
    cudaGetSymbolAddress((void**)&b2SumN, g_b2SumN);     cudaGetSymbolAddress((void**)&bnS, g_bnS);

    __nv_bfloat16 *BtProjN[2], *BtProjB[2], *BtL0[2], *BtL1N[2], *BtL1B[2], *BtL2N[2], *BtM1[2], *BtM2[2];
    {
        __nv_bfloat16* p;
        cudaGetSymbolAddress((void**)&p, g_BtProjN); BtProjN[0] = p; BtProjN[1] = p + 256 * 64;
        cudaGetSymbolAddress((void**)&p, g_BtProjB); BtProjB[0] = p; BtProjB[1] = p + 128 * 64;
        cudaGetSymbolAddress((void**)&p, g_BtL0);    BtL0[0] = p;    BtL0[1] = p + 5 * 128 * 128;
        cudaGetSymbolAddress((void**)&p, g_BtL1N);   BtL1N[0] = p;   BtL1N[1] = p + 128 * 512;
        cudaGetSymbolAddress((void**)&p, g_BtL1B);   BtL1B[0] = p;   BtL1B[1] = p + 128 * 384;
        cudaGetSymbolAddress((void**)&p, g_BtL2N);   BtL2N[0] = p;   BtL2N[1] = p + 128 * 512;
        cudaGetSymbolAddress((void**)&p, g_BtM1);    BtM1[0] = p;    BtM1[1] = p + 128 * 128;
        cudaGetSymbolAddress((void**)&p, g_BtM2);    BtM2[0] = p;    BtM2[1] = p + 128 * 128;
    }

    int ebase[5];
    { int acc = 0; for (int r = 0; r < 5; r++) { ebase[r] = acc; acc += E[r]; } }
    int maxE = 0;
    for (int r = 0; r < 5; r++) maxE = (E[r] > maxE) ? E[r] : maxE;

    // ==== fork: CSR build on s2, weight prep + layer-0 proj GEMM on default ==
    cudaEventRecord(evF, 0);
    cudaStreamWaitEvent(s2, evF, 0);

    // ---- s2: CSR build chain (independent of weights) ----
    init_k<<<(5 * NN + 255) / 256, 256, 0, s2>>>(e[0]);
    counti5_k<<<dim3((maxE + 255) / 256, 5), 256, 0, s2>>>(e[0], e[1], e[2], e[3], e[4],
                                                           E[0], E[1], E[2], E[3], E[4]);
    scan1_k<<<dim3(NBX, 5), 256, 0, s2>>>();
    scan3_k<<<dim3(NBX, 5), 256, 0, s2>>>();
    fill5_k<<<dim3((maxE + 255) / 256, 5), 256, 0, s2>>>(e[0], e[1], e[2], e[3], e[4],
                                                         E[0], E[1], E[2], E[3], E[4],
                                                         ebase[0], ebase[1], ebase[2], ebase[3], ebase[4]);
    cudaEventRecord(evJ, s2);

    // ---- default: prep + layer-0 projections (need only weights) ----
    prep_k<<<(PREP_TOTAL + 255) / 256, 256>>>(proj_W, proj_b, l0_Wl, l0_bl, l0_Wr,
                                              Wl, bl, Wr, mlp_W1, mlp_W2, bn_g);
    const int NBLK_N = (NN + 7) / 8;
    const int NBLK_B = (NB + 7) / 8;
    {
        TGJob G;
        setslot(G, 0, x_note, 64, 64, nullptr, 0, 0, BtProjN[0], BtProjN[1], 64,
                pbCatN, pn, 192, 0, NN, 192, 1.f);
        setslot(G, 1, x_beat, 64, 64, nullptr, 0, 0, BtProjB[0], BtProjB[1], 64,
                pbCatB, pb, 128, 0, NB, 128, 1.f);
        tgemmJ(1, G, 2, nullptr, nullptr);
    }

    // ==== join: everything below needs both CSR and projections ====
    cudaStreamWaitEvent(0, evJ, 0);

    const int* rp[5]; const int* cx[5]; const float* ic[5];
    for (int r = 0; r < 5; r++) {
        rp[r] = rowp + r * (NN + 1);
        cx[r] = colx + ebase[r];
        ic[r] = cntf + r * NN;
    }

    auto mkjob = [&](Agg5& J, int s, const float* xf, int lds, int soff, int rel,
                     float* agg, int ldd, int doff, int n) {
        J.xf[s] = xf; J.lds[s] = lds; J.soff[s] = soff;
        J.rowp[s] = rp[rel]; J.col[s] = cx[rel]; J.invc[s] = ic[rel];
        J.agg[s] = agg; J.ldd[s] = ldd; J.doff[s] = doff; J.n[s] = n;
    };

    // ==================== layer 0 (agg + o-GEMM + post) ====================
    {
        Agg5 J; J.nslots = 5;
        mkjob(J, 0, pn, 192, 0,   0, aggn, 192, 0,   NN);
        mkjob(J, 1, pn, 192, 64,  1, aggn, 192, 64,  NN);
        mkjob(J, 2, pb, 128, 0,   3, aggn, 192, 128, NN);
        mkjob(J, 3, pn, 192, 128, 2, aggb, 128, 0,   NB);
        mkjob(J, 4, pb, 128, 64,  4, aggb, 128, 64,  NB);
        J.boff[0] = 0; J.boff[1] = NBLK_N; J.boff[2] = 2 * NBLK_N; J.boff[3] = 3 * NBLK_N;
        J.boff[4] = 3 * NBLK_N + NBLK_B; J.boff[5] = 3 * NBLK_N + 2 * NBLK_B;
        aggmulti_k<2><<<J.boff[5], 256>>>(J);
    }
    {
        TGJob G;
        for (int j = 0; j < 3; j++)
            setslot(G, j, x_note, 64, 64, aggn + j * 64, 192, 64,
                    BtL0[0] + j * 16384, BtL0[1] + j * 16384, 128,
                    l0blCatN + j * 128, On, 384, j * 128, NN, 128, 1.f);
        for (int j = 0; j < 2; j++)
            setslot(G, 3 + j, x_beat, 64, 64, aggb + j * 64, 128, 64,
                    BtL0[0] + (3 + j) * 16384, BtL0[1] + (3 + j) * 16384, 128,
                    l0blCatB + j * 128, Ob, 256, j * 128, NB, 128, 1.f);
        tgemmJ(0, G, 5, nullptr, nullptr);
    }
    l0post2_k<<<NBLK_N + NBLK_B, 256>>>(On, Ob, ln_g, ln_b, xn0, xb0, NBLK_N);

    // ==================== layer 1 (GEMM with fused relu+LN epilogue) =========
    {
        Agg5 J; J.nslots = 5;
        mkjob(J, 0, xn0, 128, 0, 0, aggn, 384, 0,   NN);
        mkjob(J, 1, xn0, 128, 0, 1, aggn, 384, 128, NN);
        mkjob(J, 2, xb0, 128, 0, 3, aggn, 384, 256, NN);
        mkjob(J, 3, xn0, 128, 0, 2, aggb, 256, 0,   NB);
        mkjob(J, 4, xb0, 128, 0, 4, aggb, 256, 128, NB);
        J.boff[0] = 0; J.boff[1] = NBLK_N; J.boff[2] = 2 * NBLK_N; J.boff[3] = 3 * NBLK_N;
        J.boff[4] = 3 * NBLK_N + NBLK_B; J.boff[5] = 3 * NBLK_N + 2 * NBLK_B;
        aggmulti_k<4><<<J.boff[5], 256>>>(J);
    }
    {
        TGJob G;
        setslot(G, 0, aggn, 384, 384, xn0, 128, 128, BtL1N[0], BtL1N[1], 512,
                b1SumN, xn1, 128, 0, NN, 128, 1.f, 1.f / 3.f);
        setslot(G, 1, aggb, 256, 256, xb0, 128, 128, BtL1B[0], BtL1B[1], 384,
                b1SumB, xb1, 128, 0, NB, 128, 1.f, 1.f / 2.f);
        tgemmJ(3, G, 2, ln_g + 128, ln_b + 128);
    }

    // ==================== layer 2 (note dst only) ====================
    {
        Agg5 J; J.nslots = 3;
        mkjob(J, 0, xn1, 128, 0, 0, aggn, 384, 0,   NN);
        mkjob(J, 1, xn1, 128, 0, 1, aggn, 384, 128, NN);
        mkjob(J, 2, xb1, 128, 0, 3, aggn, 384, 256, NN);
        J.boff[0] = 0; J.boff[1] = NBLK_N; J.boff[2] = 2 * NBLK_N; J.boff[3] = 3 * NBLK_N;
        J.boff[4] = 3 * NBLK_N; J.boff[5] = 3 * NBLK_N;
        aggmulti_k<4><<<J.boff[3], 256>>>(J);
    }
    {
        TGJob G;
        setslot(G, 0, aggn, 384, 384, xn1, 128, 128, BtL2N[0], BtL2N[1], 512,
                b2SumN, outn, 128, 0, NN, 128, 1.f);
        tgemmJ(0, G, 1, nullptr, nullptr);
    }

    // ==================== final MLP (fused MLP1+BN+MLP2, writes d_out) =======
    {
        TGJob G;
        setslot(G, 0, outn, 128, 128, nullptr, 0, 0, BtM1[0], BtM1[1], 128,
                mlp_b1, On, 128, 0, NN, 128, 1.f / 3.f);
        G.W2h = BtM2[0]; G.W2l = BtM2[1]; G.b2 = mlp_b2; G.Cout = (float*)d_out;
        tgemmJ(4, G, 1, bnS, bn_b);
    }
}